// round 9
// baseline (speedup 1.0000x reference)
#include <cuda_runtime.h>
#include <cuda_fp16.h>
#include <math.h>
#include <stdint.h>

// Problem dims
#define TT   64
#define VV   30000
#define HID  512
#define XD   768          // EMB + E
#define G4   2048         // 4*H
#define MROWS 2048        // B*T

// ---------------- scratch (device globals; no allocation allowed) -------------
__device__ __align__(16) __half g_X2  [MROWS * XD];          // fp16 X
__device__ __align__(16) __half g_Wih2[G4 * XD];             // fp16 W_ih
__device__ __align__(16) __half g_Whh2[G4 * HID];            // fp16 W_hh
__device__ __align__(16) __half g_Wfc2[(size_t)VV * HID];    // fp16 W_fc
__device__ __align__(16) __half g_H2  [MROWS * HID];         // fp16 hidden history
__device__ __align__(16) __half g_h2A [32 * HID];            // h state ping
__device__ __align__(16) __half g_h2B [32 * HID];            // h state pong
__device__ __align__(16) float  g_pg[MROWS * G4];            // pregates fp32
__device__ __align__(16) int    g_flags[64];                 // per-CTA step flags

// ---------------- small helpers ------------------------------------------------
__device__ __forceinline__ uint32_t smem_u32(const void* p) {
    uint32_t a;
    asm("{ .reg .u64 t; cvta.to.shared.u64 t, %1; cvt.u32.u64 %0, t; }" : "=r"(a) : "l"(p));
    return a;
}
__device__ __forceinline__ void ldsm4(uint32_t* r, uint32_t addr) {
    asm volatile("ldmatrix.sync.aligned.m8n8.x4.shared.b16 {%0,%1,%2,%3}, [%4];"
                 : "=r"(r[0]), "=r"(r[1]), "=r"(r[2]), "=r"(r[3]) : "r"(addr));
}
__device__ __forceinline__ void mma16816(float* d, const uint32_t* a,
                                         uint32_t b0, uint32_t b1) {
    asm volatile("mma.sync.aligned.m16n8k16.row.col.f32.f16.f16.f32 "
                 "{%0,%1,%2,%3}, {%4,%5,%6,%7}, {%8,%9}, {%0,%1,%2,%3};"
                 : "+f"(d[0]), "+f"(d[1]), "+f"(d[2]), "+f"(d[3])
                 : "r"(a[0]), "r"(a[1]), "r"(a[2]), "r"(a[3]), "r"(b0), "r"(b1));
}
__device__ __forceinline__ void cpasync16(uint32_t dst, const void* src) {
    asm volatile("cp.async.cg.shared.global [%0], [%1], 16;" :: "r"(dst), "l"(src));
}
__device__ __forceinline__ void cpasync16z(uint32_t dst, const void* src, unsigned sz) {
    asm volatile("cp.async.cg.shared.global [%0], [%1], 16, %2;"
                 :: "r"(dst), "l"(src), "r"(sz));
}
#define CP_COMMIT() asm volatile("cp.async.commit_group;" ::: "memory")

__device__ __forceinline__ int ld_acq(const int* p) {
    int v;
    asm volatile("ld.acquire.gpu.global.b32 %0, [%1];" : "=r"(v) : "l"(p) : "memory");
    return v;
}
__device__ __forceinline__ void st_rel(int* p, int v) {
    asm volatile("st.release.gpu.global.b32 [%0], %1;" :: "l"(p), "r"(v) : "memory");
}

// ---------------- fused fp32 -> fp16 converts (W_ih, W_hh, W_fc) ---------------
#define N2_WIH (G4 * XD / 2)
#define N2_WHH (G4 * HID / 2)
#define N2_WFC (VV * HID / 2)
__global__ void cvt_all_kernel(const float* __restrict__ Wih,
                               const float* __restrict__ Whh,
                               const float* __restrict__ Wfc,
                               __half* __restrict__ dWih,
                               __half* __restrict__ dWhh,
                               __half* __restrict__ dWfc)
{
    int i = blockIdx.x * 256 + threadIdx.x;
    const float* src;
    __half* dst;
    if (i < N2_WIH)                 { src = Wih; dst = dWih; }
    else if (i < N2_WIH + N2_WHH)   { src = Whh; dst = dWhh; i -= N2_WIH; }
    else                            { src = Wfc; dst = dWfc; i -= N2_WIH + N2_WHH;
                                      if (i >= N2_WFC) return; }
    float2 v = ((const float2*)src)[i];
    ((__half2*)dst)[i] = __floats2half2_rn(v.x, v.y);
}

// ---------------- prep: X2 = fp16([emb||enc]); zero h ping + flags -------------
__global__ void prep_kernel(const float* __restrict__ enc,
                            const int*   __restrict__ captions,
                            const float* __restrict__ emb_table,
                            __half* __restrict__ X2,
                            __half* __restrict__ h0, int* __restrict__ flags)
{
    int blk = blockIdx.x;
    if (blk < MROWS) {
        int b = blk >> 6;
        int cap = captions[blk];
        const float* erow = emb_table + (size_t)cap * 512;
        const float* crow = enc + (size_t)b * 256;
        size_t base = (size_t)blk * XD;
        for (int c = threadIdx.x; c < XD; c += 256) {
            float x = (c < 512) ? erow[c] : crow[c - 512];
            X2[base + c] = __float2half(x);
        }
    } else {
        // h0 = 32*512 halves = 8192 uint32; 32 blocks x 256 threads cover all.
        int i = (blk - MROWS) * 256 + threadIdx.x;   // 0..8191
        ((uint32_t*)h0)[i] = 0u;
        if (i < 64) flags[i] = 0;
    }
}

// ---------------- HMMA GEMM: C[M,N] = A[M,K] B[N,K]^T + bias ------------------
// fp16 in, fp32 out. CTA tile 128x128, 4 warps (2m x 2n), warp tile 64x64.
// 96KB crossbar/chunk < 1024 cyc HMMA -> tensor-bound. 2 CTAs/SM.
#define KC 64
#define STAGE_BYTES 32768      // A 16KB + B 16KB
#define GSMEM (3 * STAGE_BYTES)

__global__ __launch_bounds__(128, 2) void hmma_gemm(
    const __half* __restrict__ A, const __half* __restrict__ B,
    float* __restrict__ C,
    const float* __restrict__ bias0, const float* __restrict__ bias1,
    int M, int N, int K)
{
    extern __shared__ char smem[];
    const uint32_t sb = smem_u32(smem);
    const int tid  = threadIdx.x;
    const int lane = tid & 31, wid = tid >> 5;
    const int m0 = blockIdx.y * 128, n0 = blockIdx.x * 128;
    const int wm = wid & 1, wn = wid >> 1;     // 2 x 2 warps
    const int nch = K / KC;

    const int rowA = wm * 64 + (lane & 7) + ((lane >> 3) & 1) * 8;
    const int kxA  = ((lane >> 4) * 16) ^ ((rowA & 7) * 16);
    const int rowB = wn * 64 + (lane & 7) + ((lane >= 16) ? 8 : 0);
    const int kxB  = (((lane >> 3) & 1) * 16) ^ ((rowB & 7) * 16);

    float acc[4][8][4];
#pragma unroll
    for (int i = 0; i < 4; i++)
#pragma unroll
        for (int j = 0; j < 8; j++)
#pragma unroll
            for (int e = 0; e < 4; e++) acc[i][j][e] = 0.f;

    const int prow = tid >> 3;      // 0..15 base; +16 per 128-thread step
    const int pcc  = tid & 7;
#define PREFETCH(stage, kt)                                                     \
    do {                                                                        \
        uint32_t ab = sb + (stage) * STAGE_BYTES;                               \
        _Pragma("unroll")                                                       \
        for (int j = 0; j < 8; j++) {        /* A: 128 rows */                  \
            int row = prow + j * 16;                                            \
            uint32_t dst = ab + (uint32_t)(row * 128 + ((pcc * 16) ^ ((row & 7) * 16))); \
            cpasync16(dst, A + (size_t)(m0 + row) * K + (kt) + pcc * 8);        \
        }                                                                       \
        _Pragma("unroll")                                                       \
        for (int j = 0; j < 8; j++) {        /* B: 128 rows */                  \
            int row = prow + j * 16;                                            \
            int gn = n0 + row;                                                  \
            uint32_t dst = ab + 16384u + (uint32_t)(row * 128 + ((pcc * 16) ^ ((row & 7) * 16))); \
            int gnc = gn < N ? gn : N - 1;                                      \
            cpasync16z(dst, B + (size_t)gnc * K + (kt) + pcc * 8,               \
                       gn < N ? 16u : 0u);                                      \
        }                                                                       \
        CP_COMMIT();                                                            \
    } while (0)

    PREFETCH(0, 0);
    PREFETCH(1, KC);

    for (int c = 0; c < nch; c++) {
        if (c + 2 < nch) PREFETCH((c + 2) % 3, (c + 2) * KC);
        if (c + 2 < nch)      asm volatile("cp.async.wait_group 2;" ::: "memory");
        else if (c + 1 < nch) asm volatile("cp.async.wait_group 1;" ::: "memory");
        else                  asm volatile("cp.async.wait_group 0;" ::: "memory");
        __syncthreads();

        const uint32_t As = sb + (c % 3) * STAGE_BYTES;
        const uint32_t Bs = As + 16384;
#pragma unroll
        for (int ks = 0; ks < 4; ks++) {
            uint32_t a[4][4], b[4][4];
#pragma unroll
            for (int mt = 0; mt < 4; mt++)
                ldsm4(a[mt], As + (uint32_t)((rowA + mt * 16) * 128 + ((ks * 32) ^ kxA)));
#pragma unroll
            for (int j = 0; j < 4; j++)
                ldsm4(b[j], Bs + (uint32_t)((rowB + j * 16) * 128 + ((ks * 32) ^ kxB)));
#pragma unroll
            for (int mt = 0; mt < 4; mt++)
#pragma unroll
                for (int nt = 0; nt < 8; nt++)
                    mma16816(acc[mt][nt], a[mt],
                             b[nt >> 1][(nt & 1) * 2], b[nt >> 1][(nt & 1) * 2 + 1]);
        }
        __syncthreads();
    }

    const int mrow  = m0 + wm * 64 + (lane >> 2);
    const int ncol0 = n0 + wn * 64 + (lane & 3) * 2;
#pragma unroll
    for (int mt = 0; mt < 4; mt++) {
#pragma unroll
        for (int nt = 0; nt < 8; nt++) {
            int cc = ncol0 + nt * 8;
            if (cc < N) {
                float b0v = bias0[cc], b1v = bias0[cc + 1];
                if (bias1) { b0v += bias1[cc]; b1v += bias1[cc + 1]; }
                int r0 = mrow + mt * 16;
                float2 v0 = make_float2(acc[mt][nt][0] + b0v, acc[mt][nt][1] + b1v);
                float2 v1 = make_float2(acc[mt][nt][2] + b0v, acc[mt][nt][3] + b1v);
                *(float2*)(C + (size_t)r0 * N + cc)       = v0;
                *(float2*)(C + (size_t)(r0 + 8) * N + cc) = v1;
            }
        }
    }
#undef PREFETCH
}

// ---------------- persistent LSTM, tensor-core recurrence ----------------------
// 64 CTAs x 256 threads (8 warps). CTA owns 8 hidden units -> 32 gate rows.
// W_hh (fp16) SMEM-resident. h: fp16 [32 x 512] ping-pong in L2.
// pregates tile for step t+1 prefetched into double-buffered SMEM during step t.
// Grid barrier: per-CTA flag array, one st.release.gpu per CTA, 64 parallel
// ld.acquire.gpu pollers (no atomic serialization, no per-thread membar).
#define LWS_OFF  0
#define LHS_OFF  32768
#define LPG_OFF  65536                        // 2 x 4KB pregates buffers
#define LGSM_OFF (65536 + 8192)
#define LCSM_OFF (LGSM_OFF + 32 * 33 * 4)
#define LSM_BYTES (LCSM_OFF + 256 * 4)

__device__ __forceinline__ float sigf(float x) { return 1.0f / (1.0f + expf(-x)); }

__global__ __launch_bounds__(256, 1) void lstm_persistent(
    const float* __restrict__ pregates,
    const __half* __restrict__ Whh2,
    __half* __restrict__ hA, __half* __restrict__ hB,
    __half* __restrict__ H2, int* __restrict__ flags)
{
    extern __shared__ char smem[];
    const uint32_t sb = smem_u32(smem);
    float* gsm = (float*)(smem + LGSM_OFF);
    float* csm = (float*)(smem + LCSM_OFF);

    const int tid  = threadIdx.x;
    const int lane = tid & 31, wid = tid >> 5;
    const int u0   = blockIdx.x * 8;

    // pregates prefetch geometry: thread -> (b, gate, 16B-half)
    const int qb = tid >> 3, qg = (tid >> 1) & 3, qh = tid & 1;
    const size_t qsrc_base = (size_t)qb * TT * G4 + qg * 512 + u0 + qh * 4;
    const uint32_t qdst_off = (uint32_t)(qb * 128 + qg * 32 + qh * 16);

    // stage 32 gate rows of W_hh (fp16) once
    for (int i = tid; i < 2048; i += 256) {
        int rr = i >> 6, cq = i & 63;
        int g = rr >> 3, ul = rr & 7;
        uint32_t dst = sb + LWS_OFF + (uint32_t)(rr * 1024 + ((cq * 16) ^ ((rr & 7) * 16)));
        cpasync16(dst, Whh2 + (size_t)(g * 512 + u0 + ul) * HID + cq * 8);
    }
    CP_COMMIT();
    // prefetch pregates for t = 0 into buffer 0
    cpasync16(sb + LPG_OFF + qdst_off, pregates + qsrc_base);
    CP_COMMIT();
    csm[tid] = 0.0f;

    // warp geometry
    const int wm = wid & 1, wn = wid >> 1;
    const int rowA = wm * 16 + (lane & 15);
    const int kxA  = (lane >> 4) * 16;
    const int sxA  = (rowA & 7) * 16;
    const int rowB = wn * 8 + (lane & 7);
    const int kxB  = ((lane >> 3) & 3) * 16;
    const int sxB  = (rowB & 7) * 16;
    const uint32_t wsb = sb + LWS_OFF, hsb = sb + LHS_OFF;

    const int pb = tid >> 3, pul = tid & 7;
    const int pu = u0 + pul;

    for (int t = 0; t < TT; t++) {
        // stage h (fp16 32x512) into swizzled SMEM
        const __half* hin = (t & 1) ? hB : hA;
        for (int i = tid; i < 2048; i += 256) {
            int b = i >> 6, cq = i & 63;
            uint32_t dst = hsb + (uint32_t)(b * 1024 + ((cq * 16) ^ ((b & 7) * 16)));
            cpasync16(dst, hin + b * HID + cq * 8);
        }
        CP_COMMIT();
        if (t + 1 < TT) {
            // prefetch pregates(t+1) into the other buffer; stays in flight
            cpasync16(sb + LPG_OFF + ((t + 1) & 1) * 4096 + qdst_off,
                      pregates + qsrc_base + (size_t)(t + 1) * G4);
            CP_COMMIT();
            asm volatile("cp.async.wait_group 1;" ::: "memory");
        } else {
            asm volatile("cp.async.wait_group 0;" ::: "memory");
        }
        __syncthreads();

        // MMA: [32 gate-rows x 32 batch] = Ws[32x512] * hs[32x512]^T
        float c0[4] = {0.f, 0.f, 0.f, 0.f}, c1[4] = {0.f, 0.f, 0.f, 0.f};
#pragma unroll
        for (int ks2 = 0; ks2 < 16; ks2++) {
            uint32_t bf[4], a0[4], a1[4];
            ldsm4(bf, hsb + (uint32_t)(rowB * 1024 + ((ks2 * 64 + kxB) ^ sxB)));
            ldsm4(a0, wsb + (uint32_t)(rowA * 1024 + ((ks2 * 64 + kxA) ^ sxA)));
            ldsm4(a1, wsb + (uint32_t)(rowA * 1024 + ((ks2 * 64 + 32 + kxA) ^ sxA)));
            mma16816(c0, a0, bf[0], bf[1]);
            mma16816(c1, a1, bf[2], bf[3]);
        }
#pragma unroll
        for (int e = 0; e < 4; e++) c0[e] += c1[e];
        {
            int r0 = wm * 16 + (lane >> 2);
            int cc = wn * 8 + (lane & 3) * 2;
            gsm[r0 * 33 + cc]           = c0[0];
            gsm[r0 * 33 + cc + 1]       = c0[1];
            gsm[(r0 + 8) * 33 + cc]     = c0[2];
            gsm[(r0 + 8) * 33 + cc + 1] = c0[3];
        }
        __syncthreads();

        // pointwise: 256 threads = 32 b x 8 units; pregates from SMEM buffer
        {
            const float* pgs = (const float*)(smem + LPG_OFF + (t & 1) * 4096);
            float gi = gsm[(0  + pul) * 33 + pb] + pgs[pb * 32 + 0 * 8 + pul];
            float gf = gsm[(8  + pul) * 33 + pb] + pgs[pb * 32 + 1 * 8 + pul];
            float gg = gsm[(16 + pul) * 33 + pb] + pgs[pb * 32 + 2 * 8 + pul];
            float go = gsm[(24 + pul) * 33 + pb] + pgs[pb * 32 + 3 * 8 + pul];
            float c_old = csm[tid];
            float cn = sigf(gf) * c_old + sigf(gi) * tanhf(gg);
            float hn = sigf(go) * tanhf(cn);
            csm[tid] = cn;
            __half hh = __float2half(hn);
            __half* hout = (t & 1) ? hA : hB;
            hout[pb * HID + pu] = hh;
            H2[((size_t)pb * TT + t) * HID + pu] = hh;
        }

        if (t < TT - 1) {
            // flag-array grid barrier (release/acquire, no atomics)
            __syncthreads();                       // all h stores ordered (CTA scope)
            if (tid == 0) st_rel(&flags[blockIdx.x], t + 1);
            if (tid < 64) {
                while (ld_acq(&flags[tid]) <= t) { }
            }
            __syncthreads();
        }
    }
}

// ---------------- launch ------------------------------------------------------
extern "C" void kernel_launch(void* const* d_in, const int* in_sizes, int n_in,
                              void* d_out, int out_size)
{
    const float* enc       = (const float*)d_in[0];
    const int*   captions  = (const int*)  d_in[1];
    const float* emb_table = (const float*)d_in[8];
    const float* W_ih      = (const float*)d_in[9];
    const float* W_hh      = (const float*)d_in[10];
    const float* b_ih      = (const float*)d_in[11];
    const float* b_hh      = (const float*)d_in[12];
    const float* W_fc      = (const float*)d_in[13];
    const float* b_fc      = (const float*)d_in[14];
    float* out = (float*)d_out;

    __half *pX2, *pWih2, *pWhh2, *pWfc2, *pH2, *ph2A, *ph2B;
    float *pPG;
    int* pFlags;
    cudaGetSymbolAddress((void**)&pX2, g_X2);
    cudaGetSymbolAddress((void**)&pWih2, g_Wih2);
    cudaGetSymbolAddress((void**)&pWhh2, g_Whh2);
    cudaGetSymbolAddress((void**)&pWfc2, g_Wfc2);
    cudaGetSymbolAddress((void**)&pH2, g_H2);
    cudaGetSymbolAddress((void**)&ph2A, g_h2A);
    cudaGetSymbolAddress((void**)&ph2B, g_h2B);
    cudaGetSymbolAddress((void**)&pPG, g_pg);
    cudaGetSymbolAddress((void**)&pFlags, g_flags);

    cudaFuncSetAttribute(hmma_gemm, cudaFuncAttributeMaxDynamicSharedMemorySize, GSMEM);
    cudaFuncSetAttribute(lstm_persistent, cudaFuncAttributeMaxDynamicSharedMemorySize, LSM_BYTES);

    // 1) fused fp32 -> fp16 weight converts
    {
        int total = N2_WIH + N2_WHH + N2_WFC;
        cvt_all_kernel<<<(total + 255) / 256, 256>>>(W_ih, W_hh, W_fc,
                                                     pWih2, pWhh2, pWfc2);
    }

    // 2) build X2, zero FULL h ping + flags reset
    prep_kernel<<<MROWS + 32, 256>>>(enc, captions, emb_table, pX2, ph2A, pFlags);

    // 3) pregates = X @ W_ih^T + b_ih + b_hh   (K = 768)
    {
        dim3 grid(G4 / 128, MROWS / 128);
        hmma_gemm<<<grid, 128, GSMEM>>>(pX2, pWih2, pPG, b_ih, b_hh,
                                        MROWS, G4, XD);
    }

    // 4) persistent tensor-core LSTM (one launch, emits H2 inline)
    lstm_persistent<<<64, 256, LSM_BYTES>>>(pPG, pWhh2, ph2A, ph2B, pH2, pFlags);

    // 5) out = H @ W_fc^T + b_fc   (K = 512)
    {
        dim3 grid((VV + 127) / 128, MROWS / 128);
        hmma_gemm<<<grid, 128, GSMEM>>>(pH2, pWfc2, out, b_fc, nullptr,
                                        MROWS, VV, HID);
    }
}

// round 10
// speedup vs baseline: 1.4191x; 1.4191x over previous
#include <cuda_runtime.h>
#include <cuda_fp16.h>
#include <math.h>
#include <stdint.h>

// Problem dims
#define TT   64
#define VV   30000
#define HID  512
#define XD   768          // EMB + E
#define G4   2048         // 4*H
#define MROWS 2048        // B*T

// ---------------- scratch (device globals; no allocation allowed) -------------
__device__ __align__(16) __half g_X2  [MROWS * XD];          // fp16 X
__device__ __align__(16) __half g_Wih2[G4 * XD];             // fp16 W_ih
__device__ __align__(16) __half g_Whh2[G4 * HID];            // fp16 W_hh
__device__ __align__(16) __half g_Wfc2[(size_t)VV * HID];    // fp16 W_fc
__device__ __align__(16) __half g_H2  [MROWS * HID];         // fp16 hidden history
__device__ __align__(16) __half g_h2A [32 * HID];            // h state ping
__device__ __align__(16) __half g_h2B [32 * HID];            // h state pong
__device__ __align__(16) float  g_pg[MROWS * G4];            // pregates fp32
__device__ __align__(16) int    g_bars[512];                 // 8 counters, 256B apart

// ---------------- small helpers ------------------------------------------------
__device__ __forceinline__ uint32_t smem_u32(const void* p) {
    uint32_t a;
    asm("{ .reg .u64 t; cvta.to.shared.u64 t, %1; cvt.u32.u64 %0, t; }" : "=r"(a) : "l"(p));
    return a;
}
__device__ __forceinline__ void ldsm4(uint32_t* r, uint32_t addr) {
    asm volatile("ldmatrix.sync.aligned.m8n8.x4.shared.b16 {%0,%1,%2,%3}, [%4];"
                 : "=r"(r[0]), "=r"(r[1]), "=r"(r[2]), "=r"(r[3]) : "r"(addr));
}
__device__ __forceinline__ void mma16816(float* d, const uint32_t* a,
                                         uint32_t b0, uint32_t b1) {
    asm volatile("mma.sync.aligned.m16n8k16.row.col.f32.f16.f16.f32 "
                 "{%0,%1,%2,%3}, {%4,%5,%6,%7}, {%8,%9}, {%0,%1,%2,%3};"
                 : "+f"(d[0]), "+f"(d[1]), "+f"(d[2]), "+f"(d[3])
                 : "r"(a[0]), "r"(a[1]), "r"(a[2]), "r"(a[3]), "r"(b0), "r"(b1));
}
__device__ __forceinline__ void cpasync16(uint32_t dst, const void* src) {
    asm volatile("cp.async.cg.shared.global [%0], [%1], 16;" :: "r"(dst), "l"(src));
}
__device__ __forceinline__ void cpasync16z(uint32_t dst, const void* src, unsigned sz) {
    asm volatile("cp.async.cg.shared.global [%0], [%1], 16, %2;"
                 :: "r"(dst), "l"(src), "r"(sz));
}
#define CP_COMMIT() asm volatile("cp.async.commit_group;" ::: "memory")

// ---------------- fused fp32 -> fp16 converts (W_ih, W_hh, W_fc) ---------------
#define N2_WIH (G4 * XD / 2)
#define N2_WHH (G4 * HID / 2)
#define N2_WFC (VV * HID / 2)
__global__ void cvt_all_kernel(const float* __restrict__ Wih,
                               const float* __restrict__ Whh,
                               const float* __restrict__ Wfc,
                               __half* __restrict__ dWih,
                               __half* __restrict__ dWhh,
                               __half* __restrict__ dWfc)
{
    int i = blockIdx.x * 256 + threadIdx.x;
    const float* src;
    __half* dst;
    if (i < N2_WIH)                 { src = Wih; dst = dWih; }
    else if (i < N2_WIH + N2_WHH)   { src = Whh; dst = dWhh; i -= N2_WIH; }
    else                            { src = Wfc; dst = dWfc; i -= N2_WIH + N2_WHH;
                                      if (i >= N2_WFC) return; }
    float2 v = ((const float2*)src)[i];
    ((__half2*)dst)[i] = __floats2half2_rn(v.x, v.y);
}

// ---------------- prep: X2 = fp16([emb||enc]); zero h ping + barrier counters --
__global__ void prep_kernel(const float* __restrict__ enc,
                            const int*   __restrict__ captions,
                            const float* __restrict__ emb_table,
                            __half* __restrict__ X2,
                            __half* __restrict__ h0, int* __restrict__ bars)
{
    int blk = blockIdx.x;
    if (blk < MROWS) {
        int b = blk >> 6;
        int cap = captions[blk];
        const float* erow = emb_table + (size_t)cap * 512;
        const float* crow = enc + (size_t)b * 256;
        size_t base = (size_t)blk * XD;
        for (int c = threadIdx.x; c < XD; c += 256) {
            float x = (c < 512) ? erow[c] : crow[c - 512];
            X2[base + c] = __float2half(x);
        }
    } else {
        // h0 = 32*512 halves = 8192 uint32; 32 blocks x 256 threads cover all.
        int i = (blk - MROWS) * 256 + threadIdx.x;   // 0..8191
        ((uint32_t*)h0)[i] = 0u;
        if (i < 512) bars[i] = 0;
    }
}

// ---------------- HMMA GEMM: C[M,N] = A[M,K] B[N,K]^T + bias ------------------
// fp16 in, fp32 out. CTA tile 128x128, 4 warps (2m x 2n), warp tile 64x64.
// 96KB crossbar/chunk < 1024 cyc HMMA -> tensor-bound. 2 CTAs/SM.
#define KC 64
#define STAGE_BYTES 32768      // A 16KB + B 16KB
#define GSMEM (3 * STAGE_BYTES)

__global__ __launch_bounds__(128, 2) void hmma_gemm(
    const __half* __restrict__ A, const __half* __restrict__ B,
    float* __restrict__ C,
    const float* __restrict__ bias0, const float* __restrict__ bias1,
    int M, int N, int K)
{
    extern __shared__ char smem[];
    const uint32_t sb = smem_u32(smem);
    const int tid  = threadIdx.x;
    const int lane = tid & 31, wid = tid >> 5;
    const int m0 = blockIdx.y * 128, n0 = blockIdx.x * 128;
    const int wm = wid & 1, wn = wid >> 1;     // 2 x 2 warps
    const int nch = K / KC;

    const int rowA = wm * 64 + (lane & 7) + ((lane >> 3) & 1) * 8;
    const int kxA  = ((lane >> 4) * 16) ^ ((rowA & 7) * 16);
    const int rowB = wn * 64 + (lane & 7) + ((lane >= 16) ? 8 : 0);
    const int kxB  = (((lane >> 3) & 1) * 16) ^ ((rowB & 7) * 16);

    float acc[4][8][4];
#pragma unroll
    for (int i = 0; i < 4; i++)
#pragma unroll
        for (int j = 0; j < 8; j++)
#pragma unroll
            for (int e = 0; e < 4; e++) acc[i][j][e] = 0.f;

    const int prow = tid >> 3;      // 0..15 base; +16 per 128-thread step
    const int pcc  = tid & 7;
#define PREFETCH(stage, kt)                                                     \
    do {                                                                        \
        uint32_t ab = sb + (stage) * STAGE_BYTES;                               \
        _Pragma("unroll")                                                       \
        for (int j = 0; j < 8; j++) {        /* A: 128 rows */                  \
            int row = prow + j * 16;                                            \
            uint32_t dst = ab + (uint32_t)(row * 128 + ((pcc * 16) ^ ((row & 7) * 16))); \
            cpasync16(dst, A + (size_t)(m0 + row) * K + (kt) + pcc * 8);        \
        }                                                                       \
        _Pragma("unroll")                                                       \
        for (int j = 0; j < 8; j++) {        /* B: 128 rows */                  \
            int row = prow + j * 16;                                            \
            int gn = n0 + row;                                                  \
            uint32_t dst = ab + 16384u + (uint32_t)(row * 128 + ((pcc * 16) ^ ((row & 7) * 16))); \
            int gnc = gn < N ? gn : N - 1;                                      \
            cpasync16z(dst, B + (size_t)gnc * K + (kt) + pcc * 8,               \
                       gn < N ? 16u : 0u);                                      \
        }                                                                       \
        CP_COMMIT();                                                            \
    } while (0)

    PREFETCH(0, 0);
    PREFETCH(1, KC);

    for (int c = 0; c < nch; c++) {
        if (c + 2 < nch) PREFETCH((c + 2) % 3, (c + 2) * KC);
        if (c + 2 < nch)      asm volatile("cp.async.wait_group 2;" ::: "memory");
        else if (c + 1 < nch) asm volatile("cp.async.wait_group 1;" ::: "memory");
        else                  asm volatile("cp.async.wait_group 0;" ::: "memory");
        __syncthreads();

        const uint32_t As = sb + (c % 3) * STAGE_BYTES;
        const uint32_t Bs = As + 16384;
#pragma unroll
        for (int ks = 0; ks < 4; ks++) {
            uint32_t a[4][4], b[4][4];
#pragma unroll
            for (int mt = 0; mt < 4; mt++)
                ldsm4(a[mt], As + (uint32_t)((rowA + mt * 16) * 128 + ((ks * 32) ^ kxA)));
#pragma unroll
            for (int j = 0; j < 4; j++)
                ldsm4(b[j], Bs + (uint32_t)((rowB + j * 16) * 128 + ((ks * 32) ^ kxB)));
#pragma unroll
            for (int mt = 0; mt < 4; mt++)
#pragma unroll
                for (int nt = 0; nt < 8; nt++)
                    mma16816(acc[mt][nt], a[mt],
                             b[nt >> 1][(nt & 1) * 2], b[nt >> 1][(nt & 1) * 2 + 1]);
        }
        __syncthreads();
    }

    const int mrow  = m0 + wm * 64 + (lane >> 2);
    const int ncol0 = n0 + wn * 64 + (lane & 3) * 2;
#pragma unroll
    for (int mt = 0; mt < 4; mt++) {
#pragma unroll
        for (int nt = 0; nt < 8; nt++) {
            int cc = ncol0 + nt * 8;
            if (cc < N) {
                float b0v = bias0[cc], b1v = bias0[cc + 1];
                if (bias1) { b0v += bias1[cc]; b1v += bias1[cc + 1]; }
                int r0 = mrow + mt * 16;
                float2 v0 = make_float2(acc[mt][nt][0] + b0v, acc[mt][nt][1] + b1v);
                float2 v1 = make_float2(acc[mt][nt][2] + b0v, acc[mt][nt][3] + b1v);
                *(float2*)(C + (size_t)r0 * N + cc)       = v0;
                *(float2*)(C + (size_t)(r0 + 8) * N + cc) = v1;
            }
        }
    }
#undef PREFETCH
}

// ---------------- persistent LSTM, tensor-core recurrence ----------------------
// 64 CTAs x 256 threads (8 warps). CTA owns 8 hidden units -> 32 gate rows.
// W_hh (fp16) SMEM-resident. h: fp16 [32 x 512] ping-pong in L2.
// pregates tile for step t+1 prefetched into double-buffered SMEM during step t.
// Grid barrier: 8 group counters 256B apart (8 arrivals each -> tiny atomic
// drain); 8 spinners per CTA, one per counter (64 spinners/line chip-wide =
// R8's proven-safe contention). Fences on tid0 / tid<8 only.
#define LWS_OFF  0
#define LHS_OFF  32768
#define LPG_OFF  65536                        // 2 x 4KB pregates buffers
#define LGSM_OFF (65536 + 8192)
#define LCSM_OFF (LGSM_OFF + 32 * 33 * 4)
#define LSM_BYTES (LCSM_OFF + 256 * 4)

__device__ __forceinline__ float sigf(float x) { return 1.0f / (1.0f + expf(-x)); }

__global__ __launch_bounds__(256, 1) void lstm_persistent(
    const float* __restrict__ pregates,
    const __half* __restrict__ Whh2,
    __half* __restrict__ hA, __half* __restrict__ hB,
    __half* __restrict__ H2, int* __restrict__ bars)
{
    extern __shared__ char smem[];
    const uint32_t sb = smem_u32(smem);
    float* gsm = (float*)(smem + LGSM_OFF);
    float* csm = (float*)(smem + LCSM_OFF);

    const int tid  = threadIdx.x;
    const int lane = tid & 31, wid = tid >> 5;
    const int u0   = blockIdx.x * 8;

    // pregates prefetch geometry: thread -> (b, gate, 16B-half)
    const int qb = tid >> 3, qg = (tid >> 1) & 3, qh = tid & 1;
    const size_t qsrc_base = (size_t)qb * TT * G4 + qg * 512 + u0 + qh * 4;
    const uint32_t qdst_off = (uint32_t)(qb * 128 + qg * 32 + qh * 16);

    // stage 32 gate rows of W_hh (fp16) once
    for (int i = tid; i < 2048; i += 256) {
        int rr = i >> 6, cq = i & 63;
        int g = rr >> 3, ul = rr & 7;
        uint32_t dst = sb + LWS_OFF + (uint32_t)(rr * 1024 + ((cq * 16) ^ ((rr & 7) * 16)));
        cpasync16(dst, Whh2 + (size_t)(g * 512 + u0 + ul) * HID + cq * 8);
    }
    CP_COMMIT();
    // prefetch pregates for t = 0 into buffer 0
    cpasync16(sb + LPG_OFF + qdst_off, pregates + qsrc_base);
    CP_COMMIT();
    csm[tid] = 0.0f;

    // warp geometry
    const int wm = wid & 1, wn = wid >> 1;
    const int rowA = wm * 16 + (lane & 15);
    const int kxA  = (lane >> 4) * 16;
    const int sxA  = (rowA & 7) * 16;
    const int rowB = wn * 8 + (lane & 7);
    const int kxB  = ((lane >> 3) & 3) * 16;
    const int sxB  = (rowB & 7) * 16;
    const uint32_t wsb = sb + LWS_OFF, hsb = sb + LHS_OFF;

    const int pb = tid >> 3, pul = tid & 7;
    const int pu = u0 + pul;

    for (int t = 0; t < TT; t++) {
        // stage h (fp16 32x512) into swizzled SMEM
        const __half* hin = (t & 1) ? hB : hA;
        for (int i = tid; i < 2048; i += 256) {
            int b = i >> 6, cq = i & 63;
            uint32_t dst = hsb + (uint32_t)(b * 1024 + ((cq * 16) ^ ((b & 7) * 16)));
            cpasync16(dst, hin + b * HID + cq * 8);
        }
        CP_COMMIT();
        if (t + 1 < TT) {
            // prefetch pregates(t+1) into the other buffer; stays in flight
            cpasync16(sb + LPG_OFF + ((t + 1) & 1) * 4096 + qdst_off,
                      pregates + qsrc_base + (size_t)(t + 1) * G4);
            CP_COMMIT();
            asm volatile("cp.async.wait_group 1;" ::: "memory");
        } else {
            asm volatile("cp.async.wait_group 0;" ::: "memory");
        }
        __syncthreads();

        // MMA: [32 gate-rows x 32 batch] = Ws[32x512] * hs[32x512]^T
        float c0[4] = {0.f, 0.f, 0.f, 0.f}, c1[4] = {0.f, 0.f, 0.f, 0.f};
#pragma unroll
        for (int ks2 = 0; ks2 < 16; ks2++) {
            uint32_t bf[4], a0[4], a1[4];
            ldsm4(bf, hsb + (uint32_t)(rowB * 1024 + ((ks2 * 64 + kxB) ^ sxB)));
            ldsm4(a0, wsb + (uint32_t)(rowA * 1024 + ((ks2 * 64 + kxA) ^ sxA)));
            ldsm4(a1, wsb + (uint32_t)(rowA * 1024 + ((ks2 * 64 + 32 + kxA) ^ sxA)));
            mma16816(c0, a0, bf[0], bf[1]);
            mma16816(c1, a1, bf[2], bf[3]);
        }
#pragma unroll
        for (int e = 0; e < 4; e++) c0[e] += c1[e];
        {
            int r0 = wm * 16 + (lane >> 2);
            int cc = wn * 8 + (lane & 3) * 2;
            gsm[r0 * 33 + cc]           = c0[0];
            gsm[r0 * 33 + cc + 1]       = c0[1];
            gsm[(r0 + 8) * 33 + cc]     = c0[2];
            gsm[(r0 + 8) * 33 + cc + 1] = c0[3];
        }
        __syncthreads();

        // pointwise: 256 threads = 32 b x 8 units; pregates from SMEM buffer
        {
            const float* pgs = (const float*)(smem + LPG_OFF + (t & 1) * 4096);
            float gi = gsm[(0  + pul) * 33 + pb] + pgs[pb * 32 + 0 * 8 + pul];
            float gf = gsm[(8  + pul) * 33 + pb] + pgs[pb * 32 + 1 * 8 + pul];
            float gg = gsm[(16 + pul) * 33 + pb] + pgs[pb * 32 + 2 * 8 + pul];
            float go = gsm[(24 + pul) * 33 + pb] + pgs[pb * 32 + 3 * 8 + pul];
            float c_old = csm[tid];
            float cn = sigf(gf) * c_old + sigf(gi) * tanhf(gg);
            float hn = sigf(go) * tanhf(cn);
            csm[tid] = cn;
            __half hh = __float2half(hn);
            __half* hout = (t & 1) ? hA : hB;
            hout[pb * HID + pu] = hh;
            H2[((size_t)pb * TT + t) * HID + pu] = hh;
        }

        if (t < TT - 1) {
            // grouped-counter grid barrier
            __syncthreads();                 // all h stores done (CTA scope)
            if (tid == 0) {
                __threadfence();             // publish h stores (gpu scope)
                atomicAdd(&bars[(blockIdx.x & 7) * 64], 1);
            }
            if (tid < 8) {
                int target = 8 * (t + 1);
                while (*(volatile int*)&bars[tid * 64] < target) { }
                __threadfence();             // acquire side
            }
            __syncthreads();
        }
    }
}

// ---------------- launch ------------------------------------------------------
extern "C" void kernel_launch(void* const* d_in, const int* in_sizes, int n_in,
                              void* d_out, int out_size)
{
    const float* enc       = (const float*)d_in[0];
    const int*   captions  = (const int*)  d_in[1];
    const float* emb_table = (const float*)d_in[8];
    const float* W_ih      = (const float*)d_in[9];
    const float* W_hh      = (const float*)d_in[10];
    const float* b_ih      = (const float*)d_in[11];
    const float* b_hh      = (const float*)d_in[12];
    const float* W_fc      = (const float*)d_in[13];
    const float* b_fc      = (const float*)d_in[14];
    float* out = (float*)d_out;

    __half *pX2, *pWih2, *pWhh2, *pWfc2, *pH2, *ph2A, *ph2B;
    float *pPG;
    int* pBars;
    cudaGetSymbolAddress((void**)&pX2, g_X2);
    cudaGetSymbolAddress((void**)&pWih2, g_Wih2);
    cudaGetSymbolAddress((void**)&pWhh2, g_Whh2);
    cudaGetSymbolAddress((void**)&pWfc2, g_Wfc2);
    cudaGetSymbolAddress((void**)&pH2, g_H2);
    cudaGetSymbolAddress((void**)&ph2A, g_h2A);
    cudaGetSymbolAddress((void**)&ph2B, g_h2B);
    cudaGetSymbolAddress((void**)&pPG, g_pg);
    cudaGetSymbolAddress((void**)&pBars, g_bars);

    cudaFuncSetAttribute(hmma_gemm, cudaFuncAttributeMaxDynamicSharedMemorySize, GSMEM);
    cudaFuncSetAttribute(lstm_persistent, cudaFuncAttributeMaxDynamicSharedMemorySize, LSM_BYTES);

    // 1) fused fp32 -> fp16 weight converts
    {
        int total = N2_WIH + N2_WHH + N2_WFC;
        cvt_all_kernel<<<(total + 255) / 256, 256>>>(W_ih, W_hh, W_fc,
                                                     pWih2, pWhh2, pWfc2);
    }

    // 2) build X2, zero FULL h ping + barrier counters reset
    prep_kernel<<<MROWS + 32, 256>>>(enc, captions, emb_table, pX2, ph2A, pBars);

    // 3) pregates = X @ W_ih^T + b_ih + b_hh   (K = 768)
    {
        dim3 grid(G4 / 128, MROWS / 128);
        hmma_gemm<<<grid, 128, GSMEM>>>(pX2, pWih2, pPG, b_ih, b_hh,
                                        MROWS, G4, XD);
    }

    // 4) persistent tensor-core LSTM (one launch, emits H2 inline)
    lstm_persistent<<<64, 256, LSM_BYTES>>>(pPG, pWhh2, ph2A, ph2B, pH2, pBars);

    // 5) out = H @ W_fc^T + b_fc   (K = 512)
    {
        dim3 grid((VV + 127) / 128, MROWS / 128);
        hmma_gemm<<<grid, 128, GSMEM>>>(pH2, pWfc2, out, b_fc, nullptr,
                                        MROWS, VV, HID);
    }
}

// round 11
// speedup vs baseline: 1.4315x; 1.0088x over previous
#include <cuda_runtime.h>
#include <cuda_fp16.h>
#include <math.h>
#include <stdint.h>

// Problem dims
#define TT   64
#define VV   30000
#define HID  512
#define XD   768          // EMB + E
#define G4   2048         // 4*H
#define MROWS 2048        // B*T

// ---------------- scratch (device globals; no allocation allowed) -------------
__device__ __align__(16) __half g_X2  [MROWS * XD];          // fp16 X
__device__ __align__(16) __half g_Wih2[G4 * XD];             // fp16 W_ih
__device__ __align__(16) __half g_Whh2[G4 * HID];            // fp16 W_hh
__device__ __align__(16) __half g_Wfc2[(size_t)VV * HID];    // fp16 W_fc
__device__ __align__(16) __half g_H2  [MROWS * HID];         // fp16 hidden history
__device__ __align__(16) __half g_h2A [32 * HID];            // h state ping
__device__ __align__(16) __half g_h2B [32 * HID];            // h state pong
__device__ __align__(16) float  g_pg[MROWS * G4];            // pregates fp32
__device__ __align__(16) int    g_bars[512];                 // 8 counters, 256B apart

// ---------------- small helpers ------------------------------------------------
__device__ __forceinline__ uint32_t smem_u32(const void* p) {
    uint32_t a;
    asm("{ .reg .u64 t; cvta.to.shared.u64 t, %1; cvt.u32.u64 %0, t; }" : "=r"(a) : "l"(p));
    return a;
}
__device__ __forceinline__ void ldsm4(uint32_t* r, uint32_t addr) {
    asm volatile("ldmatrix.sync.aligned.m8n8.x4.shared.b16 {%0,%1,%2,%3}, [%4];"
                 : "=r"(r[0]), "=r"(r[1]), "=r"(r[2]), "=r"(r[3]) : "r"(addr));
}
__device__ __forceinline__ void mma16816(float* d, const uint32_t* a,
                                         uint32_t b0, uint32_t b1) {
    asm volatile("mma.sync.aligned.m16n8k16.row.col.f32.f16.f16.f32 "
                 "{%0,%1,%2,%3}, {%4,%5,%6,%7}, {%8,%9}, {%0,%1,%2,%3};"
                 : "+f"(d[0]), "+f"(d[1]), "+f"(d[2]), "+f"(d[3])
                 : "r"(a[0]), "r"(a[1]), "r"(a[2]), "r"(a[3]), "r"(b0), "r"(b1));
}
__device__ __forceinline__ void cpasync16(uint32_t dst, const void* src) {
    asm volatile("cp.async.cg.shared.global [%0], [%1], 16;" :: "r"(dst), "l"(src));
}
__device__ __forceinline__ void cpasync16z(uint32_t dst, const void* src, unsigned sz) {
    asm volatile("cp.async.cg.shared.global [%0], [%1], 16, %2;"
                 :: "r"(dst), "l"(src), "r"(sz));
}
#define CP_COMMIT() asm volatile("cp.async.commit_group;" ::: "memory")

// ---------------- fused fp32 -> fp16 converts (W_ih, W_hh, W_fc) ---------------
#define N2_WIH (G4 * XD / 2)
#define N2_WHH (G4 * HID / 2)
#define N2_WFC (VV * HID / 2)
__global__ void cvt_all_kernel(const float* __restrict__ Wih,
                               const float* __restrict__ Whh,
                               const float* __restrict__ Wfc,
                               __half* __restrict__ dWih,
                               __half* __restrict__ dWhh,
                               __half* __restrict__ dWfc)
{
    int i = blockIdx.x * 256 + threadIdx.x;
    const float* src;
    __half* dst;
    if (i < N2_WIH)                 { src = Wih; dst = dWih; }
    else if (i < N2_WIH + N2_WHH)   { src = Whh; dst = dWhh; i -= N2_WIH; }
    else                            { src = Wfc; dst = dWfc; i -= N2_WIH + N2_WHH;
                                      if (i >= N2_WFC) return; }
    float2 v = ((const float2*)src)[i];
    ((__half2*)dst)[i] = __floats2half2_rn(v.x, v.y);
}

// ---------------- prep: X2 = fp16([emb||enc]); zero h ping + barrier counters --
__global__ void prep_kernel(const float* __restrict__ enc,
                            const int*   __restrict__ captions,
                            const float* __restrict__ emb_table,
                            __half* __restrict__ X2,
                            __half* __restrict__ h0, int* __restrict__ bars)
{
    int blk = blockIdx.x;
    if (blk < MROWS) {
        int b = blk >> 6;
        int cap = captions[blk];
        const float* erow = emb_table + (size_t)cap * 512;
        const float* crow = enc + (size_t)b * 256;
        size_t base = (size_t)blk * XD;
        for (int c = threadIdx.x; c < XD; c += 256) {
            float x = (c < 512) ? erow[c] : crow[c - 512];
            X2[base + c] = __float2half(x);
        }
    } else {
        // h0 = 32*512 halves = 8192 uint32; 32 blocks x 256 threads cover all.
        int i = (blk - MROWS) * 256 + threadIdx.x;   // 0..8191
        ((uint32_t*)h0)[i] = 0u;
        if (i < 512) bars[i] = 0;
    }
}

// ---------------- HMMA GEMM: C[M,N] = A[M,K] B[N,K]^T + bias ------------------
// fp16 in, fp32 out. CTA tile 128x128, 4 warps (2m x 2n), warp tile 64x64.
// 96KB crossbar/chunk < 1024 cyc HMMA -> tensor-bound. 2 CTAs/SM.
#define KC 64
#define STAGE_BYTES 32768      // A 16KB + B 16KB
#define GSMEM (3 * STAGE_BYTES)

__global__ __launch_bounds__(128, 2) void hmma_gemm(
    const __half* __restrict__ A, const __half* __restrict__ B,
    float* __restrict__ C,
    const float* __restrict__ bias0, const float* __restrict__ bias1,
    int M, int N, int K)
{
    extern __shared__ char smem[];
    const uint32_t sb = smem_u32(smem);
    const int tid  = threadIdx.x;
    const int lane = tid & 31, wid = tid >> 5;
    const int m0 = blockIdx.y * 128, n0 = blockIdx.x * 128;
    const int wm = wid & 1, wn = wid >> 1;     // 2 x 2 warps
    const int nch = K / KC;

    const int rowA = wm * 64 + (lane & 7) + ((lane >> 3) & 1) * 8;
    const int kxA  = ((lane >> 4) * 16) ^ ((rowA & 7) * 16);
    const int rowB = wn * 64 + (lane & 7) + ((lane >= 16) ? 8 : 0);
    const int kxB  = (((lane >> 3) & 1) * 16) ^ ((rowB & 7) * 16);

    float acc[4][8][4];
#pragma unroll
    for (int i = 0; i < 4; i++)
#pragma unroll
        for (int j = 0; j < 8; j++)
#pragma unroll
            for (int e = 0; e < 4; e++) acc[i][j][e] = 0.f;

    const int prow = tid >> 3;      // 0..15 base; +16 per 128-thread step
    const int pcc  = tid & 7;
#define PREFETCH(stage, kt)                                                     \
    do {                                                                        \
        uint32_t ab = sb + (stage) * STAGE_BYTES;                               \
        _Pragma("unroll")                                                       \
        for (int j = 0; j < 8; j++) {        /* A: 128 rows */                  \
            int row = prow + j * 16;                                            \
            uint32_t dst = ab + (uint32_t)(row * 128 + ((pcc * 16) ^ ((row & 7) * 16))); \
            cpasync16(dst, A + (size_t)(m0 + row) * K + (kt) + pcc * 8);        \
        }                                                                       \
        _Pragma("unroll")                                                       \
        for (int j = 0; j < 8; j++) {        /* B: 128 rows */                  \
            int row = prow + j * 16;                                            \
            int gn = n0 + row;                                                  \
            uint32_t dst = ab + 16384u + (uint32_t)(row * 128 + ((pcc * 16) ^ ((row & 7) * 16))); \
            int gnc = gn < N ? gn : N - 1;                                      \
            cpasync16z(dst, B + (size_t)gnc * K + (kt) + pcc * 8,               \
                       gn < N ? 16u : 0u);                                      \
        }                                                                       \
        CP_COMMIT();                                                            \
    } while (0)

    PREFETCH(0, 0);
    PREFETCH(1, KC);

    for (int c = 0; c < nch; c++) {
        if (c + 2 < nch) PREFETCH((c + 2) % 3, (c + 2) * KC);
        if (c + 2 < nch)      asm volatile("cp.async.wait_group 2;" ::: "memory");
        else if (c + 1 < nch) asm volatile("cp.async.wait_group 1;" ::: "memory");
        else                  asm volatile("cp.async.wait_group 0;" ::: "memory");
        __syncthreads();

        const uint32_t As = sb + (c % 3) * STAGE_BYTES;
        const uint32_t Bs = As + 16384;
#pragma unroll
        for (int ks = 0; ks < 4; ks++) {
            uint32_t a[4][4], b[4][4];
#pragma unroll
            for (int mt = 0; mt < 4; mt++)
                ldsm4(a[mt], As + (uint32_t)((rowA + mt * 16) * 128 + ((ks * 32) ^ kxA)));
#pragma unroll
            for (int j = 0; j < 4; j++)
                ldsm4(b[j], Bs + (uint32_t)((rowB + j * 16) * 128 + ((ks * 32) ^ kxB)));
#pragma unroll
            for (int mt = 0; mt < 4; mt++)
#pragma unroll
                for (int nt = 0; nt < 8; nt++)
                    mma16816(acc[mt][nt], a[mt],
                             b[nt >> 1][(nt & 1) * 2], b[nt >> 1][(nt & 1) * 2 + 1]);
        }
        __syncthreads();
    }

    const int mrow  = m0 + wm * 64 + (lane >> 2);
    const int ncol0 = n0 + wn * 64 + (lane & 3) * 2;
#pragma unroll
    for (int mt = 0; mt < 4; mt++) {
#pragma unroll
        for (int nt = 0; nt < 8; nt++) {
            int cc = ncol0 + nt * 8;
            if (cc < N) {
                float b0v = bias0[cc], b1v = bias0[cc + 1];
                if (bias1) { b0v += bias1[cc]; b1v += bias1[cc + 1]; }
                int r0 = mrow + mt * 16;
                float2 v0 = make_float2(acc[mt][nt][0] + b0v, acc[mt][nt][1] + b1v);
                float2 v1 = make_float2(acc[mt][nt][2] + b0v, acc[mt][nt][3] + b1v);
                *(float2*)(C + (size_t)r0 * N + cc)       = v0;
                *(float2*)(C + (size_t)(r0 + 8) * N + cc) = v1;
            }
        }
    }
#undef PREFETCH
}

// ---------------- persistent LSTM, tensor-core recurrence ----------------------
// 64 CTAs x 256 threads (8 warps). CTA owns 8 hidden units -> 32 gate rows.
// W_hh fragments are TIME-INVARIANT: staged to SMEM once, then hoisted into
// REGISTERS before the t-loop (32 regs/warp) -> zero per-step A ldsm traffic.
// K-split warp layout: 8 warps = 4 k-slices(128) x 2 m-tiles(16 rows); partial
// sums in 4 per-k gsm buffers, summed in the pointwise. Per-step crossbar = B
// (staged h) only: 64KB.
// Grid barrier: 8 group counters 256B apart (R10, proven).
#define LWS_OFF  0
#define LHS_OFF  32768
#define LPG_OFF  65536                        // 2 x 4KB pregates buffers
#define LGSM_OFF (65536 + 8192)
#define GK (32 * 33)                          // one gsm buffer (floats)
#define LCSM_OFF (LGSM_OFF + 4 * GK * 4)
#define LSM_BYTES (LCSM_OFF + 256 * 4)

__device__ __forceinline__ float sigf(float x) { return 1.0f / (1.0f + expf(-x)); }

__global__ __launch_bounds__(256, 1) void lstm_persistent(
    const float* __restrict__ pregates,
    const __half* __restrict__ Whh2,
    __half* __restrict__ hA, __half* __restrict__ hB,
    __half* __restrict__ H2, int* __restrict__ bars)
{
    extern __shared__ char smem[];
    const uint32_t sb = smem_u32(smem);
    float* gsm = (float*)(smem + LGSM_OFF);
    float* csm = (float*)(smem + LCSM_OFF);

    const int tid  = threadIdx.x;
    const int lane = tid & 31, wid = tid >> 5;
    const int u0   = blockIdx.x * 8;

    // pregates prefetch geometry: thread -> (b, gate, 16B-half)
    const int qb = tid >> 3, qg = (tid >> 1) & 3, qh = tid & 1;
    const size_t qsrc_base = (size_t)qb * TT * G4 + qg * 512 + u0 + qh * 4;
    const uint32_t qdst_off = (uint32_t)(qb * 128 + qg * 32 + qh * 16);

    // stage 32 gate rows of W_hh (fp16) once
    for (int i = tid; i < 2048; i += 256) {
        int rr = i >> 6, cq = i & 63;
        int g = rr >> 3, ul = rr & 7;
        uint32_t dst = sb + LWS_OFF + (uint32_t)(rr * 1024 + ((cq * 16) ^ ((rr & 7) * 16)));
        cpasync16(dst, Whh2 + (size_t)(g * 512 + u0 + ul) * HID + cq * 8);
    }
    CP_COMMIT();
    // prefetch pregates for t = 0 into buffer 0
    cpasync16(sb + LPG_OFF + qdst_off, pregates + qsrc_base);
    CP_COMMIT();
    csm[tid] = 0.0f;

    // warp geometry: km = k-slice (0..3, 128 k each), wm = m16 tile (0/1)
    const int km = wid >> 1, wm = wid & 1;
    const int kbase = km * 256;                   // byte offset of k-slice in row
    const int rowA = wm * 16 + (lane & 15);
    const int kxA  = (lane >> 4) * 16;
    const int sxA  = (rowA & 7) * 16;
    const int rb   = lane & 7;                    // B batch-row within group
    const int kxB  = ((lane >> 3) & 3) * 16;
    const int sxB  = rb * 16;
    const uint32_t wsb = sb + LWS_OFF, hsb = sb + LHS_OFF;

    // wait Ws + pg(t0), then hoist A fragments (time-invariant) into registers
    asm volatile("cp.async.wait_group 0;" ::: "memory");
    __syncthreads();
    uint32_t afr[4][2][4];
#pragma unroll
    for (int ks = 0; ks < 4; ks++) {
        int kb = kbase + ks * 64;
        ldsm4(afr[ks][0], wsb + (uint32_t)(rowA * 1024 + ((kb + kxA) ^ sxA)));
        ldsm4(afr[ks][1], wsb + (uint32_t)(rowA * 1024 + ((kb + 32 + kxA) ^ sxA)));
    }

    const int pb = tid >> 3, pul = tid & 7;
    const int pu = u0 + pul;

    for (int t = 0; t < TT; t++) {
        // stage h (fp16 32x512) into swizzled SMEM
        const __half* hin = (t & 1) ? hB : hA;
        for (int i = tid; i < 2048; i += 256) {
            int b = i >> 6, cq = i & 63;
            uint32_t dst = hsb + (uint32_t)(b * 1024 + ((cq * 16) ^ ((b & 7) * 16)));
            cpasync16(dst, hin + b * HID + cq * 8);
        }
        CP_COMMIT();
        if (t + 1 < TT) {
            // prefetch pregates(t+1) into the other buffer; stays in flight
            cpasync16(sb + LPG_OFF + ((t + 1) & 1) * 4096 + qdst_off,
                      pregates + qsrc_base + (size_t)(t + 1) * G4);
            CP_COMMIT();
            asm volatile("cp.async.wait_group 1;" ::: "memory");
        } else {
            asm volatile("cp.async.wait_group 0;" ::: "memory");
        }
        __syncthreads();

        // MMA: warp computes [16 gate-rows x 32 batch] over its k-slice of 128
        float cacc[4][4];
#pragma unroll
        for (int j = 0; j < 4; j++)
#pragma unroll
            for (int e = 0; e < 4; e++) cacc[j][e] = 0.f;
#pragma unroll
        for (int ks = 0; ks < 4; ks++) {
            int kb = kbase + ks * 64;
            uint32_t bf[4][4];
#pragma unroll
            for (int j = 0; j < 4; j++)
                ldsm4(bf[j], hsb + (uint32_t)((j * 8 + rb) * 1024 + ((kb + kxB) ^ sxB)));
#pragma unroll
            for (int j = 0; j < 4; j++) {
                mma16816(cacc[j], afr[ks][0], bf[j][0], bf[j][1]);
                mma16816(cacc[j], afr[ks][1], bf[j][2], bf[j][3]);
            }
        }
        // store partials to this k-slice's gsm buffer
        {
            float* gk = gsm + km * GK;
            int r0 = wm * 16 + (lane >> 2);
            int cc = (lane & 3) * 2;
#pragma unroll
            for (int j = 0; j < 4; j++) {
                gk[r0 * 33 + cc + j * 8]           = cacc[j][0];
                gk[r0 * 33 + cc + j * 8 + 1]       = cacc[j][1];
                gk[(r0 + 8) * 33 + cc + j * 8]     = cacc[j][2];
                gk[(r0 + 8) * 33 + cc + j * 8 + 1] = cacc[j][3];
            }
        }
        __syncthreads();

        // pointwise: 256 threads = 32 b x 8 units; sum 4 k-partials + pregates
        {
            const float* pgs = (const float*)(smem + LPG_OFF + (t & 1) * 4096);
            float gi = pgs[pb * 32 + 0 * 8 + pul];
            float gf = pgs[pb * 32 + 1 * 8 + pul];
            float gg = pgs[pb * 32 + 2 * 8 + pul];
            float go = pgs[pb * 32 + 3 * 8 + pul];
#pragma unroll
            for (int k = 0; k < 4; k++) {
                const float* gk = gsm + k * GK;
                gi += gk[(0  + pul) * 33 + pb];
                gf += gk[(8  + pul) * 33 + pb];
                gg += gk[(16 + pul) * 33 + pb];
                go += gk[(24 + pul) * 33 + pb];
            }
            float c_old = csm[tid];
            float cn = sigf(gf) * c_old + sigf(gi) * tanhf(gg);
            float hn = sigf(go) * tanhf(cn);
            csm[tid] = cn;
            __half hh = __float2half(hn);
            __half* hout = (t & 1) ? hA : hB;
            hout[pb * HID + pu] = hh;
            H2[((size_t)pb * TT + t) * HID + pu] = hh;
        }

        if (t < TT - 1) {
            // grouped-counter grid barrier
            __syncthreads();                 // all h stores done (CTA scope)
            if (tid == 0) {
                __threadfence();             // publish h stores (gpu scope)
                atomicAdd(&bars[(blockIdx.x & 7) * 64], 1);
            }
            if (tid < 8) {
                int target = 8 * (t + 1);
                while (*(volatile int*)&bars[tid * 64] < target) { }
                __threadfence();             // acquire side
            }
            __syncthreads();
        }
    }
}

// ---------------- launch ------------------------------------------------------
extern "C" void kernel_launch(void* const* d_in, const int* in_sizes, int n_in,
                              void* d_out, int out_size)
{
    const float* enc       = (const float*)d_in[0];
    const int*   captions  = (const int*)  d_in[1];
    const float* emb_table = (const float*)d_in[8];
    const float* W_ih      = (const float*)d_in[9];
    const float* W_hh      = (const float*)d_in[10];
    const float* b_ih      = (const float*)d_in[11];
    const float* b_hh      = (const float*)d_in[12];
    const float* W_fc      = (const float*)d_in[13];
    const float* b_fc      = (const float*)d_in[14];
    float* out = (float*)d_out;

    __half *pX2, *pWih2, *pWhh2, *pWfc2, *pH2, *ph2A, *ph2B;
    float *pPG;
    int* pBars;
    cudaGetSymbolAddress((void**)&pX2, g_X2);
    cudaGetSymbolAddress((void**)&pWih2, g_Wih2);
    cudaGetSymbolAddress((void**)&pWhh2, g_Whh2);
    cudaGetSymbolAddress((void**)&pWfc2, g_Wfc2);
    cudaGetSymbolAddress((void**)&pH2, g_H2);
    cudaGetSymbolAddress((void**)&ph2A, g_h2A);
    cudaGetSymbolAddress((void**)&ph2B, g_h2B);
    cudaGetSymbolAddress((void**)&pPG, g_pg);
    cudaGetSymbolAddress((void**)&pBars, g_bars);

    cudaFuncSetAttribute(hmma_gemm, cudaFuncAttributeMaxDynamicSharedMemorySize, GSMEM);
    cudaFuncSetAttribute(lstm_persistent, cudaFuncAttributeMaxDynamicSharedMemorySize, LSM_BYTES);

    // 1) fused fp32 -> fp16 weight converts
    {
        int total = N2_WIH + N2_WHH + N2_WFC;
        cvt_all_kernel<<<(total + 255) / 256, 256>>>(W_ih, W_hh, W_fc,
                                                     pWih2, pWhh2, pWfc2);
    }

    // 2) build X2, zero FULL h ping + barrier counters reset
    prep_kernel<<<MROWS + 32, 256>>>(enc, captions, emb_table, pX2, ph2A, pBars);

    // 3) pregates = X @ W_ih^T + b_ih + b_hh   (K = 768)
    {
        dim3 grid(G4 / 128, MROWS / 128);
        hmma_gemm<<<grid, 128, GSMEM>>>(pX2, pWih2, pPG, b_ih, b_hh,
                                        MROWS, G4, XD);
    }

    // 4) persistent tensor-core LSTM (one launch, emits H2 inline)
    lstm_persistent<<<64, 256, LSM_BYTES>>>(pPG, pWhh2, ph2A, ph2B, pH2, pBars);

    // 5) out = H @ W_fc^T + b_fc   (K = 512)
    {
        dim3 grid((VV + 127) / 128, MROWS / 128);
        hmma_gemm<<<grid, 128, GSMEM>>>(pH2, pWfc2, out, b_fc, nullptr,
                                        MROWS, VV, HID);
    }
}

// round 12
// speedup vs baseline: 1.6659x; 1.1637x over previous
#include <cuda_runtime.h>
#include <cuda_fp16.h>
#include <math.h>
#include <stdint.h>

// Problem dims
#define TT   64
#define VV   30000
#define HID  512
#define XD   768          // EMB + E
#define G4   2048         // 4*H
#define MROWS 2048        // B*T
#define NTILES_N 235      // ceil(30000/128)
#define NTILES_M 16
#define NTILES_TOT (NTILES_M * NTILES_N)

// ---------------- scratch (device globals; no allocation allowed) -------------
__device__ __align__(16) __half g_X2  [MROWS * XD];          // fp16 X (b-major)
__device__ __align__(16) __half g_Wih2[G4 * XD];             // fp16 W_ih
__device__ __align__(16) __half g_Whh2[G4 * HID];            // fp16 W_hh
__device__ __align__(16) __half g_Wfc2[(size_t)VV * HID];    // fp16 W_fc
__device__ __align__(16) __half g_H2  [MROWS * HID];         // fp16 hidden, T-MAJOR (row = t*32+b)
__device__ __align__(16) __half g_h2A [32 * HID];            // h state ping
__device__ __align__(16) __half g_h2B [32 * HID];            // h state pong
__device__ __align__(16) float  g_pg[MROWS * G4];            // pregates fp32 (b-major)
__device__ __align__(16) int    g_bars[512];                 // 8 counters, 256B apart
__device__ int g_ticket;

// ---------------- small helpers ------------------------------------------------
__device__ __forceinline__ uint32_t smem_u32(const void* p) {
    uint32_t a;
    asm("{ .reg .u64 t; cvta.to.shared.u64 t, %1; cvt.u32.u64 %0, t; }" : "=r"(a) : "l"(p));
    return a;
}
__device__ __forceinline__ void ldsm4(uint32_t* r, uint32_t addr) {
    asm volatile("ldmatrix.sync.aligned.m8n8.x4.shared.b16 {%0,%1,%2,%3}, [%4];"
                 : "=r"(r[0]), "=r"(r[1]), "=r"(r[2]), "=r"(r[3]) : "r"(addr));
}
__device__ __forceinline__ void mma16816(float* d, const uint32_t* a,
                                         uint32_t b0, uint32_t b1) {
    asm volatile("mma.sync.aligned.m16n8k16.row.col.f32.f16.f16.f32 "
                 "{%0,%1,%2,%3}, {%4,%5,%6,%7}, {%8,%9}, {%0,%1,%2,%3};"
                 : "+f"(d[0]), "+f"(d[1]), "+f"(d[2]), "+f"(d[3])
                 : "r"(a[0]), "r"(a[1]), "r"(a[2]), "r"(a[3]), "r"(b0), "r"(b1));
}
__device__ __forceinline__ void cpasync16(uint32_t dst, const void* src) {
    asm volatile("cp.async.cg.shared.global [%0], [%1], 16;" :: "r"(dst), "l"(src));
}
__device__ __forceinline__ void cpasync16z(uint32_t dst, const void* src, unsigned sz) {
    asm volatile("cp.async.cg.shared.global [%0], [%1], 16, %2;"
                 :: "r"(dst), "l"(src), "r"(sz));
}
#define CP_COMMIT() asm volatile("cp.async.commit_group;" ::: "memory")
__device__ __forceinline__ int ld_acq(const int* p) {
    int v;
    asm volatile("ld.acquire.gpu.global.b32 %0, [%1];" : "=r"(v) : "l"(p) : "memory");
    return v;
}

// ---------------- fused fp32 -> fp16 converts (W_ih, W_hh, W_fc) ---------------
#define N2_WIH (G4 * XD / 2)
#define N2_WHH (G4 * HID / 2)
#define N2_WFC (VV * HID / 2)
__global__ void cvt_all_kernel(const float* __restrict__ Wih,
                               const float* __restrict__ Whh,
                               const float* __restrict__ Wfc,
                               __half* __restrict__ dWih,
                               __half* __restrict__ dWhh,
                               __half* __restrict__ dWfc)
{
    int i = blockIdx.x * 256 + threadIdx.x;
    const float* src;
    __half* dst;
    if (i < N2_WIH)                 { src = Wih; dst = dWih; }
    else if (i < N2_WIH + N2_WHH)   { src = Whh; dst = dWhh; i -= N2_WIH; }
    else                            { src = Wfc; dst = dWfc; i -= N2_WIH + N2_WHH;
                                      if (i >= N2_WFC) return; }
    float2 v = ((const float2*)src)[i];
    ((__half2*)dst)[i] = __floats2half2_rn(v.x, v.y);
}

// ---------------- prep: X2 = fp16([emb||enc]); zero h ping + counters ----------
__global__ void prep_kernel(const float* __restrict__ enc,
                            const int*   __restrict__ captions,
                            const float* __restrict__ emb_table,
                            __half* __restrict__ X2,
                            __half* __restrict__ h0, int* __restrict__ bars,
                            int* __restrict__ ticket)
{
    int blk = blockIdx.x;
    if (blk < MROWS) {
        int b = blk >> 6;
        int cap = captions[blk];
        const float* erow = emb_table + (size_t)cap * 512;
        const float* crow = enc + (size_t)b * 256;
        size_t base = (size_t)blk * XD;
        for (int c = threadIdx.x; c < XD; c += 256) {
            float x = (c < 512) ? erow[c] : crow[c - 512];
            X2[base + c] = __float2half(x);
        }
    } else {
        int i = (blk - MROWS) * 256 + threadIdx.x;   // 0..8191
        ((uint32_t*)h0)[i] = 0u;
        if (i < 512) bars[i] = 0;
        if (i == 0) *ticket = 0;
    }
}

// ---------------- GEMM mainloop shared geometry --------------------------------
#define KC 64
#define STAGE_BYTES 32768      // A 16KB + B 16KB
#define GSMEM (3 * STAGE_BYTES)

// ---------------- HMMA GEMM (pregates): C = A B^T + bias0 + bias1 -------------
__global__ __launch_bounds__(128, 2) void hmma_gemm(
    const __half* __restrict__ A, const __half* __restrict__ B,
    float* __restrict__ C,
    const float* __restrict__ bias0, const float* __restrict__ bias1,
    int M, int N, int K)
{
    extern __shared__ char smem[];
    const uint32_t sb = smem_u32(smem);
    const int tid  = threadIdx.x;
    const int lane = tid & 31, wid = tid >> 5;
    const int m0 = blockIdx.y * 128, n0 = blockIdx.x * 128;
    const int wm = wid & 1, wn = wid >> 1;
    const int nch = K / KC;

    const int rowA = wm * 64 + (lane & 7) + ((lane >> 3) & 1) * 8;
    const int kxA  = ((lane >> 4) * 16) ^ ((rowA & 7) * 16);
    const int rowB = wn * 64 + (lane & 7) + ((lane >= 16) ? 8 : 0);
    const int kxB  = (((lane >> 3) & 1) * 16) ^ ((rowB & 7) * 16);

    float acc[4][8][4];
#pragma unroll
    for (int i = 0; i < 4; i++)
#pragma unroll
        for (int j = 0; j < 8; j++)
#pragma unroll
            for (int e = 0; e < 4; e++) acc[i][j][e] = 0.f;

    const int prow = tid >> 3;
    const int pcc  = tid & 7;
#define PREFETCH(stage, kt)                                                     \
    do {                                                                        \
        uint32_t ab = sb + (stage) * STAGE_BYTES;                               \
        _Pragma("unroll")                                                       \
        for (int j = 0; j < 8; j++) {                                           \
            int row = prow + j * 16;                                            \
            uint32_t dst = ab + (uint32_t)(row * 128 + ((pcc * 16) ^ ((row & 7) * 16))); \
            cpasync16(dst, A + (size_t)(m0 + row) * K + (kt) + pcc * 8);        \
        }                                                                       \
        _Pragma("unroll")                                                       \
        for (int j = 0; j < 8; j++) {                                           \
            int row = prow + j * 16;                                            \
            int gn = n0 + row;                                                  \
            uint32_t dst = ab + 16384u + (uint32_t)(row * 128 + ((pcc * 16) ^ ((row & 7) * 16))); \
            int gnc = gn < N ? gn : N - 1;                                      \
            cpasync16z(dst, B + (size_t)gnc * K + (kt) + pcc * 8,               \
                       gn < N ? 16u : 0u);                                      \
        }                                                                       \
        CP_COMMIT();                                                            \
    } while (0)

    PREFETCH(0, 0);
    PREFETCH(1, KC);
    for (int c = 0; c < nch; c++) {
        if (c + 2 < nch) PREFETCH((c + 2) % 3, (c + 2) * KC);
        if (c + 2 < nch)      asm volatile("cp.async.wait_group 2;" ::: "memory");
        else if (c + 1 < nch) asm volatile("cp.async.wait_group 1;" ::: "memory");
        else                  asm volatile("cp.async.wait_group 0;" ::: "memory");
        __syncthreads();
        const uint32_t As = sb + (c % 3) * STAGE_BYTES;
        const uint32_t Bs = As + 16384;
#pragma unroll
        for (int ks = 0; ks < 4; ks++) {
            uint32_t a[4][4], b[4][4];
#pragma unroll
            for (int mt = 0; mt < 4; mt++)
                ldsm4(a[mt], As + (uint32_t)((rowA + mt * 16) * 128 + ((ks * 32) ^ kxA)));
#pragma unroll
            for (int j = 0; j < 4; j++)
                ldsm4(b[j], Bs + (uint32_t)((rowB + j * 16) * 128 + ((ks * 32) ^ kxB)));
#pragma unroll
            for (int mt = 0; mt < 4; mt++)
#pragma unroll
                for (int nt = 0; nt < 8; nt++)
                    mma16816(acc[mt][nt], a[mt],
                             b[nt >> 1][(nt & 1) * 2], b[nt >> 1][(nt & 1) * 2 + 1]);
        }
        __syncthreads();
    }

    const int mrow  = m0 + wm * 64 + (lane >> 2);
    const int ncol0 = n0 + wn * 64 + (lane & 3) * 2;
#pragma unroll
    for (int mt = 0; mt < 4; mt++) {
#pragma unroll
        for (int nt = 0; nt < 8; nt++) {
            int cc = ncol0 + nt * 8;
            if (cc < N) {
                float b0v = bias0[cc], b1v = bias0[cc + 1];
                if (bias1) { b0v += bias1[cc]; b1v += bias1[cc + 1]; }
                int r0 = mrow + mt * 16;
                float2 v0 = make_float2(acc[mt][nt][0] + b0v, acc[mt][nt][1] + b1v);
                float2 v1 = make_float2(acc[mt][nt][2] + b0v, acc[mt][nt][3] + b1v);
                *(float2*)(C + (size_t)r0 * N + cc)       = v0;
                *(float2*)(C + (size_t)(r0 + 8) * N + cc) = v1;
            }
        }
    }
#undef PREFETCH
}

// ---------------- output-GEMM worker (PDL secondary) ---------------------------
// Persistent workers; tickets over 16 m-tiles x 235 n-tiles (m slowest).
// A = H2 (t-major, row = t*32+b); tile m ready when every bars group counter
// >= 32*(m+1) (LSTM releases h/H2 stores before each arrival).
// Epilogue remaps row t*32+b -> out row b*64+t.
__global__ __launch_bounds__(128, 2) void gemm_worker(
    const __half* __restrict__ A, const __half* __restrict__ B,
    float* __restrict__ C, const float* __restrict__ bias0,
    int* __restrict__ bars, int* __restrict__ ticket)
{
    extern __shared__ char smem[];
    __shared__ int tix;
    const uint32_t sb = smem_u32(smem);
    const int tid  = threadIdx.x;
    const int lane = tid & 31, wid = tid >> 5;
    const int wm = wid & 1, wn = wid >> 1;
    const int K = HID, N = VV;

    const int rowA = wm * 64 + (lane & 7) + ((lane >> 3) & 1) * 8;
    const int kxA  = ((lane >> 4) * 16) ^ ((rowA & 7) * 16);
    const int rowB = wn * 64 + (lane & 7) + ((lane >= 16) ? 8 : 0);
    const int kxB  = (((lane >> 3) & 1) * 16) ^ ((rowB & 7) * 16);
    const int prow = tid >> 3;
    const int pcc  = tid & 7;

    for (;;) {
        if (tid == 0) tix = atomicAdd(ticket, 1);
        __syncthreads();
        int tk = tix;
        __syncthreads();
        if (tk >= NTILES_TOT) return;
        const int m  = tk / NTILES_N;
        const int m0 = m * 128;
        const int n0 = (tk - m * NTILES_N) * 128;

        // wait until LSTM step 4m+3 is published (all 8 group counters)
        if (tid < 8) {
            const int target = 32 * (m + 1);
            while (ld_acq(&bars[tid * 64]) < target) { }
        }
        __syncthreads();

        float acc[4][8][4];
#pragma unroll
        for (int i = 0; i < 4; i++)
#pragma unroll
            for (int j = 0; j < 8; j++)
#pragma unroll
                for (int e = 0; e < 4; e++) acc[i][j][e] = 0.f;

#define WPREFETCH(stage, kt)                                                    \
    do {                                                                        \
        uint32_t ab = sb + (stage) * STAGE_BYTES;                               \
        _Pragma("unroll")                                                       \
        for (int j = 0; j < 8; j++) {                                           \
            int row = prow + j * 16;                                            \
            uint32_t dst = ab + (uint32_t)(row * 128 + ((pcc * 16) ^ ((row & 7) * 16))); \
            cpasync16(dst, A + (size_t)(m0 + row) * K + (kt) + pcc * 8);        \
        }                                                                       \
        _Pragma("unroll")                                                       \
        for (int j = 0; j < 8; j++) {                                           \
            int row = prow + j * 16;                                            \
            int gn = n0 + row;                                                  \
            uint32_t dst = ab + 16384u + (uint32_t)(row * 128 + ((pcc * 16) ^ ((row & 7) * 16))); \
            int gnc = gn < N ? gn : N - 1;                                      \
            cpasync16z(dst, B + (size_t)gnc * K + (kt) + pcc * 8,               \
                       gn < N ? 16u : 0u);                                      \
        }                                                                       \
        CP_COMMIT();                                                            \
    } while (0)

        WPREFETCH(0, 0);
        WPREFETCH(1, KC);
#pragma unroll 1
        for (int c = 0; c < 8; c++) {          // nch = 512/64 = 8
            if (c + 2 < 8) WPREFETCH((c + 2) % 3, (c + 2) * KC);
            if (c + 2 < 8)      asm volatile("cp.async.wait_group 2;" ::: "memory");
            else if (c + 1 < 8) asm volatile("cp.async.wait_group 1;" ::: "memory");
            else                asm volatile("cp.async.wait_group 0;" ::: "memory");
            __syncthreads();
            const uint32_t As = sb + (c % 3) * STAGE_BYTES;
            const uint32_t Bs = As + 16384;
#pragma unroll
            for (int ks = 0; ks < 4; ks++) {
                uint32_t a[4][4], b[4][4];
#pragma unroll
                for (int mt = 0; mt < 4; mt++)
                    ldsm4(a[mt], As + (uint32_t)((rowA + mt * 16) * 128 + ((ks * 32) ^ kxA)));
#pragma unroll
                for (int j = 0; j < 4; j++)
                    ldsm4(b[j], Bs + (uint32_t)((rowB + j * 16) * 128 + ((ks * 32) ^ kxB)));
#pragma unroll
                for (int mt = 0; mt < 4; mt++)
#pragma unroll
                    for (int nt = 0; nt < 8; nt++)
                        mma16816(acc[mt][nt], a[mt],
                                 b[nt >> 1][(nt & 1) * 2], b[nt >> 1][(nt & 1) * 2 + 1]);
            }
            __syncthreads();
        }
#undef WPREFETCH

        const int mrow  = m0 + wm * 64 + (lane >> 2);
        const int ncol0 = n0 + wn * 64 + (lane & 3) * 2;
#pragma unroll
        for (int mt = 0; mt < 4; mt++) {
#pragma unroll
            for (int nt = 0; nt < 8; nt++) {
                int cc = ncol0 + nt * 8;
                if (cc < N) {
                    float b0v = bias0[cc], b1v = bias0[cc + 1];
                    int r0 = mrow + mt * 16;
                    int or0 = (r0 & 31) * 64 + (r0 >> 5);        // b*64 + t
                    int or1 = ((r0 + 8) & 31) * 64 + ((r0 + 8) >> 5);
                    float2 v0 = make_float2(acc[mt][nt][0] + b0v, acc[mt][nt][1] + b1v);
                    float2 v1 = make_float2(acc[mt][nt][2] + b0v, acc[mt][nt][3] + b1v);
                    *(float2*)(C + (size_t)or0 * N + cc) = v0;
                    *(float2*)(C + (size_t)or1 * N + cc) = v1;
                }
            }
        }
    }
}

// ---------------- persistent LSTM, tensor-core recurrence ----------------------
// (R11 structure; H2 now t-major; arrival unconditional so workers see t=63.)
#define LWS_OFF  0
#define LHS_OFF  32768
#define LPG_OFF  65536
#define LGSM_OFF (65536 + 8192)
#define GK (32 * 33)
#define LCSM_OFF (LGSM_OFF + 4 * GK * 4)
#define LSM_BYTES (LCSM_OFF + 256 * 4)

__device__ __forceinline__ float sigf(float x) { return 1.0f / (1.0f + expf(-x)); }

__global__ __launch_bounds__(256, 1) void lstm_persistent(
    const float* __restrict__ pregates,
    const __half* __restrict__ Whh2,
    __half* __restrict__ hA, __half* __restrict__ hB,
    __half* __restrict__ H2, int* __restrict__ bars)
{
    extern __shared__ char smem[];
    const uint32_t sb = smem_u32(smem);
    float* gsm = (float*)(smem + LGSM_OFF);
    float* csm = (float*)(smem + LCSM_OFF);

    const int tid  = threadIdx.x;
    const int lane = tid & 31, wid = tid >> 5;
    const int u0   = blockIdx.x * 8;

    // PDL: release the dependent output-GEMM launch immediately
    if (tid == 0) cudaTriggerProgrammaticLaunchCompletion();

    const int qb = tid >> 3, qg = (tid >> 1) & 3, qh = tid & 1;
    const size_t qsrc_base = (size_t)qb * TT * G4 + qg * 512 + u0 + qh * 4;
    const uint32_t qdst_off = (uint32_t)(qb * 128 + qg * 32 + qh * 16);

    for (int i = tid; i < 2048; i += 256) {
        int rr = i >> 6, cq = i & 63;
        int g = rr >> 3, ul = rr & 7;
        uint32_t dst = sb + LWS_OFF + (uint32_t)(rr * 1024 + ((cq * 16) ^ ((rr & 7) * 16)));
        cpasync16(dst, Whh2 + (size_t)(g * 512 + u0 + ul) * HID + cq * 8);
    }
    CP_COMMIT();
    cpasync16(sb + LPG_OFF + qdst_off, pregates + qsrc_base);
    CP_COMMIT();
    csm[tid] = 0.0f;

    const int km = wid >> 1, wm = wid & 1;
    const int kbase = km * 256;
    const int rowA = wm * 16 + (lane & 15);
    const int kxA  = (lane >> 4) * 16;
    const int sxA  = (rowA & 7) * 16;
    const int rb   = lane & 7;
    const int kxB  = ((lane >> 3) & 3) * 16;
    const int sxB  = rb * 16;
    const uint32_t wsb = sb + LWS_OFF, hsb = sb + LHS_OFF;

    asm volatile("cp.async.wait_group 0;" ::: "memory");
    __syncthreads();
    uint32_t afr[4][2][4];
#pragma unroll
    for (int ks = 0; ks < 4; ks++) {
        int kb = kbase + ks * 64;
        ldsm4(afr[ks][0], wsb + (uint32_t)(rowA * 1024 + ((kb + kxA) ^ sxA)));
        ldsm4(afr[ks][1], wsb + (uint32_t)(rowA * 1024 + ((kb + 32 + kxA) ^ sxA)));
    }

    const int pb = tid >> 3, pul = tid & 7;
    const int pu = u0 + pul;

    for (int t = 0; t < TT; t++) {
        const __half* hin = (t & 1) ? hB : hA;
        for (int i = tid; i < 2048; i += 256) {
            int b = i >> 6, cq = i & 63;
            uint32_t dst = hsb + (uint32_t)(b * 1024 + ((cq * 16) ^ ((b & 7) * 16)));
            cpasync16(dst, hin + b * HID + cq * 8);
        }
        CP_COMMIT();
        if (t + 1 < TT) {
            cpasync16(sb + LPG_OFF + ((t + 1) & 1) * 4096 + qdst_off,
                      pregates + qsrc_base + (size_t)(t + 1) * G4);
            CP_COMMIT();
            asm volatile("cp.async.wait_group 1;" ::: "memory");
        } else {
            asm volatile("cp.async.wait_group 0;" ::: "memory");
        }
        __syncthreads();

        float cacc[4][4];
#pragma unroll
        for (int j = 0; j < 4; j++)
#pragma unroll
            for (int e = 0; e < 4; e++) cacc[j][e] = 0.f;
#pragma unroll
        for (int ks = 0; ks < 4; ks++) {
            int kb = kbase + ks * 64;
            uint32_t bf[4][4];
#pragma unroll
            for (int j = 0; j < 4; j++)
                ldsm4(bf[j], hsb + (uint32_t)((j * 8 + rb) * 1024 + ((kb + kxB) ^ sxB)));
#pragma unroll
            for (int j = 0; j < 4; j++) {
                mma16816(cacc[j], afr[ks][0], bf[j][0], bf[j][1]);
                mma16816(cacc[j], afr[ks][1], bf[j][2], bf[j][3]);
            }
        }
        {
            float* gk = gsm + km * GK;
            int r0 = wm * 16 + (lane >> 2);
            int cc = (lane & 3) * 2;
#pragma unroll
            for (int j = 0; j < 4; j++) {
                gk[r0 * 33 + cc + j * 8]           = cacc[j][0];
                gk[r0 * 33 + cc + j * 8 + 1]       = cacc[j][1];
                gk[(r0 + 8) * 33 + cc + j * 8]     = cacc[j][2];
                gk[(r0 + 8) * 33 + cc + j * 8 + 1] = cacc[j][3];
            }
        }
        __syncthreads();

        {
            const float* pgs = (const float*)(smem + LPG_OFF + (t & 1) * 4096);
            float gi = pgs[pb * 32 + 0 * 8 + pul];
            float gf = pgs[pb * 32 + 1 * 8 + pul];
            float gg = pgs[pb * 32 + 2 * 8 + pul];
            float go = pgs[pb * 32 + 3 * 8 + pul];
#pragma unroll
            for (int k = 0; k < 4; k++) {
                const float* gk = gsm + k * GK;
                gi += gk[(0  + pul) * 33 + pb];
                gf += gk[(8  + pul) * 33 + pb];
                gg += gk[(16 + pul) * 33 + pb];
                go += gk[(24 + pul) * 33 + pb];
            }
            float c_old = csm[tid];
            float cn = sigf(gf) * c_old + sigf(gi) * tanhf(gg);
            float hn = sigf(go) * tanhf(cn);
            csm[tid] = cn;
            __half hh = __float2half(hn);
            __half* hout = (t & 1) ? hA : hB;
            hout[pb * HID + pu] = hh;
            H2[((size_t)t * 32 + pb) * HID + pu] = hh;   // T-MAJOR
        }

        // arrival every step (progress signal for workers); wait except last
        __syncthreads();
        if (tid == 0) {
            __threadfence();
            atomicAdd(&bars[(blockIdx.x & 7) * 64], 1);
        }
        if (t < TT - 1) {
            if (tid < 8) {
                int target = 8 * (t + 1);
                while (*(volatile int*)&bars[tid * 64] < target) { }
                __threadfence();
            }
            __syncthreads();
        }
    }
}

// ---------------- launch ------------------------------------------------------
extern "C" void kernel_launch(void* const* d_in, const int* in_sizes, int n_in,
                              void* d_out, int out_size)
{
    const float* enc       = (const float*)d_in[0];
    const int*   captions  = (const int*)  d_in[1];
    const float* emb_table = (const float*)d_in[8];
    const float* W_ih      = (const float*)d_in[9];
    const float* W_hh      = (const float*)d_in[10];
    const float* b_ih      = (const float*)d_in[11];
    const float* b_hh      = (const float*)d_in[12];
    const float* W_fc      = (const float*)d_in[13];
    const float* b_fc      = (const float*)d_in[14];
    float* out = (float*)d_out;

    __half *pX2, *pWih2, *pWhh2, *pWfc2, *pH2, *ph2A, *ph2B;
    float *pPG;
    int *pBars, *pTicket;
    cudaGetSymbolAddress((void**)&pX2, g_X2);
    cudaGetSymbolAddress((void**)&pWih2, g_Wih2);
    cudaGetSymbolAddress((void**)&pWhh2, g_Whh2);
    cudaGetSymbolAddress((void**)&pWfc2, g_Wfc2);
    cudaGetSymbolAddress((void**)&pH2, g_H2);
    cudaGetSymbolAddress((void**)&ph2A, g_h2A);
    cudaGetSymbolAddress((void**)&ph2B, g_h2B);
    cudaGetSymbolAddress((void**)&pPG, g_pg);
    cudaGetSymbolAddress((void**)&pBars, g_bars);
    cudaGetSymbolAddress((void**)&pTicket, g_ticket);

    cudaFuncSetAttribute(hmma_gemm, cudaFuncAttributeMaxDynamicSharedMemorySize, GSMEM);
    cudaFuncSetAttribute(gemm_worker, cudaFuncAttributeMaxDynamicSharedMemorySize, GSMEM);
    cudaFuncSetAttribute(lstm_persistent, cudaFuncAttributeMaxDynamicSharedMemorySize, LSM_BYTES);

    // 1) fused fp32 -> fp16 weight converts
    {
        int total = N2_WIH + N2_WHH + N2_WFC;
        cvt_all_kernel<<<(total + 255) / 256, 256>>>(W_ih, W_hh, W_fc,
                                                     pWih2, pWhh2, pWfc2);
    }

    // 2) build X2, zero h ping + counters + ticket
    prep_kernel<<<MROWS + 32, 256>>>(enc, captions, emb_table, pX2, ph2A,
                                     pBars, pTicket);

    // 3) pregates = X @ W_ih^T + b_ih + b_hh   (K = 768)
    {
        dim3 grid(G4 / 128, MROWS / 128);
        hmma_gemm<<<grid, 128, GSMEM>>>(pX2, pWih2, pPG, b_ih, b_hh,
                                        MROWS, G4, XD);
    }

    // 4) persistent tensor-core LSTM (PDL primary; triggers early)
    lstm_persistent<<<64, 256, LSM_BYTES>>>(pPG, pWhh2, ph2A, ph2B, pH2, pBars);

    // 5) output-GEMM workers — PDL secondary (overlaps the LSTM; falls back to
    //    a plain launch if the attribute is rejected: then all progress is
    //    already complete and workers run sequentially, still correct).
    {
        cudaLaunchConfig_t cfg = {};
        cfg.gridDim = dim3(296, 1, 1);
        cfg.blockDim = dim3(128, 1, 1);
        cfg.dynamicSmemBytes = GSMEM;
        cfg.stream = 0;
        cudaLaunchAttribute at[1];
        at[0].id = cudaLaunchAttributeProgrammaticStreamSerialization;
        at[0].val.programmaticStreamSerializationAllowed = 1;
        cfg.attrs = at;
        cfg.numAttrs = 1;
        cudaError_t e = cudaLaunchKernelEx(&cfg, gemm_worker,
                                           (const __half*)pH2, (const __half*)pWfc2,
                                           out, b_fc, pBars, pTicket);
        if (e != cudaSuccess) {
            gemm_worker<<<296, 128, GSMEM>>>(pH2, pWfc2, out, b_fc, pBars, pTicket);
        }
    }
}

// round 13
// speedup vs baseline: 1.7706x; 1.0629x over previous
#include <cuda_runtime.h>
#include <cuda_fp16.h>
#include <math.h>
#include <stdint.h>

// Problem dims
#define TT   64
#define VV   30000
#define HID  512
#define XD   768          // EMB + E
#define G4   2048         // 4*H
#define MROWS 2048        // B*T
#define NTILES_N 235      // ceil(30000/128)
#define NTILES_M 16
#define NTILES_TOT (NTILES_M * NTILES_N)

// ---------------- scratch (device globals; no allocation allowed) -------------
__device__ __align__(16) __half g_X2  [MROWS * XD];          // fp16 X (b-major)
__device__ __align__(16) __half g_Wih2[G4 * XD];             // fp16 W_ih
__device__ __align__(16) __half g_Whh2[G4 * HID];            // fp16 W_hh
__device__ __align__(16) __half g_Wfc2[(size_t)VV * HID];    // fp16 W_fc
__device__ __align__(16) __half g_H2  [MROWS * HID];         // fp16 hidden, T-MAJOR (row = t*32+b)
__device__ __align__(16) __half g_h2A [32 * HID];            // h state ping
__device__ __align__(16) __half g_h2B [32 * HID];            // h state pong
__device__ __align__(16) float  g_pg[MROWS * G4];            // pregates fp32 (b-major)
__device__ __align__(16) int    g_bars[512];                 // 8 counters, 256B apart
__device__ int g_ticket;
__device__ int g_step;                                       // published LSTM progress

// ---------------- small helpers ------------------------------------------------
__device__ __forceinline__ uint32_t smem_u32(const void* p) {
    uint32_t a;
    asm("{ .reg .u64 t; cvta.to.shared.u64 t, %1; cvt.u32.u64 %0, t; }" : "=r"(a) : "l"(p));
    return a;
}
__device__ __forceinline__ void ldsm4(uint32_t* r, uint32_t addr) {
    asm volatile("ldmatrix.sync.aligned.m8n8.x4.shared.b16 {%0,%1,%2,%3}, [%4];"
                 : "=r"(r[0]), "=r"(r[1]), "=r"(r[2]), "=r"(r[3]) : "r"(addr));
}
__device__ __forceinline__ void mma16816(float* d, const uint32_t* a,
                                         uint32_t b0, uint32_t b1) {
    asm volatile("mma.sync.aligned.m16n8k16.row.col.f32.f16.f16.f32 "
                 "{%0,%1,%2,%3}, {%4,%5,%6,%7}, {%8,%9}, {%0,%1,%2,%3};"
                 : "+f"(d[0]), "+f"(d[1]), "+f"(d[2]), "+f"(d[3])
                 : "r"(a[0]), "r"(a[1]), "r"(a[2]), "r"(a[3]), "r"(b0), "r"(b1));
}
__device__ __forceinline__ void cpasync16(uint32_t dst, const void* src) {
    asm volatile("cp.async.cg.shared.global [%0], [%1], 16;" :: "r"(dst), "l"(src));
}
__device__ __forceinline__ void cpasync16z(uint32_t dst, const void* src, unsigned sz) {
    asm volatile("cp.async.cg.shared.global [%0], [%1], 16, %2;"
                 :: "r"(dst), "l"(src), "r"(sz));
}
#define CP_COMMIT() asm volatile("cp.async.commit_group;" ::: "memory")
__device__ __forceinline__ int ld_acq(const int* p) {
    int v;
    asm volatile("ld.acquire.gpu.global.b32 %0, [%1];" : "=r"(v) : "l"(p) : "memory");
    return v;
}
__device__ __forceinline__ void st_rel(int* p, int v) {
    asm volatile("st.release.gpu.global.b32 [%0], %1;" :: "l"(p), "r"(v) : "memory");
}

// ---------------- fused fp32 -> fp16 converts (W_ih, W_hh, W_fc) ---------------
#define N2_WIH (G4 * XD / 2)
#define N2_WHH (G4 * HID / 2)
#define N2_WFC (VV * HID / 2)
__global__ void cvt_all_kernel(const float* __restrict__ Wih,
                               const float* __restrict__ Whh,
                               const float* __restrict__ Wfc,
                               __half* __restrict__ dWih,
                               __half* __restrict__ dWhh,
                               __half* __restrict__ dWfc)
{
    int i = blockIdx.x * 256 + threadIdx.x;
    const float* src;
    __half* dst;
    if (i < N2_WIH)                 { src = Wih; dst = dWih; }
    else if (i < N2_WIH + N2_WHH)   { src = Whh; dst = dWhh; i -= N2_WIH; }
    else                            { src = Wfc; dst = dWfc; i -= N2_WIH + N2_WHH;
                                      if (i >= N2_WFC) return; }
    float2 v = ((const float2*)src)[i];
    ((__half2*)dst)[i] = __floats2half2_rn(v.x, v.y);
}

// ---------------- prep: X2 = fp16([emb||enc]); zero h ping + counters ----------
__global__ void prep_kernel(const float* __restrict__ enc,
                            const int*   __restrict__ captions,
                            const float* __restrict__ emb_table,
                            __half* __restrict__ X2,
                            __half* __restrict__ h0, int* __restrict__ bars,
                            int* __restrict__ ticket, int* __restrict__ stepf)
{
    int blk = blockIdx.x;
    if (blk < MROWS) {
        int b = blk >> 6;
        int cap = captions[blk];
        const float* erow = emb_table + (size_t)cap * 512;
        const float* crow = enc + (size_t)b * 256;
        size_t base = (size_t)blk * XD;
        for (int c = threadIdx.x; c < XD; c += 256) {
            float x = (c < 512) ? erow[c] : crow[c - 512];
            X2[base + c] = __float2half(x);
        }
    } else {
        int i = (blk - MROWS) * 256 + threadIdx.x;   // 0..8191
        ((uint32_t*)h0)[i] = 0u;
        if (i < 512) bars[i] = 0;
        if (i == 0) { *ticket = 0; *stepf = -1; }
    }
}

// ---------------- GEMM mainloop shared geometry --------------------------------
#define KC 64
#define STAGE_BYTES 32768      // A 16KB + B 16KB
#define GSMEM (3 * STAGE_BYTES)

// ---------------- HMMA GEMM (pregates): C = A B^T + bias0 + bias1 -------------
__global__ __launch_bounds__(128, 2) void hmma_gemm(
    const __half* __restrict__ A, const __half* __restrict__ B,
    float* __restrict__ C,
    const float* __restrict__ bias0, const float* __restrict__ bias1,
    int M, int N, int K)
{
    extern __shared__ char smem[];
    const uint32_t sb = smem_u32(smem);
    const int tid  = threadIdx.x;
    const int lane = tid & 31, wid = tid >> 5;
    const int m0 = blockIdx.y * 128, n0 = blockIdx.x * 128;
    const int wm = wid & 1, wn = wid >> 1;
    const int nch = K / KC;

    const int rowA = wm * 64 + (lane & 7) + ((lane >> 3) & 1) * 8;
    const int kxA  = ((lane >> 4) * 16) ^ ((rowA & 7) * 16);
    const int rowB = wn * 64 + (lane & 7) + ((lane >= 16) ? 8 : 0);
    const int kxB  = (((lane >> 3) & 1) * 16) ^ ((rowB & 7) * 16);

    float acc[4][8][4];
#pragma unroll
    for (int i = 0; i < 4; i++)
#pragma unroll
        for (int j = 0; j < 8; j++)
#pragma unroll
            for (int e = 0; e < 4; e++) acc[i][j][e] = 0.f;

    const int prow = tid >> 3;
    const int pcc  = tid & 7;
#define PREFETCH(stage, kt)                                                     \
    do {                                                                        \
        uint32_t ab = sb + (stage) * STAGE_BYTES;                               \
        _Pragma("unroll")                                                       \
        for (int j = 0; j < 8; j++) {                                           \
            int row = prow + j * 16;                                            \
            uint32_t dst = ab + (uint32_t)(row * 128 + ((pcc * 16) ^ ((row & 7) * 16))); \
            cpasync16(dst, A + (size_t)(m0 + row) * K + (kt) + pcc * 8);        \
        }                                                                       \
        _Pragma("unroll")                                                       \
        for (int j = 0; j < 8; j++) {                                           \
            int row = prow + j * 16;                                            \
            int gn = n0 + row;                                                  \
            uint32_t dst = ab + 16384u + (uint32_t)(row * 128 + ((pcc * 16) ^ ((row & 7) * 16))); \
            int gnc = gn < N ? gn : N - 1;                                      \
            cpasync16z(dst, B + (size_t)gnc * K + (kt) + pcc * 8,               \
                       gn < N ? 16u : 0u);                                      \
        }                                                                       \
        CP_COMMIT();                                                            \
    } while (0)

    PREFETCH(0, 0);
    PREFETCH(1, KC);
    for (int c = 0; c < nch; c++) {
        if (c + 2 < nch) PREFETCH((c + 2) % 3, (c + 2) * KC);
        if (c + 2 < nch)      asm volatile("cp.async.wait_group 2;" ::: "memory");
        else if (c + 1 < nch) asm volatile("cp.async.wait_group 1;" ::: "memory");
        else                  asm volatile("cp.async.wait_group 0;" ::: "memory");
        __syncthreads();
        const uint32_t As = sb + (c % 3) * STAGE_BYTES;
        const uint32_t Bs = As + 16384;
#pragma unroll
        for (int ks = 0; ks < 4; ks++) {
            uint32_t a[4][4], b[4][4];
#pragma unroll
            for (int mt = 0; mt < 4; mt++)
                ldsm4(a[mt], As + (uint32_t)((rowA + mt * 16) * 128 + ((ks * 32) ^ kxA)));
#pragma unroll
            for (int j = 0; j < 4; j++)
                ldsm4(b[j], Bs + (uint32_t)((rowB + j * 16) * 128 + ((ks * 32) ^ kxB)));
#pragma unroll
            for (int mt = 0; mt < 4; mt++)
#pragma unroll
                for (int nt = 0; nt < 8; nt++)
                    mma16816(acc[mt][nt], a[mt],
                             b[nt >> 1][(nt & 1) * 2], b[nt >> 1][(nt & 1) * 2 + 1]);
        }
        __syncthreads();
    }

    const int mrow  = m0 + wm * 64 + (lane >> 2);
    const int ncol0 = n0 + wn * 64 + (lane & 3) * 2;
#pragma unroll
    for (int mt = 0; mt < 4; mt++) {
#pragma unroll
        for (int nt = 0; nt < 8; nt++) {
            int cc = ncol0 + nt * 8;
            if (cc < N) {
                float b0v = bias0[cc], b1v = bias0[cc + 1];
                if (bias1) { b0v += bias1[cc]; b1v += bias1[cc + 1]; }
                int r0 = mrow + mt * 16;
                float2 v0 = make_float2(acc[mt][nt][0] + b0v, acc[mt][nt][1] + b1v);
                float2 v1 = make_float2(acc[mt][nt][2] + b0v, acc[mt][nt][3] + b1v);
                *(float2*)(C + (size_t)r0 * N + cc)       = v0;
                *(float2*)(C + (size_t)(r0 + 8) * N + cc) = v1;
            }
        }
    }
#undef PREFETCH
}

// ---------------- output-GEMM worker (PDL secondary) ---------------------------
// Persistent workers; tickets over 16 m-tiles x 235 n-tiles (m slowest).
// A = H2 (t-major, row = t*32+b); tile m ready when g_step >= 4m+3.
// Single poller per CTA with nanosleep backoff (no pressure on LSTM barrier
// lines). Epilogue remaps row t*32+b -> out row b*64+t.
__global__ __launch_bounds__(128, 2) void gemm_worker(
    const __half* __restrict__ A, const __half* __restrict__ B,
    float* __restrict__ C, const float* __restrict__ bias0,
    int* __restrict__ stepf, int* __restrict__ ticket)
{
    extern __shared__ char smem[];
    __shared__ int tix;
    const uint32_t sb = smem_u32(smem);
    const int tid  = threadIdx.x;
    const int lane = tid & 31, wid = tid >> 5;
    const int wm = wid & 1, wn = wid >> 1;
    const int K = HID, N = VV;

    const int rowA = wm * 64 + (lane & 7) + ((lane >> 3) & 1) * 8;
    const int kxA  = ((lane >> 4) * 16) ^ ((rowA & 7) * 16);
    const int rowB = wn * 64 + (lane & 7) + ((lane >= 16) ? 8 : 0);
    const int kxB  = (((lane >> 3) & 1) * 16) ^ ((rowB & 7) * 16);
    const int prow = tid >> 3;
    const int pcc  = tid & 7;

    for (;;) {
        if (tid == 0) tix = atomicAdd(ticket, 1);
        __syncthreads();
        int tk = tix;
        __syncthreads();
        if (tk >= NTILES_TOT) return;
        const int m  = tk / NTILES_N;
        const int m0 = m * 128;
        const int n0 = (tk - m * NTILES_N) * 128;

        // wait until LSTM published step 4m+3 (single poller, backoff)
        if (tid == 0) {
            const int target = 4 * m + 3;
            while (ld_acq(stepf) < target) __nanosleep(128);
        }
        __syncthreads();

        float acc[4][8][4];
#pragma unroll
        for (int i = 0; i < 4; i++)
#pragma unroll
            for (int j = 0; j < 8; j++)
#pragma unroll
                for (int e = 0; e < 4; e++) acc[i][j][e] = 0.f;

#define WPREFETCH(stage, kt)                                                    \
    do {                                                                        \
        uint32_t ab = sb + (stage) * STAGE_BYTES;                               \
        _Pragma("unroll")                                                       \
        for (int j = 0; j < 8; j++) {                                           \
            int row = prow + j * 16;                                            \
            uint32_t dst = ab + (uint32_t)(row * 128 + ((pcc * 16) ^ ((row & 7) * 16))); \
            cpasync16(dst, A + (size_t)(m0 + row) * K + (kt) + pcc * 8);        \
        }                                                                       \
        _Pragma("unroll")                                                       \
        for (int j = 0; j < 8; j++) {                                           \
            int row = prow + j * 16;                                            \
            int gn = n0 + row;                                                  \
            uint32_t dst = ab + 16384u + (uint32_t)(row * 128 + ((pcc * 16) ^ ((row & 7) * 16))); \
            int gnc = gn < N ? gn : N - 1;                                      \
            cpasync16z(dst, B + (size_t)gnc * K + (kt) + pcc * 8,               \
                       gn < N ? 16u : 0u);                                      \
        }                                                                       \
        CP_COMMIT();                                                            \
    } while (0)

        WPREFETCH(0, 0);
        WPREFETCH(1, KC);
#pragma unroll 1
        for (int c = 0; c < 8; c++) {          // nch = 512/64 = 8
            if (c + 2 < 8) WPREFETCH((c + 2) % 3, (c + 2) * KC);
            if (c + 2 < 8)      asm volatile("cp.async.wait_group 2;" ::: "memory");
            else if (c + 1 < 8) asm volatile("cp.async.wait_group 1;" ::: "memory");
            else                asm volatile("cp.async.wait_group 0;" ::: "memory");
            __syncthreads();
            const uint32_t As = sb + (c % 3) * STAGE_BYTES;
            const uint32_t Bs = As + 16384;
#pragma unroll
            for (int ks = 0; ks < 4; ks++) {
                uint32_t a[4][4], b[4][4];
#pragma unroll
                for (int mt = 0; mt < 4; mt++)
                    ldsm4(a[mt], As + (uint32_t)((rowA + mt * 16) * 128 + ((ks * 32) ^ kxA)));
#pragma unroll
                for (int j = 0; j < 4; j++)
                    ldsm4(b[j], Bs + (uint32_t)((rowB + j * 16) * 128 + ((ks * 32) ^ kxB)));
#pragma unroll
                for (int mt = 0; mt < 4; mt++)
#pragma unroll
                    for (int nt = 0; nt < 8; nt++)
                        mma16816(acc[mt][nt], a[mt],
                                 b[nt >> 1][(nt & 1) * 2], b[nt >> 1][(nt & 1) * 2 + 1]);
            }
            __syncthreads();
        }
#undef WPREFETCH

        const int mrow  = m0 + wm * 64 + (lane >> 2);
        const int ncol0 = n0 + wn * 64 + (lane & 3) * 2;
#pragma unroll
        for (int mt = 0; mt < 4; mt++) {
#pragma unroll
            for (int nt = 0; nt < 8; nt++) {
                int cc = ncol0 + nt * 8;
                if (cc < N) {
                    float b0v = bias0[cc], b1v = bias0[cc + 1];
                    int r0 = mrow + mt * 16;
                    int or0 = (r0 & 31) * 64 + (r0 >> 5);        // b*64 + t
                    int or1 = ((r0 + 8) & 31) * 64 + ((r0 + 8) >> 5);
                    float2 v0 = make_float2(acc[mt][nt][0] + b0v, acc[mt][nt][1] + b1v);
                    float2 v1 = make_float2(acc[mt][nt][2] + b0v, acc[mt][nt][3] + b1v);
                    *(float2*)(C + (size_t)or0 * N + cc) = v0;
                    *(float2*)(C + (size_t)or1 * N + cc) = v1;
                }
            }
        }
    }
}

// ---------------- persistent LSTM, tensor-core recurrence ----------------------
// (R11 structure; H2 t-major; CTA0 publishes progress to g_step after its wait.)
#define LWS_OFF  0
#define LHS_OFF  32768
#define LPG_OFF  65536
#define LGSM_OFF (65536 + 8192)
#define GK (32 * 33)
#define LCSM_OFF (LGSM_OFF + 4 * GK * 4)
#define LSM_BYTES (LCSM_OFF + 256 * 4)

__device__ __forceinline__ float sigf(float x) { return 1.0f / (1.0f + expf(-x)); }

__global__ __launch_bounds__(256, 1) void lstm_persistent(
    const float* __restrict__ pregates,
    const __half* __restrict__ Whh2,
    __half* __restrict__ hA, __half* __restrict__ hB,
    __half* __restrict__ H2, int* __restrict__ bars, int* __restrict__ stepf)
{
    extern __shared__ char smem[];
    const uint32_t sb = smem_u32(smem);
    float* gsm = (float*)(smem + LGSM_OFF);
    float* csm = (float*)(smem + LCSM_OFF);

    const int tid  = threadIdx.x;
    const int lane = tid & 31, wid = tid >> 5;
    const int u0   = blockIdx.x * 8;

    // PDL: release the dependent output-GEMM launch immediately
    if (tid == 0) cudaTriggerProgrammaticLaunchCompletion();

    const int qb = tid >> 3, qg = (tid >> 1) & 3, qh = tid & 1;
    const size_t qsrc_base = (size_t)qb * TT * G4 + qg * 512 + u0 + qh * 4;
    const uint32_t qdst_off = (uint32_t)(qb * 128 + qg * 32 + qh * 16);

    for (int i = tid; i < 2048; i += 256) {
        int rr = i >> 6, cq = i & 63;
        int g = rr >> 3, ul = rr & 7;
        uint32_t dst = sb + LWS_OFF + (uint32_t)(rr * 1024 + ((cq * 16) ^ ((rr & 7) * 16)));
        cpasync16(dst, Whh2 + (size_t)(g * 512 + u0 + ul) * HID + cq * 8);
    }
    CP_COMMIT();
    cpasync16(sb + LPG_OFF + qdst_off, pregates + qsrc_base);
    CP_COMMIT();
    csm[tid] = 0.0f;

    const int km = wid >> 1, wm = wid & 1;
    const int kbase = km * 256;
    const int rowA = wm * 16 + (lane & 15);
    const int kxA  = (lane >> 4) * 16;
    const int sxA  = (rowA & 7) * 16;
    const int rb   = lane & 7;
    const int kxB  = ((lane >> 3) & 3) * 16;
    const int sxB  = rb * 16;
    const uint32_t wsb = sb + LWS_OFF, hsb = sb + LHS_OFF;

    asm volatile("cp.async.wait_group 0;" ::: "memory");
    __syncthreads();
    uint32_t afr[4][2][4];
#pragma unroll
    for (int ks = 0; ks < 4; ks++) {
        int kb = kbase + ks * 64;
        ldsm4(afr[ks][0], wsb + (uint32_t)(rowA * 1024 + ((kb + kxA) ^ sxA)));
        ldsm4(afr[ks][1], wsb + (uint32_t)(rowA * 1024 + ((kb + 32 + kxA) ^ sxA)));
    }

    const int pb = tid >> 3, pul = tid & 7;
    const int pu = u0 + pul;

    for (int t = 0; t < TT; t++) {
        const __half* hin = (t & 1) ? hB : hA;
        for (int i = tid; i < 2048; i += 256) {
            int b = i >> 6, cq = i & 63;
            uint32_t dst = hsb + (uint32_t)(b * 1024 + ((cq * 16) ^ ((b & 7) * 16)));
            cpasync16(dst, hin + b * HID + cq * 8);
        }
        CP_COMMIT();
        if (t + 1 < TT) {
            cpasync16(sb + LPG_OFF + ((t + 1) & 1) * 4096 + qdst_off,
                      pregates + qsrc_base + (size_t)(t + 1) * G4);
            CP_COMMIT();
            asm volatile("cp.async.wait_group 1;" ::: "memory");
        } else {
            asm volatile("cp.async.wait_group 0;" ::: "memory");
        }
        __syncthreads();

        float cacc[4][4];
#pragma unroll
        for (int j = 0; j < 4; j++)
#pragma unroll
            for (int e = 0; e < 4; e++) cacc[j][e] = 0.f;
#pragma unroll
        for (int ks = 0; ks < 4; ks++) {
            int kb = kbase + ks * 64;
            uint32_t bf[4][4];
#pragma unroll
            for (int j = 0; j < 4; j++)
                ldsm4(bf[j], hsb + (uint32_t)((j * 8 + rb) * 1024 + ((kb + kxB) ^ sxB)));
#pragma unroll
            for (int j = 0; j < 4; j++) {
                mma16816(cacc[j], afr[ks][0], bf[j][0], bf[j][1]);
                mma16816(cacc[j], afr[ks][1], bf[j][2], bf[j][3]);
            }
        }
        {
            float* gk = gsm + km * GK;
            int r0 = wm * 16 + (lane >> 2);
            int cc = (lane & 3) * 2;
#pragma unroll
            for (int j = 0; j < 4; j++) {
                gk[r0 * 33 + cc + j * 8]           = cacc[j][0];
                gk[r0 * 33 + cc + j * 8 + 1]       = cacc[j][1];
                gk[(r0 + 8) * 33 + cc + j * 8]     = cacc[j][2];
                gk[(r0 + 8) * 33 + cc + j * 8 + 1] = cacc[j][3];
            }
        }
        __syncthreads();

        {
            const float* pgs = (const float*)(smem + LPG_OFF + (t & 1) * 4096);
            float gi = pgs[pb * 32 + 0 * 8 + pul];
            float gf = pgs[pb * 32 + 1 * 8 + pul];
            float gg = pgs[pb * 32 + 2 * 8 + pul];
            float go = pgs[pb * 32 + 3 * 8 + pul];
#pragma unroll
            for (int k = 0; k < 4; k++) {
                const float* gk = gsm + k * GK;
                gi += gk[(0  + pul) * 33 + pb];
                gf += gk[(8  + pul) * 33 + pb];
                gg += gk[(16 + pul) * 33 + pb];
                go += gk[(24 + pul) * 33 + pb];
            }
            float c_old = csm[tid];
            float cn = sigf(gf) * c_old + sigf(gi) * tanhf(gg);
            float hn = sigf(go) * tanhf(cn);
            csm[tid] = cn;
            __half hh = __float2half(hn);
            __half* hout = (t & 1) ? hA : hB;
            hout[pb * HID + pu] = hh;
            H2[((size_t)t * 32 + pb) * HID + pu] = hh;   // T-MAJOR
        }

        // arrival; wait (all CTAs for t<63, CTA0 also at t=63); CTA0 publishes
        __syncthreads();
        if (tid == 0) {
            __threadfence();
            atomicAdd(&bars[(blockIdx.x & 7) * 64], 1);
        }
        if (t < TT - 1 || blockIdx.x == 0) {       // block-uniform branch
            if (tid < 8) {
                int target = 8 * (t + 1);
                while (*(volatile int*)&bars[tid * 64] < target) { }
                __threadfence();
            }
            __syncthreads();
            if (blockIdx.x == 0 && tid == 0) st_rel(stepf, t);
        }
    }
}

// ---------------- launch ------------------------------------------------------
extern "C" void kernel_launch(void* const* d_in, const int* in_sizes, int n_in,
                              void* d_out, int out_size)
{
    const float* enc       = (const float*)d_in[0];
    const int*   captions  = (const int*)  d_in[1];
    const float* emb_table = (const float*)d_in[8];
    const float* W_ih      = (const float*)d_in[9];
    const float* W_hh      = (const float*)d_in[10];
    const float* b_ih      = (const float*)d_in[11];
    const float* b_hh      = (const float*)d_in[12];
    const float* W_fc      = (const float*)d_in[13];
    const float* b_fc      = (const float*)d_in[14];
    float* out = (float*)d_out;

    __half *pX2, *pWih2, *pWhh2, *pWfc2, *pH2, *ph2A, *ph2B;
    float *pPG;
    int *pBars, *pTicket, *pStep;
    cudaGetSymbolAddress((void**)&pX2, g_X2);
    cudaGetSymbolAddress((void**)&pWih2, g_Wih2);
    cudaGetSymbolAddress((void**)&pWhh2, g_Whh2);
    cudaGetSymbolAddress((void**)&pWfc2, g_Wfc2);
    cudaGetSymbolAddress((void**)&pH2, g_H2);
    cudaGetSymbolAddress((void**)&ph2A, g_h2A);
    cudaGetSymbolAddress((void**)&ph2B, g_h2B);
    cudaGetSymbolAddress((void**)&pPG, g_pg);
    cudaGetSymbolAddress((void**)&pBars, g_bars);
    cudaGetSymbolAddress((void**)&pTicket, g_ticket);
    cudaGetSymbolAddress((void**)&pStep, g_step);

    cudaFuncSetAttribute(hmma_gemm, cudaFuncAttributeMaxDynamicSharedMemorySize, GSMEM);
    cudaFuncSetAttribute(gemm_worker, cudaFuncAttributeMaxDynamicSharedMemorySize, GSMEM);
    cudaFuncSetAttribute(lstm_persistent, cudaFuncAttributeMaxDynamicSharedMemorySize, LSM_BYTES);

    // 1) fused fp32 -> fp16 weight converts
    {
        int total = N2_WIH + N2_WHH + N2_WFC;
        cvt_all_kernel<<<(total + 255) / 256, 256>>>(W_ih, W_hh, W_fc,
                                                     pWih2, pWhh2, pWfc2);
    }

    // 2) build X2, zero h ping + counters + ticket + step flag
    prep_kernel<<<MROWS + 32, 256>>>(enc, captions, emb_table, pX2, ph2A,
                                     pBars, pTicket, pStep);

    // 3) pregates = X @ W_ih^T + b_ih + b_hh   (K = 768)
    {
        dim3 grid(G4 / 128, MROWS / 128);
        hmma_gemm<<<grid, 128, GSMEM>>>(pX2, pWih2, pPG, b_ih, b_hh,
                                        MROWS, G4, XD);
    }

    // 4) persistent tensor-core LSTM (PDL primary; triggers early)
    lstm_persistent<<<64, 256, LSM_BYTES>>>(pPG, pWhh2, ph2A, ph2B, pH2,
                                            pBars, pStep);

    // 5) output-GEMM workers — PDL secondary (overlaps the LSTM; plain-launch
    //    fallback is still correct: g_step already 63 then).
    {
        cudaLaunchConfig_t cfg = {};
        cfg.gridDim = dim3(296, 1, 1);
        cfg.blockDim = dim3(128, 1, 1);
        cfg.dynamicSmemBytes = GSMEM;
        cfg.stream = 0;
        cudaLaunchAttribute at[1];
        at[0].id = cudaLaunchAttributeProgrammaticStreamSerialization;
        at[0].val.programmaticStreamSerializationAllowed = 1;
        cfg.attrs = at;
        cfg.numAttrs = 1;
        cudaError_t e = cudaLaunchKernelEx(&cfg, gemm_worker,
                                           (const __half*)pH2, (const __half*)pWfc2,
                                           out, b_fc, pStep, pTicket);
        if (e != cudaSuccess) {
            gemm_worker<<<296, 128, GSMEM>>>(pH2, pWfc2, out, b_fc, pStep, pTicket);
        }
    }
}

// round 14
// speedup vs baseline: 1.8681x; 1.0550x over previous
#include <cuda_runtime.h>
#include <cuda_fp16.h>
#include <math.h>
#include <stdint.h>

// Problem dims
#define TT   64
#define VV   30000
#define HID  512
#define XD   768          // EMB + E
#define G4   2048         // 4*H
#define MROWS 2048        // B*T
#define NTILES_N 235      // ceil(30000/128)
#define NTILES_M 16
#define NTILES_TOT (NTILES_M * NTILES_N)

// ---------------- scratch (device globals; no allocation allowed) -------------
__device__ __align__(16) __half g_X2  [MROWS * XD];          // fp16 X (b-major)
__device__ __align__(16) __half g_Wih2[G4 * XD];             // fp16 W_ih
__device__ __align__(16) __half g_Whh2[G4 * HID];            // fp16 W_hh
__device__ __align__(16) __half g_Wfc2[(size_t)VV * HID];    // fp16 W_fc
__device__ __align__(16) __half g_H2  [MROWS * HID];         // fp16 hidden, T-MAJOR (row = t*32+b)
__device__ __align__(16) __half g_h2A [32 * HID];            // h state ping
__device__ __align__(16) __half g_h2B [32 * HID];            // h state pong
__device__ __align__(16) float  g_pg[MROWS * G4];            // pregates fp32 (b-major)
__device__ __align__(16) int    g_bars[512];                 // 8 counters, 256B apart
__device__ int g_ticket;
__device__ int g_step;                                       // published LSTM progress

// ---------------- small helpers ------------------------------------------------
__device__ __forceinline__ uint32_t smem_u32(const void* p) {
    uint32_t a;
    asm("{ .reg .u64 t; cvta.to.shared.u64 t, %1; cvt.u32.u64 %0, t; }" : "=r"(a) : "l"(p));
    return a;
}
__device__ __forceinline__ void ldsm4(uint32_t* r, uint32_t addr) {
    asm volatile("ldmatrix.sync.aligned.m8n8.x4.shared.b16 {%0,%1,%2,%3}, [%4];"
                 : "=r"(r[0]), "=r"(r[1]), "=r"(r[2]), "=r"(r[3]) : "r"(addr));
}
__device__ __forceinline__ void mma16816(float* d, const uint32_t* a,
                                         uint32_t b0, uint32_t b1) {
    asm volatile("mma.sync.aligned.m16n8k16.row.col.f32.f16.f16.f32 "
                 "{%0,%1,%2,%3}, {%4,%5,%6,%7}, {%8,%9}, {%0,%1,%2,%3};"
                 : "+f"(d[0]), "+f"(d[1]), "+f"(d[2]), "+f"(d[3])
                 : "r"(a[0]), "r"(a[1]), "r"(a[2]), "r"(a[3]), "r"(b0), "r"(b1));
}
__device__ __forceinline__ void cpasync16(uint32_t dst, const void* src) {
    asm volatile("cp.async.cg.shared.global [%0], [%1], 16;" :: "r"(dst), "l"(src));
}
__device__ __forceinline__ void cpasync16z(uint32_t dst, const void* src, unsigned sz) {
    asm volatile("cp.async.cg.shared.global [%0], [%1], 16, %2;"
                 :: "r"(dst), "l"(src), "r"(sz));
}
#define CP_COMMIT() asm volatile("cp.async.commit_group;" ::: "memory")
__device__ __forceinline__ int ld_acq(const int* p) {
    int v;
    asm volatile("ld.acquire.gpu.global.b32 %0, [%1];" : "=r"(v) : "l"(p) : "memory");
    return v;
}
__device__ __forceinline__ void st_rel(int* p, int v) {
    asm volatile("st.release.gpu.global.b32 [%0], %1;" :: "l"(p), "r"(v) : "memory");
}

#define N2_WIH (G4 * XD / 2)
#define N2_WHH (G4 * HID / 2)
#define N2_WFC (VV * HID / 2)
#define NBLK_WSMALL ((N2_WIH + N2_WHH + 255) / 256)

// ---------------- prep: X2, h ping zero, flags, + cvt(Wih,Whh) -----------------
__global__ void prep_kernel(const float* __restrict__ enc,
                            const int*   __restrict__ captions,
                            const float* __restrict__ emb_table,
                            const float* __restrict__ Wih,
                            const float* __restrict__ Whh,
                            __half* __restrict__ X2,
                            __half* __restrict__ dWih,
                            __half* __restrict__ dWhh,
                            __half* __restrict__ h0, int* __restrict__ bars,
                            int* __restrict__ ticket, int* __restrict__ stepf)
{
    int blk = blockIdx.x;
    if (blk < MROWS) {
        int b = blk >> 6;
        int cap = captions[blk];
        const float* erow = emb_table + (size_t)cap * 512;
        const float* crow = enc + (size_t)b * 256;
        size_t base = (size_t)blk * XD;
        for (int c = threadIdx.x; c < XD; c += 256) {
            float x = (c < 512) ? erow[c] : crow[c - 512];
            X2[base + c] = __float2half(x);
        }
    } else if (blk < MROWS + 32) {
        int i = (blk - MROWS) * 256 + threadIdx.x;   // 0..8191
        ((uint32_t*)h0)[i] = 0u;
        if (i < 512) bars[i] = 0;
        if (i == 0) { *ticket = 0; *stepf = -1; }
    } else {
        int i = (blk - MROWS - 32) * 256 + threadIdx.x;
        const float* src;
        __half* dst;
        if (i < N2_WIH) { src = Wih; dst = dWih; }
        else            { src = Whh; dst = dWhh; i -= N2_WIH;
                          if (i >= N2_WHH) return; }
        float2 v = ((const float2*)src)[i];
        ((__half2*)dst)[i] = __floats2half2_rn(v.x, v.y);
    }
}

// ---------------- W_fc convert (PDL secondary: overlaps the LSTM) --------------
__global__ void cvt_wfc_kernel(const float* __restrict__ Wfc,
                               __half* __restrict__ dWfc)
{
    int i = blockIdx.x * 256 + threadIdx.x;
    if (i >= N2_WFC) return;
    float2 v = ((const float2*)Wfc)[i];
    ((__half2*)dWfc)[i] = __floats2half2_rn(v.x, v.y);
}

// ---------------- GEMM mainloop shared geometry --------------------------------
#define KC 64
#define STAGE_BYTES 32768      // A 16KB + B 16KB
#define GSMEM (3 * STAGE_BYTES)

// ---------------- HMMA GEMM (pregates): C = A B^T + bias0 + bias1 -------------
__global__ __launch_bounds__(128, 2) void hmma_gemm(
    const __half* __restrict__ A, const __half* __restrict__ B,
    float* __restrict__ C,
    const float* __restrict__ bias0, const float* __restrict__ bias1,
    int M, int N, int K)
{
    extern __shared__ char smem[];
    const uint32_t sb = smem_u32(smem);
    const int tid  = threadIdx.x;
    const int lane = tid & 31, wid = tid >> 5;
    const int m0 = blockIdx.y * 128, n0 = blockIdx.x * 128;
    const int wm = wid & 1, wn = wid >> 1;
    const int nch = K / KC;

    const int rowA = wm * 64 + (lane & 7) + ((lane >> 3) & 1) * 8;
    const int kxA  = ((lane >> 4) * 16) ^ ((rowA & 7) * 16);
    const int rowB = wn * 64 + (lane & 7) + ((lane >= 16) ? 8 : 0);
    const int kxB  = (((lane >> 3) & 1) * 16) ^ ((rowB & 7) * 16);

    float acc[4][8][4];
#pragma unroll
    for (int i = 0; i < 4; i++)
#pragma unroll
        for (int j = 0; j < 8; j++)
#pragma unroll
            for (int e = 0; e < 4; e++) acc[i][j][e] = 0.f;

    const int prow = tid >> 3;
    const int pcc  = tid & 7;
#define PREFETCH(stage, kt)                                                     \
    do {                                                                        \
        uint32_t ab = sb + (stage) * STAGE_BYTES;                               \
        _Pragma("unroll")                                                       \
        for (int j = 0; j < 8; j++) {                                           \
            int row = prow + j * 16;                                            \
            uint32_t dst = ab + (uint32_t)(row * 128 + ((pcc * 16) ^ ((row & 7) * 16))); \
            cpasync16(dst, A + (size_t)(m0 + row) * K + (kt) + pcc * 8);        \
        }                                                                       \
        _Pragma("unroll")                                                       \
        for (int j = 0; j < 8; j++) {                                           \
            int row = prow + j * 16;                                            \
            int gn = n0 + row;                                                  \
            uint32_t dst = ab + 16384u + (uint32_t)(row * 128 + ((pcc * 16) ^ ((row & 7) * 16))); \
            int gnc = gn < N ? gn : N - 1;                                      \
            cpasync16z(dst, B + (size_t)gnc * K + (kt) + pcc * 8,               \
                       gn < N ? 16u : 0u);                                      \
        }                                                                       \
        CP_COMMIT();                                                            \
    } while (0)

    PREFETCH(0, 0);
    PREFETCH(1, KC);
    for (int c = 0; c < nch; c++) {
        if (c + 2 < nch) PREFETCH((c + 2) % 3, (c + 2) * KC);
        if (c + 2 < nch)      asm volatile("cp.async.wait_group 2;" ::: "memory");
        else if (c + 1 < nch) asm volatile("cp.async.wait_group 1;" ::: "memory");
        else                  asm volatile("cp.async.wait_group 0;" ::: "memory");
        __syncthreads();
        const uint32_t As = sb + (c % 3) * STAGE_BYTES;
        const uint32_t Bs = As + 16384;
#pragma unroll
        for (int ks = 0; ks < 4; ks++) {
            uint32_t a[4][4], b[4][4];
#pragma unroll
            for (int mt = 0; mt < 4; mt++)
                ldsm4(a[mt], As + (uint32_t)((rowA + mt * 16) * 128 + ((ks * 32) ^ kxA)));
#pragma unroll
            for (int j = 0; j < 4; j++)
                ldsm4(b[j], Bs + (uint32_t)((rowB + j * 16) * 128 + ((ks * 32) ^ kxB)));
#pragma unroll
            for (int mt = 0; mt < 4; mt++)
#pragma unroll
                for (int nt = 0; nt < 8; nt++)
                    mma16816(acc[mt][nt], a[mt],
                             b[nt >> 1][(nt & 1) * 2], b[nt >> 1][(nt & 1) * 2 + 1]);
        }
        __syncthreads();
    }

    const int mrow  = m0 + wm * 64 + (lane >> 2);
    const int ncol0 = n0 + wn * 64 + (lane & 3) * 2;
#pragma unroll
    for (int mt = 0; mt < 4; mt++) {
#pragma unroll
        for (int nt = 0; nt < 8; nt++) {
            int cc = ncol0 + nt * 8;
            if (cc < N) {
                float b0v = bias0[cc], b1v = bias0[cc + 1];
                if (bias1) { b0v += bias1[cc]; b1v += bias1[cc + 1]; }
                int r0 = mrow + mt * 16;
                float2 v0 = make_float2(acc[mt][nt][0] + b0v, acc[mt][nt][1] + b1v);
                float2 v1 = make_float2(acc[mt][nt][2] + b0v, acc[mt][nt][3] + b1v);
                *(float2*)(C + (size_t)r0 * N + cc)       = v0;
                *(float2*)(C + (size_t)(r0 + 8) * N + cc) = v1;
            }
        }
    }
#undef PREFETCH
}

// ---------------- output-GEMM worker (PDL tertiary) ----------------------------
__global__ __launch_bounds__(128, 2) void gemm_worker(
    const __half* __restrict__ A, const __half* __restrict__ B,
    float* __restrict__ C, const float* __restrict__ bias0,
    int* __restrict__ stepf, int* __restrict__ ticket)
{
    extern __shared__ char smem[];
    __shared__ int tix;
    const uint32_t sb = smem_u32(smem);
    const int tid  = threadIdx.x;
    const int lane = tid & 31, wid = tid >> 5;
    const int wm = wid & 1, wn = wid >> 1;
    const int K = HID, N = VV;

    const int rowA = wm * 64 + (lane & 7) + ((lane >> 3) & 1) * 8;
    const int kxA  = ((lane >> 4) * 16) ^ ((rowA & 7) * 16);
    const int rowB = wn * 64 + (lane & 7) + ((lane >= 16) ? 8 : 0);
    const int kxB  = (((lane >> 3) & 1) * 16) ^ ((rowB & 7) * 16);
    const int prow = tid >> 3;
    const int pcc  = tid & 7;

    for (;;) {
        if (tid == 0) tix = atomicAdd(ticket, 1);
        __syncthreads();
        int tk = tix;
        __syncthreads();
        if (tk >= NTILES_TOT) return;
        const int m  = tk / NTILES_N;
        const int m0 = m * 128;
        const int n0 = (tk - m * NTILES_N) * 128;

        if (tid == 0) {
            const int target = 4 * m + 3;
            while (ld_acq(stepf) < target) __nanosleep(128);
        }
        __syncthreads();

        float acc[4][8][4];
#pragma unroll
        for (int i = 0; i < 4; i++)
#pragma unroll
            for (int j = 0; j < 8; j++)
#pragma unroll
                for (int e = 0; e < 4; e++) acc[i][j][e] = 0.f;

#define WPREFETCH(stage, kt)                                                    \
    do {                                                                        \
        uint32_t ab = sb + (stage) * STAGE_BYTES;                               \
        _Pragma("unroll")                                                       \
        for (int j = 0; j < 8; j++) {                                           \
            int row = prow + j * 16;                                            \
            uint32_t dst = ab + (uint32_t)(row * 128 + ((pcc * 16) ^ ((row & 7) * 16))); \
            cpasync16(dst, A + (size_t)(m0 + row) * K + (kt) + pcc * 8);        \
        }                                                                       \
        _Pragma("unroll")                                                       \
        for (int j = 0; j < 8; j++) {                                           \
            int row = prow + j * 16;                                            \
            int gn = n0 + row;                                                  \
            uint32_t dst = ab + 16384u + (uint32_t)(row * 128 + ((pcc * 16) ^ ((row & 7) * 16))); \
            int gnc = gn < N ? gn : N - 1;                                      \
            cpasync16z(dst, B + (size_t)gnc * K + (kt) + pcc * 8,               \
                       gn < N ? 16u : 0u);                                      \
        }                                                                       \
        CP_COMMIT();                                                            \
    } while (0)

        WPREFETCH(0, 0);
        WPREFETCH(1, KC);
#pragma unroll 1
        for (int c = 0; c < 8; c++) {
            if (c + 2 < 8) WPREFETCH((c + 2) % 3, (c + 2) * KC);
            if (c + 2 < 8)      asm volatile("cp.async.wait_group 2;" ::: "memory");
            else if (c + 1 < 8) asm volatile("cp.async.wait_group 1;" ::: "memory");
            else                asm volatile("cp.async.wait_group 0;" ::: "memory");
            __syncthreads();
            const uint32_t As = sb + (c % 3) * STAGE_BYTES;
            const uint32_t Bs = As + 16384;
#pragma unroll
            for (int ks = 0; ks < 4; ks++) {
                uint32_t a[4][4], b[4][4];
#pragma unroll
                for (int mt = 0; mt < 4; mt++)
                    ldsm4(a[mt], As + (uint32_t)((rowA + mt * 16) * 128 + ((ks * 32) ^ kxA)));
#pragma unroll
                for (int j = 0; j < 4; j++)
                    ldsm4(b[j], Bs + (uint32_t)((rowB + j * 16) * 128 + ((ks * 32) ^ kxB)));
#pragma unroll
                for (int mt = 0; mt < 4; mt++)
#pragma unroll
                    for (int nt = 0; nt < 8; nt++)
                        mma16816(acc[mt][nt], a[mt],
                                 b[nt >> 1][(nt & 1) * 2], b[nt >> 1][(nt & 1) * 2 + 1]);
            }
            __syncthreads();
        }
#undef WPREFETCH

        const int mrow  = m0 + wm * 64 + (lane >> 2);
        const int ncol0 = n0 + wn * 64 + (lane & 3) * 2;
#pragma unroll
        for (int mt = 0; mt < 4; mt++) {
#pragma unroll
            for (int nt = 0; nt < 8; nt++) {
                int cc = ncol0 + nt * 8;
                if (cc < N) {
                    float b0v = bias0[cc], b1v = bias0[cc + 1];
                    int r0 = mrow + mt * 16;
                    int or0 = (r0 & 31) * 64 + (r0 >> 5);        // b*64 + t
                    int or1 = ((r0 + 8) & 31) * 64 + ((r0 + 8) >> 5);
                    float2 v0 = make_float2(acc[mt][nt][0] + b0v, acc[mt][nt][1] + b1v);
                    float2 v1 = make_float2(acc[mt][nt][2] + b0v, acc[mt][nt][3] + b1v);
                    *(float2*)(C + (size_t)or0 * N + cc) = v0;
                    *(float2*)(C + (size_t)or1 * N + cc) = v1;
                }
            }
        }
    }
}

// ---------------- persistent LSTM, tensor-core recurrence ----------------------
#define LWS_OFF  0
#define LHS_OFF  32768
#define LPG_OFF  65536
#define LGSM_OFF (65536 + 8192)
#define GK (32 * 33)
#define LCSM_OFF (LGSM_OFF + 4 * GK * 4)
#define LSM_BYTES (LCSM_OFF + 256 * 4)

__device__ __forceinline__ float sigf(float x) { return 1.0f / (1.0f + expf(-x)); }

__global__ __launch_bounds__(256, 1) void lstm_persistent(
    const float* __restrict__ pregates,
    const __half* __restrict__ Whh2,
    __half* __restrict__ hA, __half* __restrict__ hB,
    __half* __restrict__ H2, int* __restrict__ bars, int* __restrict__ stepf)
{
    extern __shared__ char smem[];
    const uint32_t sb = smem_u32(smem);
    float* gsm = (float*)(smem + LGSM_OFF);
    float* csm = (float*)(smem + LCSM_OFF);

    const int tid  = threadIdx.x;
    const int lane = tid & 31, wid = tid >> 5;
    const int u0   = blockIdx.x * 8;

    // PDL: release the dependent cvt_wfc (and transitively workers)
    if (tid == 0) cudaTriggerProgrammaticLaunchCompletion();

    const int qb = tid >> 3, qg = (tid >> 1) & 3, qh = tid & 1;
    const size_t qsrc_base = (size_t)qb * TT * G4 + qg * 512 + u0 + qh * 4;
    const uint32_t qdst_off = (uint32_t)(qb * 128 + qg * 32 + qh * 16);

    for (int i = tid; i < 2048; i += 256) {
        int rr = i >> 6, cq = i & 63;
        int g = rr >> 3, ul = rr & 7;
        uint32_t dst = sb + LWS_OFF + (uint32_t)(rr * 1024 + ((cq * 16) ^ ((rr & 7) * 16)));
        cpasync16(dst, Whh2 + (size_t)(g * 512 + u0 + ul) * HID + cq * 8);
    }
    CP_COMMIT();
    cpasync16(sb + LPG_OFF + qdst_off, pregates + qsrc_base);
    CP_COMMIT();
    csm[tid] = 0.0f;

    const int km = wid >> 1, wm = wid & 1;
    const int kbase = km * 256;
    const int rowA = wm * 16 + (lane & 15);
    const int kxA  = (lane >> 4) * 16;
    const int sxA  = (rowA & 7) * 16;
    const int rb   = lane & 7;
    const int kxB  = ((lane >> 3) & 3) * 16;
    const int sxB  = rb * 16;
    const uint32_t wsb = sb + LWS_OFF, hsb = sb + LHS_OFF;

    asm volatile("cp.async.wait_group 0;" ::: "memory");
    __syncthreads();
    uint32_t afr[4][2][4];
#pragma unroll
    for (int ks = 0; ks < 4; ks++) {
        int kb = kbase + ks * 64;
        ldsm4(afr[ks][0], wsb + (uint32_t)(rowA * 1024 + ((kb + kxA) ^ sxA)));
        ldsm4(afr[ks][1], wsb + (uint32_t)(rowA * 1024 + ((kb + 32 + kxA) ^ sxA)));
    }

    const int pb = tid >> 3, pul = tid & 7;
    const int pu = u0 + pul;

    for (int t = 0; t < TT; t++) {
        const __half* hin = (t & 1) ? hB : hA;
        for (int i = tid; i < 2048; i += 256) {
            int b = i >> 6, cq = i & 63;
            uint32_t dst = hsb + (uint32_t)(b * 1024 + ((cq * 16) ^ ((b & 7) * 16)));
            cpasync16(dst, hin + b * HID + cq * 8);
        }
        CP_COMMIT();
        if (t + 1 < TT) {
            cpasync16(sb + LPG_OFF + ((t + 1) & 1) * 4096 + qdst_off,
                      pregates + qsrc_base + (size_t)(t + 1) * G4);
            CP_COMMIT();
            asm volatile("cp.async.wait_group 1;" ::: "memory");
        } else {
            asm volatile("cp.async.wait_group 0;" ::: "memory");
        }
        __syncthreads();

        float cacc[4][4];
#pragma unroll
        for (int j = 0; j < 4; j++)
#pragma unroll
            for (int e = 0; e < 4; e++) cacc[j][e] = 0.f;
#pragma unroll
        for (int ks = 0; ks < 4; ks++) {
            int kb = kbase + ks * 64;
            uint32_t bf[4][4];
#pragma unroll
            for (int j = 0; j < 4; j++)
                ldsm4(bf[j], hsb + (uint32_t)((j * 8 + rb) * 1024 + ((kb + kxB) ^ sxB)));
#pragma unroll
            for (int j = 0; j < 4; j++) {
                mma16816(cacc[j], afr[ks][0], bf[j][0], bf[j][1]);
                mma16816(cacc[j], afr[ks][1], bf[j][2], bf[j][3]);
            }
        }
        {
            float* gk = gsm + km * GK;
            int r0 = wm * 16 + (lane >> 2);
            int cc = (lane & 3) * 2;
#pragma unroll
            for (int j = 0; j < 4; j++) {
                gk[r0 * 33 + cc + j * 8]           = cacc[j][0];
                gk[r0 * 33 + cc + j * 8 + 1]       = cacc[j][1];
                gk[(r0 + 8) * 33 + cc + j * 8]     = cacc[j][2];
                gk[(r0 + 8) * 33 + cc + j * 8 + 1] = cacc[j][3];
            }
        }
        __syncthreads();

        {
            const float* pgs = (const float*)(smem + LPG_OFF + (t & 1) * 4096);
            float gi = pgs[pb * 32 + 0 * 8 + pul];
            float gf = pgs[pb * 32 + 1 * 8 + pul];
            float gg = pgs[pb * 32 + 2 * 8 + pul];
            float go = pgs[pb * 32 + 3 * 8 + pul];
#pragma unroll
            for (int k = 0; k < 4; k++) {
                const float* gk = gsm + k * GK;
                gi += gk[(0  + pul) * 33 + pb];
                gf += gk[(8  + pul) * 33 + pb];
                gg += gk[(16 + pul) * 33 + pb];
                go += gk[(24 + pul) * 33 + pb];
            }
            float c_old = csm[tid];
            float cn = sigf(gf) * c_old + sigf(gi) * tanhf(gg);
            float hn = sigf(go) * tanhf(cn);
            csm[tid] = cn;
            __half hh = __float2half(hn);
            __half* hout = (t & 1) ? hA : hB;
            hout[pb * HID + pu] = hh;
            H2[((size_t)t * 32 + pb) * HID + pu] = hh;   // T-MAJOR
        }

        __syncthreads();
        if (tid == 0) {
            __threadfence();
            atomicAdd(&bars[(blockIdx.x & 7) * 64], 1);
        }
        if (t < TT - 1 || blockIdx.x == 0) {       // block-uniform branch
            if (tid < 8) {
                int target = 8 * (t + 1);
                while (*(volatile int*)&bars[tid * 64] < target) { }
                __threadfence();
            }
            __syncthreads();
            if (blockIdx.x == 0 && tid == 0) st_rel(stepf, t);
        }
    }
}

// ---------------- launch ------------------------------------------------------
extern "C" void kernel_launch(void* const* d_in, const int* in_sizes, int n_in,
                              void* d_out, int out_size)
{
    const float* enc       = (const float*)d_in[0];
    const int*   captions  = (const int*)  d_in[1];
    const float* emb_table = (const float*)d_in[8];
    const float* W_ih      = (const float*)d_in[9];
    const float* W_hh      = (const float*)d_in[10];
    const float* b_ih      = (const float*)d_in[11];
    const float* b_hh      = (const float*)d_in[12];
    const float* W_fc      = (const float*)d_in[13];
    const float* b_fc      = (const float*)d_in[14];
    float* out = (float*)d_out;

    __half *pX2, *pWih2, *pWhh2, *pWfc2, *pH2, *ph2A, *ph2B;
    float *pPG;
    int *pBars, *pTicket, *pStep;
    cudaGetSymbolAddress((void**)&pX2, g_X2);
    cudaGetSymbolAddress((void**)&pWih2, g_Wih2);
    cudaGetSymbolAddress((void**)&pWhh2, g_Whh2);
    cudaGetSymbolAddress((void**)&pWfc2, g_Wfc2);
    cudaGetSymbolAddress((void**)&pH2, g_H2);
    cudaGetSymbolAddress((void**)&ph2A, g_h2A);
    cudaGetSymbolAddress((void**)&ph2B, g_h2B);
    cudaGetSymbolAddress((void**)&pPG, g_pg);
    cudaGetSymbolAddress((void**)&pBars, g_bars);
    cudaGetSymbolAddress((void**)&pTicket, g_ticket);
    cudaGetSymbolAddress((void**)&pStep, g_step);

    cudaFuncSetAttribute(hmma_gemm, cudaFuncAttributeMaxDynamicSharedMemorySize, GSMEM);
    cudaFuncSetAttribute(gemm_worker, cudaFuncAttributeMaxDynamicSharedMemorySize, GSMEM);
    cudaFuncSetAttribute(lstm_persistent, cudaFuncAttributeMaxDynamicSharedMemorySize, LSM_BYTES);

    // 1) prep: X2, h0+flags, cvt(Wih,Whh)
    prep_kernel<<<MROWS + 32 + NBLK_WSMALL, 256>>>(enc, captions, emb_table,
                                                   W_ih, W_hh, pX2, pWih2, pWhh2,
                                                   ph2A, pBars, pTicket, pStep);

    // 2) pregates = X @ W_ih^T + b_ih + b_hh   (K = 768)
    {
        dim3 grid(G4 / 128, MROWS / 128);
        hmma_gemm<<<grid, 128, GSMEM>>>(pX2, pWih2, pPG, b_ih, b_hh,
                                        MROWS, G4, XD);
    }

    // 3) persistent tensor-core LSTM (PDL primary; triggers at top)
    lstm_persistent<<<64, 256, LSM_BYTES>>>(pPG, pWhh2, ph2A, ph2B, pH2,
                                            pBars, pStep);

    // 4) W_fc convert — PDL secondary: starts when the LSTM triggers, runs on
    //    idle SMs during the LSTM. Implicit trigger at ITS completion releases
    //    the workers (which need the converted W_fc).
    {
        cudaLaunchConfig_t cfg = {};
        cfg.gridDim = dim3((N2_WFC + 255) / 256, 1, 1);
        cfg.blockDim = dim3(256, 1, 1);
        cfg.stream = 0;
        cudaLaunchAttribute at[1];
        at[0].id = cudaLaunchAttributeProgrammaticStreamSerialization;
        at[0].val.programmaticStreamSerializationAllowed = 1;
        cfg.attrs = at;
        cfg.numAttrs = 1;
        cudaError_t e = cudaLaunchKernelEx(&cfg, cvt_wfc_kernel, W_fc, pWfc2);
        if (e != cudaSuccess)
            cvt_wfc_kernel<<<(N2_WFC + 255) / 256, 256>>>(W_fc, pWfc2);
    }

    // 5) output-GEMM workers — PDL tertiary (released at cvt_wfc completion;
    //    overlaps the remainder of the LSTM).
    {
        cudaLaunchConfig_t cfg = {};
        cfg.gridDim = dim3(296, 1, 1);
        cfg.blockDim = dim3(128, 1, 1);
        cfg.dynamicSmemBytes = GSMEM;
        cfg.stream = 0;
        cudaLaunchAttribute at[1];
        at[0].id = cudaLaunchAttributeProgrammaticStreamSerialization;
        at[0].val.programmaticStreamSerializationAllowed = 1;
        cfg.attrs = at;
        cfg.numAttrs = 1;
        cudaError_t e = cudaLaunchKernelEx(&cfg, gemm_worker,
                                           (const __half*)pH2, (const __half*)pWfc2,
                                           out, b_fc, pStep, pTicket);
        if (e != cudaSuccess) {
            gemm_worker<<<296, 128, GSMEM>>>(pH2, pWfc2, out, b_fc, pStep, pTicket);
        }
    }
}

// round 15
// speedup vs baseline: 1.9476x; 1.0426x over previous
#include <cuda_runtime.h>
#include <cuda_fp16.h>
#include <math.h>
#include <stdint.h>

// Problem dims
#define TT   64
#define VV   30000
#define HID  512
#define XD   768          // EMB + E
#define G4   2048         // 4*H
#define MROWS 2048        // B*T
#define NTILES_N 235      // ceil(30000/128)
#define NTILES_M 16
#define NTILES_TOT (NTILES_M * NTILES_N)

// ---------------- scratch (device globals; no allocation allowed) -------------
__device__ __align__(16) __half g_X2  [MROWS * XD];          // fp16 X (b-major)
__device__ __align__(16) __half g_Wih2[G4 * XD];             // fp16 W_ih
__device__ __align__(16) __half g_Whh2[G4 * HID];            // fp16 W_hh
__device__ __align__(16) __half g_Wfc2[(size_t)VV * HID];    // fp16 W_fc
__device__ __align__(16) __half g_H2  [MROWS * HID];         // fp16 hidden, T-MAJOR (row = t*32+b)
__device__ __align__(16) __half g_h2A [32 * HID];            // h state ping
__device__ __align__(16) __half g_h2B [32 * HID];            // h state pong
__device__ __align__(16) float  g_pg[MROWS * G4];            // pregates fp32 (b-major)
__device__ __align__(16) int    g_bars[512];                 // 4 counters, 256B apart
__device__ int g_ticket;
__device__ int g_step;                                       // published LSTM progress

// ---------------- small helpers ------------------------------------------------
__device__ __forceinline__ uint32_t smem_u32(const void* p) {
    uint32_t a;
    asm("{ .reg .u64 t; cvta.to.shared.u64 t, %1; cvt.u32.u64 %0, t; }" : "=r"(a) : "l"(p));
    return a;
}
__device__ __forceinline__ void ldsm4(uint32_t* r, uint32_t addr) {
    asm volatile("ldmatrix.sync.aligned.m8n8.x4.shared.b16 {%0,%1,%2,%3}, [%4];"
                 : "=r"(r[0]), "=r"(r[1]), "=r"(r[2]), "=r"(r[3]) : "r"(addr));
}
__device__ __forceinline__ void mma16816(float* d, const uint32_t* a,
                                         uint32_t b0, uint32_t b1) {
    asm volatile("mma.sync.aligned.m16n8k16.row.col.f32.f16.f16.f32 "
                 "{%0,%1,%2,%3}, {%4,%5,%6,%7}, {%8,%9}, {%0,%1,%2,%3};"
                 : "+f"(d[0]), "+f"(d[1]), "+f"(d[2]), "+f"(d[3])
                 : "r"(a[0]), "r"(a[1]), "r"(a[2]), "r"(a[3]), "r"(b0), "r"(b1));
}
__device__ __forceinline__ void cpasync16(uint32_t dst, const void* src) {
    asm volatile("cp.async.cg.shared.global [%0], [%1], 16;" :: "r"(dst), "l"(src));
}
__device__ __forceinline__ void cpasync16z(uint32_t dst, const void* src, unsigned sz) {
    asm volatile("cp.async.cg.shared.global [%0], [%1], 16, %2;"
                 :: "r"(dst), "l"(src), "r"(sz));
}
#define CP_COMMIT() asm volatile("cp.async.commit_group;" ::: "memory")
__device__ __forceinline__ int ld_acq(const int* p) {
    int v;
    asm volatile("ld.acquire.gpu.global.b32 %0, [%1];" : "=r"(v) : "l"(p) : "memory");
    return v;
}
__device__ __forceinline__ void st_rel(int* p, int v) {
    asm volatile("st.release.gpu.global.b32 [%0], %1;" :: "l"(p), "r"(v) : "memory");
}

#define N2_WIH (G4 * XD / 2)
#define N2_WHH (G4 * HID / 2)
#define N2_WFC (VV * HID / 2)
#define NBLK_WSMALL ((N2_WIH + N2_WHH + 255) / 256)

// ---------------- prep: X2, h ping zero, flags, + cvt(Wih,Whh) -----------------
__global__ void prep_kernel(const float* __restrict__ enc,
                            const int*   __restrict__ captions,
                            const float* __restrict__ emb_table,
                            const float* __restrict__ Wih,
                            const float* __restrict__ Whh,
                            __half* __restrict__ X2,
                            __half* __restrict__ dWih,
                            __half* __restrict__ dWhh,
                            __half* __restrict__ h0, int* __restrict__ bars,
                            int* __restrict__ ticket, int* __restrict__ stepf)
{
    int blk = blockIdx.x;
    if (blk < MROWS) {
        int b = blk >> 6;
        int cap = captions[blk];
        const float* erow = emb_table + (size_t)cap * 512;
        const float* crow = enc + (size_t)b * 256;
        size_t base = (size_t)blk * XD;
        for (int c = threadIdx.x; c < XD; c += 256) {
            float x = (c < 512) ? erow[c] : crow[c - 512];
            X2[base + c] = __float2half(x);
        }
    } else if (blk < MROWS + 32) {
        int i = (blk - MROWS) * 256 + threadIdx.x;   // 0..8191
        ((uint32_t*)h0)[i] = 0u;
        if (i < 512) bars[i] = 0;
        if (i == 0) { *ticket = 0; *stepf = -1; }
    } else {
        int i = (blk - MROWS - 32) * 256 + threadIdx.x;
        const float* src;
        __half* dst;
        if (i < N2_WIH) { src = Wih; dst = dWih; }
        else            { src = Whh; dst = dWhh; i -= N2_WIH;
                          if (i >= N2_WHH) return; }
        float2 v = ((const float2*)src)[i];
        ((__half2*)dst)[i] = __floats2half2_rn(v.x, v.y);
    }
}

// ---------------- W_fc convert (PDL secondary: overlaps the LSTM) --------------
__global__ void cvt_wfc_kernel(const float* __restrict__ Wfc,
                               __half* __restrict__ dWfc)
{
    int i = blockIdx.x * 256 + threadIdx.x;
    if (i >= N2_WFC) return;
    float2 v = ((const float2*)Wfc)[i];
    ((__half2*)dWfc)[i] = __floats2half2_rn(v.x, v.y);
}

// ---------------- GEMM mainloop shared geometry --------------------------------
#define KC 64
#define STAGE_BYTES 32768      // A 16KB + B 16KB
#define GSMEM (3 * STAGE_BYTES)

// ---------------- HMMA GEMM (pregates): C = A B^T + bias0 + bias1 -------------
__global__ __launch_bounds__(128, 2) void hmma_gemm(
    const __half* __restrict__ A, const __half* __restrict__ B,
    float* __restrict__ C,
    const float* __restrict__ bias0, const float* __restrict__ bias1,
    int M, int N, int K)
{
    extern __shared__ char smem[];
    const uint32_t sb = smem_u32(smem);
    const int tid  = threadIdx.x;
    const int lane = tid & 31, wid = tid >> 5;
    const int m0 = blockIdx.y * 128, n0 = blockIdx.x * 128;
    const int wm = wid & 1, wn = wid >> 1;
    const int nch = K / KC;

    const int rowA = wm * 64 + (lane & 7) + ((lane >> 3) & 1) * 8;
    const int kxA  = ((lane >> 4) * 16) ^ ((rowA & 7) * 16);
    const int rowB = wn * 64 + (lane & 7) + ((lane >= 16) ? 8 : 0);
    const int kxB  = (((lane >> 3) & 1) * 16) ^ ((rowB & 7) * 16);

    float acc[4][8][4];
#pragma unroll
    for (int i = 0; i < 4; i++)
#pragma unroll
        for (int j = 0; j < 8; j++)
#pragma unroll
            for (int e = 0; e < 4; e++) acc[i][j][e] = 0.f;

    const int prow = tid >> 3;
    const int pcc  = tid & 7;
#define PREFETCH(stage, kt)                                                     \
    do {                                                                        \
        uint32_t ab = sb + (stage) * STAGE_BYTES;                               \
        _Pragma("unroll")                                                       \
        for (int j = 0; j < 8; j++) {                                           \
            int row = prow + j * 16;                                            \
            uint32_t dst = ab + (uint32_t)(row * 128 + ((pcc * 16) ^ ((row & 7) * 16))); \
            cpasync16(dst, A + (size_t)(m0 + row) * K + (kt) + pcc * 8);        \
        }                                                                       \
        _Pragma("unroll")                                                       \
        for (int j = 0; j < 8; j++) {                                           \
            int row = prow + j * 16;                                            \
            int gn = n0 + row;                                                  \
            uint32_t dst = ab + 16384u + (uint32_t)(row * 128 + ((pcc * 16) ^ ((row & 7) * 16))); \
            int gnc = gn < N ? gn : N - 1;                                      \
            cpasync16z(dst, B + (size_t)gnc * K + (kt) + pcc * 8,               \
                       gn < N ? 16u : 0u);                                      \
        }                                                                       \
        CP_COMMIT();                                                            \
    } while (0)

    PREFETCH(0, 0);
    PREFETCH(1, KC);
    for (int c = 0; c < nch; c++) {
        if (c + 2 < nch) PREFETCH((c + 2) % 3, (c + 2) * KC);
        if (c + 2 < nch)      asm volatile("cp.async.wait_group 2;" ::: "memory");
        else if (c + 1 < nch) asm volatile("cp.async.wait_group 1;" ::: "memory");
        else                  asm volatile("cp.async.wait_group 0;" ::: "memory");
        __syncthreads();
        const uint32_t As = sb + (c % 3) * STAGE_BYTES;
        const uint32_t Bs = As + 16384;
#pragma unroll
        for (int ks = 0; ks < 4; ks++) {
            uint32_t a[4][4], b[4][4];
#pragma unroll
            for (int mt = 0; mt < 4; mt++)
                ldsm4(a[mt], As + (uint32_t)((rowA + mt * 16) * 128 + ((ks * 32) ^ kxA)));
#pragma unroll
            for (int j = 0; j < 4; j++)
                ldsm4(b[j], Bs + (uint32_t)((rowB + j * 16) * 128 + ((ks * 32) ^ kxB)));
#pragma unroll
            for (int mt = 0; mt < 4; mt++)
#pragma unroll
                for (int nt = 0; nt < 8; nt++)
                    mma16816(acc[mt][nt], a[mt],
                             b[nt >> 1][(nt & 1) * 2], b[nt >> 1][(nt & 1) * 2 + 1]);
        }
        __syncthreads();
    }

    const int mrow  = m0 + wm * 64 + (lane >> 2);
    const int ncol0 = n0 + wn * 64 + (lane & 3) * 2;
#pragma unroll
    for (int mt = 0; mt < 4; mt++) {
#pragma unroll
        for (int nt = 0; nt < 8; nt++) {
            int cc = ncol0 + nt * 8;
            if (cc < N) {
                float b0v = bias0[cc], b1v = bias0[cc + 1];
                if (bias1) { b0v += bias1[cc]; b1v += bias1[cc + 1]; }
                int r0 = mrow + mt * 16;
                float2 v0 = make_float2(acc[mt][nt][0] + b0v, acc[mt][nt][1] + b1v);
                float2 v1 = make_float2(acc[mt][nt][2] + b0v, acc[mt][nt][3] + b1v);
                *(float2*)(C + (size_t)r0 * N + cc)       = v0;
                *(float2*)(C + (size_t)(r0 + 8) * N + cc) = v1;
            }
        }
    }
#undef PREFETCH
}

// ---------------- output-GEMM worker (PDL tertiary) ----------------------------
__global__ __launch_bounds__(128, 2) void gemm_worker(
    const __half* __restrict__ A, const __half* __restrict__ B,
    float* __restrict__ C, const float* __restrict__ bias0,
    int* __restrict__ stepf, int* __restrict__ ticket)
{
    extern __shared__ char smem[];
    __shared__ int tix;
    const uint32_t sb = smem_u32(smem);
    const int tid  = threadIdx.x;
    const int lane = tid & 31, wid = tid >> 5;
    const int wm = wid & 1, wn = wid >> 1;
    const int K = HID, N = VV;

    const int rowA = wm * 64 + (lane & 7) + ((lane >> 3) & 1) * 8;
    const int kxA  = ((lane >> 4) * 16) ^ ((rowA & 7) * 16);
    const int rowB = wn * 64 + (lane & 7) + ((lane >= 16) ? 8 : 0);
    const int kxB  = (((lane >> 3) & 1) * 16) ^ ((rowB & 7) * 16);
    const int prow = tid >> 3;
    const int pcc  = tid & 7;

    for (;;) {
        if (tid == 0) tix = atomicAdd(ticket, 1);
        __syncthreads();
        int tk = tix;
        __syncthreads();
        if (tk >= NTILES_TOT) return;
        const int m  = tk / NTILES_N;
        const int m0 = m * 128;
        const int n0 = (tk - m * NTILES_N) * 128;

        if (tid == 0) {
            const int target = 4 * m + 3;
            while (ld_acq(stepf) < target) __nanosleep(128);
        }
        __syncthreads();

        float acc[4][8][4];
#pragma unroll
        for (int i = 0; i < 4; i++)
#pragma unroll
            for (int j = 0; j < 8; j++)
#pragma unroll
                for (int e = 0; e < 4; e++) acc[i][j][e] = 0.f;

#define WPREFETCH(stage, kt)                                                    \
    do {                                                                        \
        uint32_t ab = sb + (stage) * STAGE_BYTES;                               \
        _Pragma("unroll")                                                       \
        for (int j = 0; j < 8; j++) {                                           \
            int row = prow + j * 16;                                            \
            uint32_t dst = ab + (uint32_t)(row * 128 + ((pcc * 16) ^ ((row & 7) * 16))); \
            cpasync16(dst, A + (size_t)(m0 + row) * K + (kt) + pcc * 8);        \
        }                                                                       \
        _Pragma("unroll")                                                       \
        for (int j = 0; j < 8; j++) {                                           \
            int row = prow + j * 16;                                            \
            int gn = n0 + row;                                                  \
            uint32_t dst = ab + 16384u + (uint32_t)(row * 128 + ((pcc * 16) ^ ((row & 7) * 16))); \
            int gnc = gn < N ? gn : N - 1;                                      \
            cpasync16z(dst, B + (size_t)gnc * K + (kt) + pcc * 8,               \
                       gn < N ? 16u : 0u);                                      \
        }                                                                       \
        CP_COMMIT();                                                            \
    } while (0)

        WPREFETCH(0, 0);
        WPREFETCH(1, KC);
#pragma unroll 1
        for (int c = 0; c < 8; c++) {
            if (c + 2 < 8) WPREFETCH((c + 2) % 3, (c + 2) * KC);
            if (c + 2 < 8)      asm volatile("cp.async.wait_group 2;" ::: "memory");
            else if (c + 1 < 8) asm volatile("cp.async.wait_group 1;" ::: "memory");
            else                asm volatile("cp.async.wait_group 0;" ::: "memory");
            __syncthreads();
            const uint32_t As = sb + (c % 3) * STAGE_BYTES;
            const uint32_t Bs = As + 16384;
#pragma unroll
            for (int ks = 0; ks < 4; ks++) {
                uint32_t a[4][4], b[4][4];
#pragma unroll
                for (int mt = 0; mt < 4; mt++)
                    ldsm4(a[mt], As + (uint32_t)((rowA + mt * 16) * 128 + ((ks * 32) ^ kxA)));
#pragma unroll
                for (int j = 0; j < 4; j++)
                    ldsm4(b[j], Bs + (uint32_t)((rowB + j * 16) * 128 + ((ks * 32) ^ kxB)));
#pragma unroll
                for (int mt = 0; mt < 4; mt++)
#pragma unroll
                    for (int nt = 0; nt < 8; nt++)
                        mma16816(acc[mt][nt], a[mt],
                                 b[nt >> 1][(nt & 1) * 2], b[nt >> 1][(nt & 1) * 2 + 1]);
            }
            __syncthreads();
        }
#undef WPREFETCH

        const int mrow  = m0 + wm * 64 + (lane >> 2);
        const int ncol0 = n0 + wn * 64 + (lane & 3) * 2;
#pragma unroll
        for (int mt = 0; mt < 4; mt++) {
#pragma unroll
            for (int nt = 0; nt < 8; nt++) {
                int cc = ncol0 + nt * 8;
                if (cc < N) {
                    float b0v = bias0[cc], b1v = bias0[cc + 1];
                    int r0 = mrow + mt * 16;
                    int or0 = (r0 & 31) * 64 + (r0 >> 5);        // b*64 + t
                    int or1 = ((r0 + 8) & 31) * 64 + ((r0 + 8) >> 5);
                    float2 v0 = make_float2(acc[mt][nt][0] + b0v, acc[mt][nt][1] + b1v);
                    float2 v1 = make_float2(acc[mt][nt][2] + b0v, acc[mt][nt][3] + b1v);
                    *(float2*)(C + (size_t)or0 * N + cc) = v0;
                    *(float2*)(C + (size_t)or1 * N + cc) = v1;
                }
            }
        }
    }
}

// ---------------- persistent LSTM, tensor-core recurrence ----------------------
// 32 CTAs x 256 threads. CTA owns 16 hidden units -> 64 gate rows (g*16+ul).
// W_hh fragments hoisted to registers (64/warp). 8 warps = 4 k-slices x 2
// 32-row groups (2 m16 tiles each). Barrier: 4 group counters, 8 arrivals each.
// h/H2 stores coalesced as __half2 (32B contiguous per b-row).
#define LWS_OFF  0
#define LHS_OFF  65536
#define LPG_OFF  98304                         // 2 x 8KB pregates buffers
#define LGSM_OFF (98304 + 16384)
#define GK (64 * 33)                           // one k-slice gsm buffer (floats)
#define LCSM_OFF (LGSM_OFF + 4 * GK * 4)
#define LSM_BYTES (LCSM_OFF + 512 * 4)

__device__ __forceinline__ float sigf(float x) { return 1.0f / (1.0f + expf(-x)); }

__global__ __launch_bounds__(256, 1) void lstm_persistent(
    const float* __restrict__ pregates,
    const __half* __restrict__ Whh2,
    __half* __restrict__ hA, __half* __restrict__ hB,
    __half* __restrict__ H2, int* __restrict__ bars, int* __restrict__ stepf)
{
    extern __shared__ char smem[];
    const uint32_t sb = smem_u32(smem);
    float* gsm = (float*)(smem + LGSM_OFF);
    float* csm = (float*)(smem + LCSM_OFF);

    const int tid  = threadIdx.x;
    const int lane = tid & 31, wid = tid >> 5;
    const int u0   = blockIdx.x * 16;

    // PDL: release the dependent cvt_wfc (and transitively workers)
    if (tid == 0) cudaTriggerProgrammaticLaunchCompletion();

    // pregates prefetch geometry: 2 x cp.async16 per thread
    // covers 32 b x 4 gates x 16 units (8 KB)
    const int qb = tid >> 3, qg = (tid >> 1) & 3, qh = tid & 1;
    const size_t qsrc_base = (size_t)qb * TT * G4 + qg * 512 + u0 + qh * 4;
    const uint32_t qdst_off = (uint32_t)(qb * 256 + qg * 64 + qh * 16);

    // stage 64 gate rows of W_hh (fp16): rr = g*16+ul <-> global g*512+u0+ul
    for (int i = tid; i < 4096; i += 256) {
        int rr = i >> 6, cq = i & 63;
        int g = rr >> 4, ul = rr & 15;
        uint32_t dst = sb + LWS_OFF + (uint32_t)(rr * 1024 + ((cq * 16) ^ ((rr & 7) * 16)));
        cpasync16(dst, Whh2 + (size_t)(g * 512 + u0 + ul) * HID + cq * 8);
    }
    CP_COMMIT();
    // prefetch pregates for t = 0 into buffer 0
    cpasync16(sb + LPG_OFF + qdst_off,      pregates + qsrc_base);
    cpasync16(sb + LPG_OFF + qdst_off + 32, pregates + qsrc_base + 8);
    CP_COMMIT();
    csm[tid] = 0.0f;
    csm[tid + 256] = 0.0f;

    // warp geometry: km = k-slice (0..3, 128 k), mg = 32-row group (0/1)
    const int km = wid >> 1, mg = wid & 1;
    const int kbase = km * 256;                 // byte offset of k-slice in row
    const int kxA  = (lane >> 4) * 16;
    const int rb   = lane & 7;
    const int kxB  = ((lane >> 3) & 3) * 16;
    const int sxB  = rb * 16;
    const uint32_t wsb = sb + LWS_OFF, hsb = sb + LHS_OFF;

    asm volatile("cp.async.wait_group 0;" ::: "memory");
    __syncthreads();
    // hoist A fragments (time-invariant): 2 m16 tiles x 4 k-chunks x 2 frags
    uint32_t afr[2][4][2][4];
#pragma unroll
    for (int mt = 0; mt < 2; mt++) {
        int rowA = mg * 32 + mt * 16 + (lane & 15);
        int sxA  = (rowA & 7) * 16;
#pragma unroll
        for (int ks = 0; ks < 4; ks++) {
            int kb = kbase + ks * 64;
            ldsm4(afr[mt][ks][0], wsb + (uint32_t)(rowA * 1024 + ((kb + kxA) ^ sxA)));
            ldsm4(afr[mt][ks][1], wsb + (uint32_t)(rowA * 1024 + ((kb + 32 + kxA) ^ sxA)));
        }
    }

    // pointwise mapping: tid -> (b = tid>>3, unit pair up = (tid&7)*2)
    const int pb = tid >> 3, pup = (tid & 7) * 2;
    const int pu = u0 + pup;

    for (int t = 0; t < TT; t++) {
        // stage h (fp16 32x512) into swizzled SMEM
        const __half* hin = (t & 1) ? hB : hA;
        for (int i = tid; i < 2048; i += 256) {
            int b = i >> 6, cq = i & 63;
            uint32_t dst = hsb + (uint32_t)(b * 1024 + ((cq * 16) ^ ((b & 7) * 16)));
            cpasync16(dst, hin + b * HID + cq * 8);
        }
        CP_COMMIT();
        if (t + 1 < TT) {
            uint32_t pgd = sb + LPG_OFF + ((t + 1) & 1) * 8192 + qdst_off;
            const float* pgsrc = pregates + qsrc_base + (size_t)(t + 1) * G4;
            cpasync16(pgd,      pgsrc);
            cpasync16(pgd + 32, pgsrc + 8);
            CP_COMMIT();
            asm volatile("cp.async.wait_group 1;" ::: "memory");
        } else {
            asm volatile("cp.async.wait_group 0;" ::: "memory");
        }
        __syncthreads();

        // MMA: warp computes [32 gate-rows x 32 batch] over its 128-k slice
        float cacc[2][4][4];
#pragma unroll
        for (int mt = 0; mt < 2; mt++)
#pragma unroll
            for (int j = 0; j < 4; j++)
#pragma unroll
                for (int e = 0; e < 4; e++) cacc[mt][j][e] = 0.f;
#pragma unroll
        for (int ks = 0; ks < 4; ks++) {
            int kb = kbase + ks * 64;
            uint32_t bf[4][4];
#pragma unroll
            for (int j = 0; j < 4; j++)
                ldsm4(bf[j], hsb + (uint32_t)((j * 8 + rb) * 1024 + ((kb + kxB) ^ sxB)));
#pragma unroll
            for (int mt = 0; mt < 2; mt++)
#pragma unroll
                for (int j = 0; j < 4; j++) {
                    mma16816(cacc[mt][j], afr[mt][ks][0], bf[j][0], bf[j][1]);
                    mma16816(cacc[mt][j], afr[mt][ks][1], bf[j][2], bf[j][3]);
                }
        }
        // store partials to this k-slice's gsm buffer
        {
            float* gk = gsm + km * GK;
            int cc = (lane & 3) * 2;
#pragma unroll
            for (int mt = 0; mt < 2; mt++) {
                int r0 = mg * 32 + mt * 16 + (lane >> 2);
#pragma unroll
                for (int j = 0; j < 4; j++) {
                    gk[r0 * 33 + cc + j * 8]           = cacc[mt][j][0];
                    gk[r0 * 33 + cc + j * 8 + 1]       = cacc[mt][j][1];
                    gk[(r0 + 8) * 33 + cc + j * 8]     = cacc[mt][j][2];
                    gk[(r0 + 8) * 33 + cc + j * 8 + 1] = cacc[mt][j][3];
                }
            }
        }
        __syncthreads();

        // pointwise: 256 threads = 32 b x 8 unit-pairs; sum 4 k-partials + pg
        {
            const float* pgs = (const float*)(smem + LPG_OFF + (t & 1) * 8192);
            __half2 hh2;
            float hn2[2];
#pragma unroll
            for (int s = 0; s < 2; s++) {
                int ul = pup + s;
                float gi = pgs[pb * 64 + 0 * 16 + ul];
                float gf = pgs[pb * 64 + 1 * 16 + ul];
                float gg = pgs[pb * 64 + 2 * 16 + ul];
                float go = pgs[pb * 64 + 3 * 16 + ul];
#pragma unroll
                for (int k = 0; k < 4; k++) {
                    const float* gk = gsm + k * GK;
                    gi += gk[(0  + ul) * 33 + pb];
                    gf += gk[(16 + ul) * 33 + pb];
                    gg += gk[(32 + ul) * 33 + pb];
                    go += gk[(48 + ul) * 33 + pb];
                }
                float c_old = csm[pb * 16 + ul];
                float cn = sigf(gf) * c_old + sigf(gi) * tanhf(gg);
                hn2[s] = sigf(go) * tanhf(cn);
                csm[pb * 16 + ul] = cn;
            }
            hh2 = __floats2half2_rn(hn2[0], hn2[1]);
            __half* hout = (t & 1) ? hA : hB;
            *(__half2*)(hout + pb * HID + pu) = hh2;
            *(__half2*)(H2 + ((size_t)t * 32 + pb) * HID + pu) = hh2;   // T-MAJOR
        }

        __syncthreads();
        if (tid == 0) {
            __threadfence();
            atomicAdd(&bars[(blockIdx.x & 3) * 64], 1);
        }
        if (t < TT - 1 || blockIdx.x == 0) {       // block-uniform branch
            if (tid < 4) {
                int target = 8 * (t + 1);
                while (*(volatile int*)&bars[tid * 64] < target) { }
                __threadfence();
            }
            __syncthreads();
            if (blockIdx.x == 0 && tid == 0) st_rel(stepf, t);
        }
    }
}

// ---------------- launch ------------------------------------------------------
extern "C" void kernel_launch(void* const* d_in, const int* in_sizes, int n_in,
                              void* d_out, int out_size)
{
    const float* enc       = (const float*)d_in[0];
    const int*   captions  = (const int*)  d_in[1];
    const float* emb_table = (const float*)d_in[8];
    const float* W_ih      = (const float*)d_in[9];
    const float* W_hh      = (const float*)d_in[10];
    const float* b_ih      = (const float*)d_in[11];
    const float* b_hh      = (const float*)d_in[12];
    const float* W_fc      = (const float*)d_in[13];
    const float* b_fc      = (const float*)d_in[14];
    float* out = (float*)d_out;

    __half *pX2, *pWih2, *pWhh2, *pWfc2, *pH2, *ph2A, *ph2B;
    float *pPG;
    int *pBars, *pTicket, *pStep;
    cudaGetSymbolAddress((void**)&pX2, g_X2);
    cudaGetSymbolAddress((void**)&pWih2, g_Wih2);
    cudaGetSymbolAddress((void**)&pWhh2, g_Whh2);
    cudaGetSymbolAddress((void**)&pWfc2, g_Wfc2);
    cudaGetSymbolAddress((void**)&pH2, g_H2);
    cudaGetSymbolAddress((void**)&ph2A, g_h2A);
    cudaGetSymbolAddress((void**)&ph2B, g_h2B);
    cudaGetSymbolAddress((void**)&pPG, g_pg);
    cudaGetSymbolAddress((void**)&pBars, g_bars);
    cudaGetSymbolAddress((void**)&pTicket, g_ticket);
    cudaGetSymbolAddress((void**)&pStep, g_step);

    cudaFuncSetAttribute(hmma_gemm, cudaFuncAttributeMaxDynamicSharedMemorySize, GSMEM);
    cudaFuncSetAttribute(gemm_worker, cudaFuncAttributeMaxDynamicSharedMemorySize, GSMEM);
    cudaFuncSetAttribute(lstm_persistent, cudaFuncAttributeMaxDynamicSharedMemorySize, LSM_BYTES);

    // 1) prep: X2, h0+flags, cvt(Wih,Whh)
    prep_kernel<<<MROWS + 32 + NBLK_WSMALL, 256>>>(enc, captions, emb_table,
                                                   W_ih, W_hh, pX2, pWih2, pWhh2,
                                                   ph2A, pBars, pTicket, pStep);

    // 2) pregates = X @ W_ih^T + b_ih + b_hh   (K = 768)
    {
        dim3 grid(G4 / 128, MROWS / 128);
        hmma_gemm<<<grid, 128, GSMEM>>>(pX2, pWih2, pPG, b_ih, b_hh,
                                        MROWS, G4, XD);
    }

    // 3) persistent tensor-core LSTM (32 CTAs; PDL primary, triggers at top)
    lstm_persistent<<<32, 256, LSM_BYTES>>>(pPG, pWhh2, ph2A, ph2B, pH2,
                                            pBars, pStep);

    // 4) W_fc convert — PDL secondary (overlaps the LSTM on free SMs)
    {
        cudaLaunchConfig_t cfg = {};
        cfg.gridDim = dim3((N2_WFC + 255) / 256, 1, 1);
        cfg.blockDim = dim3(256, 1, 1);
        cfg.stream = 0;
        cudaLaunchAttribute at[1];
        at[0].id = cudaLaunchAttributeProgrammaticStreamSerialization;
        at[0].val.programmaticStreamSerializationAllowed = 1;
        cfg.attrs = at;
        cfg.numAttrs = 1;
        cudaError_t e = cudaLaunchKernelEx(&cfg, cvt_wfc_kernel, W_fc, pWfc2);
        if (e != cudaSuccess)
            cvt_wfc_kernel<<<(N2_WFC + 255) / 256, 256>>>(W_fc, pWfc2);
    }

    // 5) output-GEMM workers — PDL tertiary
    {
        cudaLaunchConfig_t cfg = {};
        cfg.gridDim = dim3(296, 1, 1);
        cfg.blockDim = dim3(128, 1, 1);
        cfg.dynamicSmemBytes = GSMEM;
        cfg.stream = 0;
        cudaLaunchAttribute at[1];
        at[0].id = cudaLaunchAttributeProgrammaticStreamSerialization;
        at[0].val.programmaticStreamSerializationAllowed = 1;
        cfg.attrs = at;
        cfg.numAttrs = 1;
        cudaError_t e = cudaLaunchKernelEx(&cfg, gemm_worker,
                                           (const __half*)pH2, (const __half*)pWfc2,
                                           out, b_fc, pStep, pTicket);
        if (e != cudaSuccess) {
            gemm_worker<<<296, 128, GSMEM>>>(pH2, pWfc2, out, b_fc, pStep, pTicket);
        }
    }
}

// round 16
// speedup vs baseline: 1.9883x; 1.0209x over previous
#include <cuda_runtime.h>
#include <cuda_fp16.h>
#include <math.h>
#include <stdint.h>

// Problem dims
#define TT   64
#define VV   30000
#define HID  512
#define XD   768          // EMB + E
#define G4   2048         // 4*H
#define MROWS 2048        // B*T
#define NTILES_N 235      // ceil(30000/128)
#define NTILES_M 16
#define NTILES_TOT (NTILES_M * NTILES_N)

// ---------------- scratch (device globals; no allocation allowed) -------------
__device__ __align__(16) __half g_X2  [MROWS * XD];          // fp16 X, T-MAJOR (row = t*32+b)
__device__ __align__(16) __half g_Wih2[G4 * XD];             // fp16 W_ih
__device__ __align__(16) __half g_Whh2[G4 * HID];            // fp16 W_hh
__device__ __align__(16) __half g_Wfc2[(size_t)VV * HID];    // fp16 W_fc
__device__ __align__(16) __half g_H2  [MROWS * HID];         // fp16 hidden, T-MAJOR
__device__ __align__(16) __half g_h2A [32 * HID];            // h state ping
__device__ __align__(16) __half g_h2B [32 * HID];            // h state pong
__device__ __align__(16) float  g_pg[MROWS * G4];            // pregates fp32, T-MAJOR
__device__ __align__(16) int    g_bars[512];                 // 4 counters, 256B apart
__device__ int g_ticket;
__device__ int g_step;                                       // published LSTM progress
__device__ int g_pgp[16];                                    // pregates m-group progress

// ---------------- small helpers ------------------------------------------------
__device__ __forceinline__ uint32_t smem_u32(const void* p) {
    uint32_t a;
    asm("{ .reg .u64 t; cvta.to.shared.u64 t, %1; cvt.u32.u64 %0, t; }" : "=r"(a) : "l"(p));
    return a;
}
__device__ __forceinline__ void ldsm4(uint32_t* r, uint32_t addr) {
    asm volatile("ldmatrix.sync.aligned.m8n8.x4.shared.b16 {%0,%1,%2,%3}, [%4];"
                 : "=r"(r[0]), "=r"(r[1]), "=r"(r[2]), "=r"(r[3]) : "r"(addr));
}
__device__ __forceinline__ void mma16816(float* d, const uint32_t* a,
                                         uint32_t b0, uint32_t b1) {
    asm volatile("mma.sync.aligned.m16n8k16.row.col.f32.f16.f16.f32 "
                 "{%0,%1,%2,%3}, {%4,%5,%6,%7}, {%8,%9}, {%0,%1,%2,%3};"
                 : "+f"(d[0]), "+f"(d[1]), "+f"(d[2]), "+f"(d[3])
                 : "r"(a[0]), "r"(a[1]), "r"(a[2]), "r"(a[3]), "r"(b0), "r"(b1));
}
__device__ __forceinline__ void cpasync16(uint32_t dst, const void* src) {
    asm volatile("cp.async.cg.shared.global [%0], [%1], 16;" :: "r"(dst), "l"(src));
}
__device__ __forceinline__ void cpasync16z(uint32_t dst, const void* src, unsigned sz) {
    asm volatile("cp.async.cg.shared.global [%0], [%1], 16, %2;"
                 :: "r"(dst), "l"(src), "r"(sz));
}
#define CP_COMMIT() asm volatile("cp.async.commit_group;" ::: "memory")
__device__ __forceinline__ int ld_acq(const int* p) {
    int v;
    asm volatile("ld.acquire.gpu.global.b32 %0, [%1];" : "=r"(v) : "l"(p) : "memory");
    return v;
}
__device__ __forceinline__ void st_rel(int* p, int v) {
    asm volatile("st.release.gpu.global.b32 [%0], %1;" :: "l"(p), "r"(v) : "memory");
}

#define N2_WIH (G4 * XD / 2)
#define N2_WHH (G4 * HID / 2)
#define N2_WFC (VV * HID / 2)
#define NBLK_WSMALL ((N2_WIH + N2_WHH + 255) / 256)

// ---------------- prep: X2 (t-major), h ping zero, flags, cvt(Wih,Whh) ---------
__global__ void prep_kernel(const float* __restrict__ enc,
                            const int*   __restrict__ captions,
                            const float* __restrict__ emb_table,
                            const float* __restrict__ Wih,
                            const float* __restrict__ Whh,
                            __half* __restrict__ X2,
                            __half* __restrict__ dWih,
                            __half* __restrict__ dWhh,
                            __half* __restrict__ h0, int* __restrict__ bars,
                            int* __restrict__ ticket, int* __restrict__ stepf,
                            int* __restrict__ pgp)
{
    int blk = blockIdx.x;
    if (blk < MROWS) {
        int b = blk >> 6, t = blk & 63;
        int cap = captions[blk];
        const float* erow = emb_table + (size_t)cap * 512;
        const float* crow = enc + (size_t)b * 256;
        size_t base = (size_t)(t * 32 + b) * XD;          // T-MAJOR row
        for (int c = threadIdx.x; c < XD; c += 256) {
            float x = (c < 512) ? erow[c] : crow[c - 512];
            X2[base + c] = __float2half(x);
        }
    } else if (blk < MROWS + 32) {
        int i = (blk - MROWS) * 256 + threadIdx.x;   // 0..8191
        ((uint32_t*)h0)[i] = 0u;
        if (i < 512) bars[i] = 0;
        if (i < 16) pgp[i] = 0;
        if (i == 0) { *ticket = 0; *stepf = -1; }
    } else {
        int i = (blk - MROWS - 32) * 256 + threadIdx.x;
        const float* src;
        __half* dst;
        if (i < N2_WIH) { src = Wih; dst = dWih; }
        else            { src = Whh; dst = dWhh; i -= N2_WIH;
                          if (i >= N2_WHH) return; }
        float2 v = ((const float2*)src)[i];
        ((__half2*)dst)[i] = __floats2half2_rn(v.x, v.y);
    }
}

// ---------------- W_fc convert (PDL: overlaps the LSTM) ------------------------
__global__ void cvt_wfc_kernel(const float* __restrict__ Wfc,
                               __half* __restrict__ dWfc)
{
    int i = blockIdx.x * 256 + threadIdx.x;
    if (i >= N2_WFC) return;
    float2 v = ((const float2*)Wfc)[i];
    ((__half2*)dWfc)[i] = __floats2half2_rn(v.x, v.y);
}

// ---------------- GEMM mainloop shared geometry --------------------------------
#define KC 64
#define STAGE_BYTES 32768      // A 16KB + B 16KB
#define GSMEM (3 * STAGE_BYTES)

// ---------------- HMMA GEMM (pregates): C = A B^T + bias0 + bias1 --------------
// Triggers PDL at CTA-top (releases the LSTM); bumps prog[blockIdx.y] when its
// tile (steps 4m..4m+3) is fully stored.
__global__ __launch_bounds__(128, 2) void hmma_gemm(
    const __half* __restrict__ A, const __half* __restrict__ B,
    float* __restrict__ C,
    const float* __restrict__ bias0, const float* __restrict__ bias1,
    int M, int N, int K, int* __restrict__ prog)
{
    extern __shared__ char smem[];
    const uint32_t sb = smem_u32(smem);
    const int tid  = threadIdx.x;
    const int lane = tid & 31, wid = tid >> 5;
    const int m0 = blockIdx.y * 128, n0 = blockIdx.x * 128;
    const int wm = wid & 1, wn = wid >> 1;
    const int nch = K / KC;

    if (tid == 0) cudaTriggerProgrammaticLaunchCompletion();

    const int rowA = wm * 64 + (lane & 7) + ((lane >> 3) & 1) * 8;
    const int kxA  = ((lane >> 4) * 16) ^ ((rowA & 7) * 16);
    const int rowB = wn * 64 + (lane & 7) + ((lane >= 16) ? 8 : 0);
    const int kxB  = (((lane >> 3) & 1) * 16) ^ ((rowB & 7) * 16);

    float acc[4][8][4];
#pragma unroll
    for (int i = 0; i < 4; i++)
#pragma unroll
        for (int j = 0; j < 8; j++)
#pragma unroll
            for (int e = 0; e < 4; e++) acc[i][j][e] = 0.f;

    const int prow = tid >> 3;
    const int pcc  = tid & 7;
#define PREFETCH(stage, kt)                                                     \
    do {                                                                        \
        uint32_t ab = sb + (stage) * STAGE_BYTES;                               \
        _Pragma("unroll")                                                       \
        for (int j = 0; j < 8; j++) {                                           \
            int row = prow + j * 16;                                            \
            uint32_t dst = ab + (uint32_t)(row * 128 + ((pcc * 16) ^ ((row & 7) * 16))); \
            cpasync16(dst, A + (size_t)(m0 + row) * K + (kt) + pcc * 8);        \
        }                                                                       \
        _Pragma("unroll")                                                       \
        for (int j = 0; j < 8; j++) {                                           \
            int row = prow + j * 16;                                            \
            int gn = n0 + row;                                                  \
            uint32_t dst = ab + 16384u + (uint32_t)(row * 128 + ((pcc * 16) ^ ((row & 7) * 16))); \
            int gnc = gn < N ? gn : N - 1;                                      \
            cpasync16z(dst, B + (size_t)gnc * K + (kt) + pcc * 8,               \
                       gn < N ? 16u : 0u);                                      \
        }                                                                       \
        CP_COMMIT();                                                            \
    } while (0)

    PREFETCH(0, 0);
    PREFETCH(1, KC);
    for (int c = 0; c < nch; c++) {
        if (c + 2 < nch) PREFETCH((c + 2) % 3, (c + 2) * KC);
        if (c + 2 < nch)      asm volatile("cp.async.wait_group 2;" ::: "memory");
        else if (c + 1 < nch) asm volatile("cp.async.wait_group 1;" ::: "memory");
        else                  asm volatile("cp.async.wait_group 0;" ::: "memory");
        __syncthreads();
        const uint32_t As = sb + (c % 3) * STAGE_BYTES;
        const uint32_t Bs = As + 16384;
#pragma unroll
        for (int ks = 0; ks < 4; ks++) {
            uint32_t a[4][4], b[4][4];
#pragma unroll
            for (int mt = 0; mt < 4; mt++)
                ldsm4(a[mt], As + (uint32_t)((rowA + mt * 16) * 128 + ((ks * 32) ^ kxA)));
#pragma unroll
            for (int j = 0; j < 4; j++)
                ldsm4(b[j], Bs + (uint32_t)((rowB + j * 16) * 128 + ((ks * 32) ^ kxB)));
#pragma unroll
            for (int mt = 0; mt < 4; mt++)
#pragma unroll
                for (int nt = 0; nt < 8; nt++)
                    mma16816(acc[mt][nt], a[mt],
                             b[nt >> 1][(nt & 1) * 2], b[nt >> 1][(nt & 1) * 2 + 1]);
        }
        __syncthreads();
    }

    const int mrow  = m0 + wm * 64 + (lane >> 2);
    const int ncol0 = n0 + wn * 64 + (lane & 3) * 2;
#pragma unroll
    for (int mt = 0; mt < 4; mt++) {
#pragma unroll
        for (int nt = 0; nt < 8; nt++) {
            int cc = ncol0 + nt * 8;
            if (cc < N) {
                float b0v = bias0[cc], b1v = bias0[cc + 1];
                if (bias1) { b0v += bias1[cc]; b1v += bias1[cc + 1]; }
                int r0 = mrow + mt * 16;
                float2 v0 = make_float2(acc[mt][nt][0] + b0v, acc[mt][nt][1] + b1v);
                float2 v1 = make_float2(acc[mt][nt][2] + b0v, acc[mt][nt][3] + b1v);
                *(float2*)(C + (size_t)r0 * N + cc)       = v0;
                *(float2*)(C + (size_t)(r0 + 8) * N + cc) = v1;
            }
        }
    }
    // publish tile completion for the LSTM's gated pg-prefetch
    __threadfence();
    __syncthreads();
    if (tid == 0 && prog) atomicAdd(&prog[blockIdx.y], 1);
#undef PREFETCH
}

// ---------------- output-GEMM worker (PDL tail of the chain) --------------------
__global__ __launch_bounds__(128, 2) void gemm_worker(
    const __half* __restrict__ A, const __half* __restrict__ B,
    float* __restrict__ C, const float* __restrict__ bias0,
    int* __restrict__ stepf, int* __restrict__ ticket)
{
    extern __shared__ char smem[];
    __shared__ int tix;
    const uint32_t sb = smem_u32(smem);
    const int tid  = threadIdx.x;
    const int lane = tid & 31, wid = tid >> 5;
    const int wm = wid & 1, wn = wid >> 1;
    const int K = HID, N = VV;

    const int rowA = wm * 64 + (lane & 7) + ((lane >> 3) & 1) * 8;
    const int kxA  = ((lane >> 4) * 16) ^ ((rowA & 7) * 16);
    const int rowB = wn * 64 + (lane & 7) + ((lane >= 16) ? 8 : 0);
    const int kxB  = (((lane >> 3) & 1) * 16) ^ ((rowB & 7) * 16);
    const int prow = tid >> 3;
    const int pcc  = tid & 7;

    for (;;) {
        if (tid == 0) tix = atomicAdd(ticket, 1);
        __syncthreads();
        int tk = tix;
        __syncthreads();
        if (tk >= NTILES_TOT) return;
        const int m  = tk / NTILES_N;
        const int m0 = m * 128;
        const int n0 = (tk - m * NTILES_N) * 128;

        if (tid == 0) {
            const int target = 4 * m + 3;
            while (ld_acq(stepf) < target) __nanosleep(128);
        }
        __syncthreads();

        float acc[4][8][4];
#pragma unroll
        for (int i = 0; i < 4; i++)
#pragma unroll
            for (int j = 0; j < 8; j++)
#pragma unroll
                for (int e = 0; e < 4; e++) acc[i][j][e] = 0.f;

#define WPREFETCH(stage, kt)                                                    \
    do {                                                                        \
        uint32_t ab = sb + (stage) * STAGE_BYTES;                               \
        _Pragma("unroll")                                                       \
        for (int j = 0; j < 8; j++) {                                           \
            int row = prow + j * 16;                                            \
            uint32_t dst = ab + (uint32_t)(row * 128 + ((pcc * 16) ^ ((row & 7) * 16))); \
            cpasync16(dst, A + (size_t)(m0 + row) * K + (kt) + pcc * 8);        \
        }                                                                       \
        _Pragma("unroll")                                                       \
        for (int j = 0; j < 8; j++) {                                           \
            int row = prow + j * 16;                                            \
            int gn = n0 + row;                                                  \
            uint32_t dst = ab + 16384u + (uint32_t)(row * 128 + ((pcc * 16) ^ ((row & 7) * 16))); \
            int gnc = gn < N ? gn : N - 1;                                      \
            cpasync16z(dst, B + (size_t)gnc * K + (kt) + pcc * 8,               \
                       gn < N ? 16u : 0u);                                      \
        }                                                                       \
        CP_COMMIT();                                                            \
    } while (0)

        WPREFETCH(0, 0);
        WPREFETCH(1, KC);
#pragma unroll 1
        for (int c = 0; c < 8; c++) {
            if (c + 2 < 8) WPREFETCH((c + 2) % 3, (c + 2) * KC);
            if (c + 2 < 8)      asm volatile("cp.async.wait_group 2;" ::: "memory");
            else if (c + 1 < 8) asm volatile("cp.async.wait_group 1;" ::: "memory");
            else                asm volatile("cp.async.wait_group 0;" ::: "memory");
            __syncthreads();
            const uint32_t As = sb + (c % 3) * STAGE_BYTES;
            const uint32_t Bs = As + 16384;
#pragma unroll
            for (int ks = 0; ks < 4; ks++) {
                uint32_t a[4][4], b[4][4];
#pragma unroll
                for (int mt = 0; mt < 4; mt++)
                    ldsm4(a[mt], As + (uint32_t)((rowA + mt * 16) * 128 + ((ks * 32) ^ kxA)));
#pragma unroll
                for (int j = 0; j < 4; j++)
                    ldsm4(b[j], Bs + (uint32_t)((rowB + j * 16) * 128 + ((ks * 32) ^ kxB)));
#pragma unroll
                for (int mt = 0; mt < 4; mt++)
#pragma unroll
                    for (int nt = 0; nt < 8; nt++)
                        mma16816(acc[mt][nt], a[mt],
                                 b[nt >> 1][(nt & 1) * 2], b[nt >> 1][(nt & 1) * 2 + 1]);
            }
            __syncthreads();
        }
#undef WPREFETCH

        const int mrow  = m0 + wm * 64 + (lane >> 2);
        const int ncol0 = n0 + wn * 64 + (lane & 3) * 2;
#pragma unroll
        for (int mt = 0; mt < 4; mt++) {
#pragma unroll
            for (int nt = 0; nt < 8; nt++) {
                int cc = ncol0 + nt * 8;
                if (cc < N) {
                    float b0v = bias0[cc], b1v = bias0[cc + 1];
                    int r0 = mrow + mt * 16;
                    int or0 = (r0 & 31) * 64 + (r0 >> 5);        // b*64 + t
                    int or1 = ((r0 + 8) & 31) * 64 + ((r0 + 8) >> 5);
                    float2 v0 = make_float2(acc[mt][nt][0] + b0v, acc[mt][nt][1] + b1v);
                    float2 v1 = make_float2(acc[mt][nt][2] + b0v, acc[mt][nt][3] + b1v);
                    *(float2*)(C + (size_t)or0 * N + cc) = v0;
                    *(float2*)(C + (size_t)or1 * N + cc) = v1;
                }
            }
        }
    }
}

// ---------------- persistent LSTM, tensor-core recurrence ----------------------
// 32 CTAs x 256 threads; 16 units/CTA. A-fragments in registers. pg prefetch
// gated on pregates m-group progress (t-major pg). Barrier: 4 group counters.
#define LWS_OFF  0
#define LHS_OFF  65536
#define LPG_OFF  98304                         // 2 x 8KB pregates buffers
#define LGSM_OFF (98304 + 16384)
#define GK (64 * 33)
#define LCSM_OFF (LGSM_OFF + 4 * GK * 4)
#define LSM_BYTES (LCSM_OFF + 512 * 4)

__device__ __forceinline__ float sigf(float x) { return 1.0f / (1.0f + expf(-x)); }

__global__ __launch_bounds__(256, 1) void lstm_persistent(
    const float* __restrict__ pregates,
    const __half* __restrict__ Whh2,
    __half* __restrict__ hA, __half* __restrict__ hB,
    __half* __restrict__ H2, int* __restrict__ bars, int* __restrict__ stepf,
    int* __restrict__ pgp)
{
    extern __shared__ char smem[];
    const uint32_t sb = smem_u32(smem);
    float* gsm = (float*)(smem + LGSM_OFF);
    float* csm = (float*)(smem + LCSM_OFF);

    const int tid  = threadIdx.x;
    const int lane = tid & 31, wid = tid >> 5;
    const int u0   = blockIdx.x * 16;

    // PDL: release cvt_wfc (and transitively workers)
    if (tid == 0) cudaTriggerProgrammaticLaunchCompletion();

    // pregates prefetch geometry (t-major: row = t*32+b)
    const int qb = tid >> 3, qg = (tid >> 1) & 3, qh = tid & 1;
    const size_t qsrc_base = (size_t)qb * G4 + qg * 512 + u0 + qh * 4;
    const uint32_t qdst_off = (uint32_t)(qb * 256 + qg * 64 + qh * 16);

    // stage 64 gate rows of W_hh (fp16)
    for (int i = tid; i < 4096; i += 256) {
        int rr = i >> 6, cq = i & 63;
        int g = rr >> 4, ul = rr & 15;
        uint32_t dst = sb + LWS_OFF + (uint32_t)(rr * 1024 + ((cq * 16) ^ ((rr & 7) * 16)));
        cpasync16(dst, Whh2 + (size_t)(g * 512 + u0 + ul) * HID + cq * 8);
    }
    CP_COMMIT();
    // gate + prefetch pregates for t = 0 (group 0)
    if (tid == 0) { while (ld_acq(&pgp[0]) < 16) __nanosleep(64); }
    __syncthreads();
    cpasync16(sb + LPG_OFF + qdst_off,      pregates + qsrc_base);
    cpasync16(sb + LPG_OFF + qdst_off + 32, pregates + qsrc_base + 8);
    CP_COMMIT();
    csm[tid] = 0.0f;
    csm[tid + 256] = 0.0f;

    // warp geometry
    const int km = wid >> 1, mg = wid & 1;
    const int kbase = km * 256;
    const int kxA  = (lane >> 4) * 16;
    const int rb   = lane & 7;
    const int kxB  = ((lane >> 3) & 3) * 16;
    const int sxB  = rb * 16;
    const uint32_t wsb = sb + LWS_OFF, hsb = sb + LHS_OFF;

    asm volatile("cp.async.wait_group 0;" ::: "memory");
    __syncthreads();
    uint32_t afr[2][4][2][4];
#pragma unroll
    for (int mt = 0; mt < 2; mt++) {
        int rowA = mg * 32 + mt * 16 + (lane & 15);
        int sxA  = (rowA & 7) * 16;
#pragma unroll
        for (int ks = 0; ks < 4; ks++) {
            int kb = kbase + ks * 64;
            ldsm4(afr[mt][ks][0], wsb + (uint32_t)(rowA * 1024 + ((kb + kxA) ^ sxA)));
            ldsm4(afr[mt][ks][1], wsb + (uint32_t)(rowA * 1024 + ((kb + 32 + kxA) ^ sxA)));
        }
    }

    const int pb = tid >> 3, pup = (tid & 7) * 2;
    const int pu = u0 + pup;

    for (int t = 0; t < TT; t++) {
        const __half* hin = (t & 1) ? hB : hA;
        for (int i = tid; i < 2048; i += 256) {
            int b = i >> 6, cq = i & 63;
            uint32_t dst = hsb + (uint32_t)(b * 1024 + ((cq * 16) ^ ((b & 7) * 16)));
            cpasync16(dst, hin + b * HID + cq * 8);
        }
        CP_COMMIT();
        if (t + 1 < TT) {
            if (((t + 1) & 3) == 0) {          // new pregates m-group boundary
                if (tid == 0) {
                    while (ld_acq(&pgp[(t + 1) >> 2]) < 16) __nanosleep(64);
                }
                __syncthreads();
            }
            uint32_t pgd = sb + LPG_OFF + ((t + 1) & 1) * 8192 + qdst_off;
            const float* pgsrc = pregates + qsrc_base + (size_t)(t + 1) * 32 * G4;
            cpasync16(pgd,      pgsrc);
            cpasync16(pgd + 32, pgsrc + 8);
            CP_COMMIT();
            asm volatile("cp.async.wait_group 1;" ::: "memory");
        } else {
            asm volatile("cp.async.wait_group 0;" ::: "memory");
        }
        __syncthreads();

        float cacc[2][4][4];
#pragma unroll
        for (int mt = 0; mt < 2; mt++)
#pragma unroll
            for (int j = 0; j < 4; j++)
#pragma unroll
                for (int e = 0; e < 4; e++) cacc[mt][j][e] = 0.f;
#pragma unroll
        for (int ks = 0; ks < 4; ks++) {
            int kb = kbase + ks * 64;
            uint32_t bf[4][4];
#pragma unroll
            for (int j = 0; j < 4; j++)
                ldsm4(bf[j], hsb + (uint32_t)((j * 8 + rb) * 1024 + ((kb + kxB) ^ sxB)));
#pragma unroll
            for (int mt = 0; mt < 2; mt++)
#pragma unroll
                for (int j = 0; j < 4; j++) {
                    mma16816(cacc[mt][j], afr[mt][ks][0], bf[j][0], bf[j][1]);
                    mma16816(cacc[mt][j], afr[mt][ks][1], bf[j][2], bf[j][3]);
                }
        }
        {
            float* gk = gsm + km * GK;
            int cc = (lane & 3) * 2;
#pragma unroll
            for (int mt = 0; mt < 2; mt++) {
                int r0 = mg * 32 + mt * 16 + (lane >> 2);
#pragma unroll
                for (int j = 0; j < 4; j++) {
                    gk[r0 * 33 + cc + j * 8]           = cacc[mt][j][0];
                    gk[r0 * 33 + cc + j * 8 + 1]       = cacc[mt][j][1];
                    gk[(r0 + 8) * 33 + cc + j * 8]     = cacc[mt][j][2];
                    gk[(r0 + 8) * 33 + cc + j * 8 + 1] = cacc[mt][j][3];
                }
            }
        }
        __syncthreads();

        {
            const float* pgs = (const float*)(smem + LPG_OFF + (t & 1) * 8192);
            __half2 hh2;
            float hn2[2];
#pragma unroll
            for (int s = 0; s < 2; s++) {
                int ul = pup + s;
                float gi = pgs[pb * 64 + 0 * 16 + ul];
                float gf = pgs[pb * 64 + 1 * 16 + ul];
                float gg = pgs[pb * 64 + 2 * 16 + ul];
                float go = pgs[pb * 64 + 3 * 16 + ul];
#pragma unroll
                for (int k = 0; k < 4; k++) {
                    const float* gk = gsm + k * GK;
                    gi += gk[(0  + ul) * 33 + pb];
                    gf += gk[(16 + ul) * 33 + pb];
                    gg += gk[(32 + ul) * 33 + pb];
                    go += gk[(48 + ul) * 33 + pb];
                }
                float c_old = csm[pb * 16 + ul];
                float cn = sigf(gf) * c_old + sigf(gi) * tanhf(gg);
                hn2[s] = sigf(go) * tanhf(cn);
                csm[pb * 16 + ul] = cn;
            }
            hh2 = __floats2half2_rn(hn2[0], hn2[1]);
            __half* hout = (t & 1) ? hA : hB;
            *(__half2*)(hout + pb * HID + pu) = hh2;
            *(__half2*)(H2 + ((size_t)t * 32 + pb) * HID + pu) = hh2;
        }

        __syncthreads();
        if (tid == 0) {
            __threadfence();
            atomicAdd(&bars[(blockIdx.x & 3) * 64], 1);
        }
        if (t < TT - 1 || blockIdx.x == 0) {
            if (tid < 4) {
                int target = 8 * (t + 1);
                while (*(volatile int*)&bars[tid * 64] < target) { }
                __threadfence();
            }
            __syncthreads();
            if (blockIdx.x == 0 && tid == 0) st_rel(stepf, t);
        }
    }
}

// ---------------- launch ------------------------------------------------------
extern "C" void kernel_launch(void* const* d_in, const int* in_sizes, int n_in,
                              void* d_out, int out_size)
{
    const float* enc       = (const float*)d_in[0];
    const int*   captions  = (const int*)  d_in[1];
    const float* emb_table = (const float*)d_in[8];
    const float* W_ih      = (const float*)d_in[9];
    const float* W_hh      = (const float*)d_in[10];
    const float* b_ih      = (const float*)d_in[11];
    const float* b_hh      = (const float*)d_in[12];
    const float* W_fc      = (const float*)d_in[13];
    const float* b_fc      = (const float*)d_in[14];
    float* out = (float*)d_out;

    __half *pX2, *pWih2, *pWhh2, *pWfc2, *pH2, *ph2A, *ph2B;
    float *pPG;
    int *pBars, *pTicket, *pStep, *pPgp;
    cudaGetSymbolAddress((void**)&pX2, g_X2);
    cudaGetSymbolAddress((void**)&pWih2, g_Wih2);
    cudaGetSymbolAddress((void**)&pWhh2, g_Whh2);
    cudaGetSymbolAddress((void**)&pWfc2, g_Wfc2);
    cudaGetSymbolAddress((void**)&pH2, g_H2);
    cudaGetSymbolAddress((void**)&ph2A, g_h2A);
    cudaGetSymbolAddress((void**)&ph2B, g_h2B);
    cudaGetSymbolAddress((void**)&pPG, g_pg);
    cudaGetSymbolAddress((void**)&pBars, g_bars);
    cudaGetSymbolAddress((void**)&pTicket, g_ticket);
    cudaGetSymbolAddress((void**)&pStep, g_step);
    cudaGetSymbolAddress((void**)&pPgp, g_pgp);

    cudaFuncSetAttribute(hmma_gemm, cudaFuncAttributeMaxDynamicSharedMemorySize, GSMEM);
    cudaFuncSetAttribute(gemm_worker, cudaFuncAttributeMaxDynamicSharedMemorySize, GSMEM);
    cudaFuncSetAttribute(lstm_persistent, cudaFuncAttributeMaxDynamicSharedMemorySize, LSM_BYTES);

    // 1) prep: X2 (t-major), h0+flags, cvt(Wih,Whh)
    prep_kernel<<<MROWS + 32 + NBLK_WSMALL, 256>>>(enc, captions, emb_table,
                                                   W_ih, W_hh, pX2, pWih2, pWhh2,
                                                   ph2A, pBars, pTicket, pStep, pPgp);

    // 2) pregates (t-major) — triggers at CTA-top, releases the LSTM
    {
        dim3 grid(G4 / 128, MROWS / 128);
        hmma_gemm<<<grid, 128, GSMEM>>>(pX2, pWih2, pPG, b_ih, b_hh,
                                        MROWS, G4, XD, pPgp);
    }

    // 3) persistent LSTM — PDL behind pregates; gated on pgp groups
    {
        cudaLaunchConfig_t cfg = {};
        cfg.gridDim = dim3(32, 1, 1);
        cfg.blockDim = dim3(256, 1, 1);
        cfg.dynamicSmemBytes = LSM_BYTES;
        cfg.stream = 0;
        cudaLaunchAttribute at[1];
        at[0].id = cudaLaunchAttributeProgrammaticStreamSerialization;
        at[0].val.programmaticStreamSerializationAllowed = 1;
        cfg.attrs = at;
        cfg.numAttrs = 1;
        cudaError_t e = cudaLaunchKernelEx(&cfg, lstm_persistent,
                                           (const float*)pPG, (const __half*)pWhh2,
                                           ph2A, ph2B, pH2, pBars, pStep, pPgp);
        if (e != cudaSuccess)
            lstm_persistent<<<32, 256, LSM_BYTES>>>(pPG, pWhh2, ph2A, ph2B, pH2,
                                                    pBars, pStep, pPgp);
    }

    // 4) W_fc convert — PDL behind the LSTM's top trigger
    {
        cudaLaunchConfig_t cfg = {};
        cfg.gridDim = dim3((N2_WFC + 255) / 256, 1, 1);
        cfg.blockDim = dim3(256, 1, 1);
        cfg.stream = 0;
        cudaLaunchAttribute at[1];
        at[0].id = cudaLaunchAttributeProgrammaticStreamSerialization;
        at[0].val.programmaticStreamSerializationAllowed = 1;
        cfg.attrs = at;
        cfg.numAttrs = 1;
        cudaError_t e = cudaLaunchKernelEx(&cfg, cvt_wfc_kernel, W_fc, pWfc2);
        if (e != cudaSuccess)
            cvt_wfc_kernel<<<(N2_WFC + 255) / 256, 256>>>(W_fc, pWfc2);
    }

    // 5) output-GEMM workers — PDL behind cvt_wfc completion
    {
        cudaLaunchConfig_t cfg = {};
        cfg.gridDim = dim3(296, 1, 1);
        cfg.blockDim = dim3(128, 1, 1);
        cfg.dynamicSmemBytes = GSMEM;
        cfg.stream = 0;
        cudaLaunchAttribute at[1];
        at[0].id = cudaLaunchAttributeProgrammaticStreamSerialization;
        at[0].val.programmaticStreamSerializationAllowed = 1;
        cfg.attrs = at;
        cfg.numAttrs = 1;
        cudaError_t e = cudaLaunchKernelEx(&cfg, gemm_worker,
                                           (const __half*)pH2, (const __half*)pWfc2,
                                           out, b_fc, pStep, pTicket);
        if (e != cudaSuccess) {
            gemm_worker<<<296, 128, GSMEM>>>(pH2, pWfc2, out, b_fc, pStep, pTicket);
        }
    }
}

// round 17
// speedup vs baseline: 1.9936x; 1.0026x over previous
#include <cuda_runtime.h>
#include <cuda_fp16.h>
#include <math.h>
#include <stdint.h>

// Problem dims
#define TT   64
#define VV   30000
#define HID  512
#define XD   768          // EMB + E
#define G4   2048         // 4*H
#define MROWS 2048        // B*T
#define NTILES_N 235      // ceil(30000/128)
#define NTILES_M 16
#define NTILES_TOT (NTILES_M * NTILES_N)

// ---------------- scratch (device globals; no allocation allowed) -------------
__device__ __align__(16) __half g_X2  [MROWS * XD];          // fp16 X, T-MAJOR (row = t*32+b)
__device__ __align__(16) __half g_Wih2[G4 * XD];             // fp16 W_ih
__device__ __align__(16) __half g_Whh2[G4 * HID];            // fp16 W_hh
__device__ __align__(16) __half g_Wfc2[(size_t)VV * HID];    // fp16 W_fc
__device__ __align__(16) __half g_H2  [MROWS * HID];         // fp16 hidden, T-MAJOR
__device__ __align__(16) __half g_h2A [32 * HID];            // h state ping
__device__ __align__(16) __half g_h2B [32 * HID];            // h state pong
__device__ __align__(16) float  g_pg[MROWS * G4];            // pregates fp32, T-MAJOR
__device__ __align__(16) int    g_bars[512];                 // 4 counters, 256B apart
__device__ int g_ticket;
__device__ int g_step;                                       // published LSTM progress
__device__ int g_pgp[16];                                    // pregates m-group progress

// ---------------- small helpers ------------------------------------------------
__device__ __forceinline__ uint32_t smem_u32(const void* p) {
    uint32_t a;
    asm("{ .reg .u64 t; cvta.to.shared.u64 t, %1; cvt.u32.u64 %0, t; }" : "=r"(a) : "l"(p));
    return a;
}
__device__ __forceinline__ void ldsm4(uint32_t* r, uint32_t addr) {
    asm volatile("ldmatrix.sync.aligned.m8n8.x4.shared.b16 {%0,%1,%2,%3}, [%4];"
                 : "=r"(r[0]), "=r"(r[1]), "=r"(r[2]), "=r"(r[3]) : "r"(addr));
}
__device__ __forceinline__ void mma16816(float* d, const uint32_t* a,
                                         uint32_t b0, uint32_t b1) {
    asm volatile("mma.sync.aligned.m16n8k16.row.col.f32.f16.f16.f32 "
                 "{%0,%1,%2,%3}, {%4,%5,%6,%7}, {%8,%9}, {%0,%1,%2,%3};"
                 : "+f"(d[0]), "+f"(d[1]), "+f"(d[2]), "+f"(d[3])
                 : "r"(a[0]), "r"(a[1]), "r"(a[2]), "r"(a[3]), "r"(b0), "r"(b1));
}
__device__ __forceinline__ void cpasync16(uint32_t dst, const void* src) {
    asm volatile("cp.async.cg.shared.global [%0], [%1], 16;" :: "r"(dst), "l"(src));
}
__device__ __forceinline__ void cpasync16z(uint32_t dst, const void* src, unsigned sz) {
    asm volatile("cp.async.cg.shared.global [%0], [%1], 16, %2;"
                 :: "r"(dst), "l"(src), "r"(sz));
}
#define CP_COMMIT() asm volatile("cp.async.commit_group;" ::: "memory")
__device__ __forceinline__ int ld_acq(const int* p) {
    int v;
    asm volatile("ld.acquire.gpu.global.b32 %0, [%1];" : "=r"(v) : "l"(p) : "memory");
    return v;
}
__device__ __forceinline__ void st_rel(int* p, int v) {
    asm volatile("st.release.gpu.global.b32 [%0], %1;" :: "l"(p), "r"(v) : "memory");
}

#define N2_WIH (G4 * XD / 2)
#define N2_WHH (G4 * HID / 2)
#define N2_WFC (VV * HID / 2)
#define NBLK_WSMALL ((N2_WIH + N2_WHH + 255) / 256)

// ---------------- prep: X2 (t-major), h ping zero, flags, cvt(Wih,Whh) ---------
__global__ void prep_kernel(const float* __restrict__ enc,
                            const int*   __restrict__ captions,
                            const float* __restrict__ emb_table,
                            const float* __restrict__ Wih,
                            const float* __restrict__ Whh,
                            __half* __restrict__ X2,
                            __half* __restrict__ dWih,
                            __half* __restrict__ dWhh,
                            __half* __restrict__ h0, int* __restrict__ bars,
                            int* __restrict__ ticket, int* __restrict__ stepf,
                            int* __restrict__ pgp)
{
    int blk = blockIdx.x;
    if (blk < MROWS) {
        int b = blk >> 6, t = blk & 63;
        int cap = captions[blk];
        const float* erow = emb_table + (size_t)cap * 512;
        const float* crow = enc + (size_t)b * 256;
        size_t base = (size_t)(t * 32 + b) * XD;          // T-MAJOR row
        for (int c = threadIdx.x; c < XD; c += 256) {
            float x = (c < 512) ? erow[c] : crow[c - 512];
            X2[base + c] = __float2half(x);
        }
    } else if (blk < MROWS + 32) {
        int i = (blk - MROWS) * 256 + threadIdx.x;   // 0..8191
        ((uint32_t*)h0)[i] = 0u;
        if (i < 512) bars[i] = 0;
        if (i < 16) pgp[i] = 0;
        if (i == 0) { *ticket = 0; *stepf = -1; }
    } else {
        int i = (blk - MROWS - 32) * 256 + threadIdx.x;
        const float* src;
        __half* dst;
        if (i < N2_WIH) { src = Wih; dst = dWih; }
        else            { src = Whh; dst = dWhh; i -= N2_WIH;
                          if (i >= N2_WHH) return; }
        float2 v = ((const float2*)src)[i];
        ((__half2*)dst)[i] = __floats2half2_rn(v.x, v.y);
    }
}

// ---------------- W_fc convert (PDL: overlaps the LSTM) ------------------------
__global__ void cvt_wfc_kernel(const float* __restrict__ Wfc,
                               __half* __restrict__ dWfc)
{
    int i = blockIdx.x * 256 + threadIdx.x;
    if (i >= N2_WFC) return;
    float2 v = ((const float2*)Wfc)[i];
    ((__half2*)dWfc)[i] = __floats2half2_rn(v.x, v.y);
}

// ---------------- GEMM mainloop shared geometry --------------------------------
#define KC 64
#define STAGE_BYTES 32768      // A 16KB + B 16KB
#define GSMEM (3 * STAGE_BYTES)

// ---------------- HMMA GEMM (pregates): C = A B^T + bias0 + bias1 --------------
__global__ __launch_bounds__(128, 2) void hmma_gemm(
    const __half* __restrict__ A, const __half* __restrict__ B,
    float* __restrict__ C,
    const float* __restrict__ bias0, const float* __restrict__ bias1,
    int M, int N, int K, int* __restrict__ prog)
{
    extern __shared__ char smem[];
    const uint32_t sb = smem_u32(smem);
    const int tid  = threadIdx.x;
    const int lane = tid & 31, wid = tid >> 5;
    const int m0 = blockIdx.y * 128, n0 = blockIdx.x * 128;
    const int wm = wid & 1, wn = wid >> 1;
    const int nch = K / KC;

    if (tid == 0) cudaTriggerProgrammaticLaunchCompletion();

    const int rowA = wm * 64 + (lane & 7) + ((lane >> 3) & 1) * 8;
    const int kxA  = ((lane >> 4) * 16) ^ ((rowA & 7) * 16);
    const int rowB = wn * 64 + (lane & 7) + ((lane >= 16) ? 8 : 0);
    const int kxB  = (((lane >> 3) & 1) * 16) ^ ((rowB & 7) * 16);

    float acc[4][8][4];
#pragma unroll
    for (int i = 0; i < 4; i++)
#pragma unroll
        for (int j = 0; j < 8; j++)
#pragma unroll
            for (int e = 0; e < 4; e++) acc[i][j][e] = 0.f;

    const int prow = tid >> 3;
    const int pcc  = tid & 7;
#define PREFETCH(stage, kt)                                                     \
    do {                                                                        \
        uint32_t ab = sb + (stage) * STAGE_BYTES;                               \
        _Pragma("unroll")                                                       \
        for (int j = 0; j < 8; j++) {                                           \
            int row = prow + j * 16;                                            \
            uint32_t dst = ab + (uint32_t)(row * 128 + ((pcc * 16) ^ ((row & 7) * 16))); \
            cpasync16(dst, A + (size_t)(m0 + row) * K + (kt) + pcc * 8);        \
        }                                                                       \
        _Pragma("unroll")                                                       \
        for (int j = 0; j < 8; j++) {                                           \
            int row = prow + j * 16;                                            \
            int gn = n0 + row;                                                  \
            uint32_t dst = ab + 16384u + (uint32_t)(row * 128 + ((pcc * 16) ^ ((row & 7) * 16))); \
            int gnc = gn < N ? gn : N - 1;                                      \
            cpasync16z(dst, B + (size_t)gnc * K + (kt) + pcc * 8,               \
                       gn < N ? 16u : 0u);                                      \
        }                                                                       \
        CP_COMMIT();                                                            \
    } while (0)

    PREFETCH(0, 0);
    PREFETCH(1, KC);
    for (int c = 0; c < nch; c++) {
        if (c + 2 < nch) PREFETCH((c + 2) % 3, (c + 2) * KC);
        if (c + 2 < nch)      asm volatile("cp.async.wait_group 2;" ::: "memory");
        else if (c + 1 < nch) asm volatile("cp.async.wait_group 1;" ::: "memory");
        else                  asm volatile("cp.async.wait_group 0;" ::: "memory");
        __syncthreads();
        const uint32_t As = sb + (c % 3) * STAGE_BYTES;
        const uint32_t Bs = As + 16384;
#pragma unroll
        for (int ks = 0; ks < 4; ks++) {
            uint32_t a[4][4], b[4][4];
#pragma unroll
            for (int mt = 0; mt < 4; mt++)
                ldsm4(a[mt], As + (uint32_t)((rowA + mt * 16) * 128 + ((ks * 32) ^ kxA)));
#pragma unroll
            for (int j = 0; j < 4; j++)
                ldsm4(b[j], Bs + (uint32_t)((rowB + j * 16) * 128 + ((ks * 32) ^ kxB)));
#pragma unroll
            for (int mt = 0; mt < 4; mt++)
#pragma unroll
                for (int nt = 0; nt < 8; nt++)
                    mma16816(acc[mt][nt], a[mt],
                             b[nt >> 1][(nt & 1) * 2], b[nt >> 1][(nt & 1) * 2 + 1]);
        }
        __syncthreads();
    }

    const int mrow  = m0 + wm * 64 + (lane >> 2);
    const int ncol0 = n0 + wn * 64 + (lane & 3) * 2;
#pragma unroll
    for (int mt = 0; mt < 4; mt++) {
#pragma unroll
        for (int nt = 0; nt < 8; nt++) {
            int cc = ncol0 + nt * 8;
            if (cc < N) {
                float b0v = bias0[cc], b1v = bias0[cc + 1];
                if (bias1) { b0v += bias1[cc]; b1v += bias1[cc + 1]; }
                int r0 = mrow + mt * 16;
                float2 v0 = make_float2(acc[mt][nt][0] + b0v, acc[mt][nt][1] + b1v);
                float2 v1 = make_float2(acc[mt][nt][2] + b0v, acc[mt][nt][3] + b1v);
                *(float2*)(C + (size_t)r0 * N + cc)       = v0;
                *(float2*)(C + (size_t)(r0 + 8) * N + cc) = v1;
            }
        }
    }
    __threadfence();
    __syncthreads();
    if (tid == 0 && prog) atomicAdd(&prog[blockIdx.y], 1);
#undef PREFETCH
}

// ---------------- output-GEMM worker (PDL tail of the chain) --------------------
__global__ __launch_bounds__(128, 2) void gemm_worker(
    const __half* __restrict__ A, const __half* __restrict__ B,
    float* __restrict__ C, const float* __restrict__ bias0,
    int* __restrict__ stepf, int* __restrict__ ticket)
{
    extern __shared__ char smem[];
    __shared__ int tix;
    const uint32_t sb = smem_u32(smem);
    const int tid  = threadIdx.x;
    const int lane = tid & 31, wid = tid >> 5;
    const int wm = wid & 1, wn = wid >> 1;
    const int K = HID, N = VV;

    const int rowA = wm * 64 + (lane & 7) + ((lane >> 3) & 1) * 8;
    const int kxA  = ((lane >> 4) * 16) ^ ((rowA & 7) * 16);
    const int rowB = wn * 64 + (lane & 7) + ((lane >= 16) ? 8 : 0);
    const int kxB  = (((lane >> 3) & 1) * 16) ^ ((rowB & 7) * 16);
    const int prow = tid >> 3;
    const int pcc  = tid & 7;

    for (;;) {
        if (tid == 0) tix = atomicAdd(ticket, 1);
        __syncthreads();
        int tk = tix;
        __syncthreads();
        if (tk >= NTILES_TOT) return;
        const int m  = tk / NTILES_N;
        const int m0 = m * 128;
        const int n0 = (tk - m * NTILES_N) * 128;

        if (tid == 0) {
            const int target = 4 * m + 3;
            while (ld_acq(stepf) < target) __nanosleep(128);
        }
        __syncthreads();

        float acc[4][8][4];
#pragma unroll
        for (int i = 0; i < 4; i++)
#pragma unroll
            for (int j = 0; j < 8; j++)
#pragma unroll
                for (int e = 0; e < 4; e++) acc[i][j][e] = 0.f;

#define WPREFETCH(stage, kt)                                                    \
    do {                                                                        \
        uint32_t ab = sb + (stage) * STAGE_BYTES;                               \
        _Pragma("unroll")                                                       \
        for (int j = 0; j < 8; j++) {                                           \
            int row = prow + j * 16;                                            \
            uint32_t dst = ab + (uint32_t)(row * 128 + ((pcc * 16) ^ ((row & 7) * 16))); \
            cpasync16(dst, A + (size_t)(m0 + row) * K + (kt) + pcc * 8);        \
        }                                                                       \
        _Pragma("unroll")                                                       \
        for (int j = 0; j < 8; j++) {                                           \
            int row = prow + j * 16;                                            \
            int gn = n0 + row;                                                  \
            uint32_t dst = ab + 16384u + (uint32_t)(row * 128 + ((pcc * 16) ^ ((row & 7) * 16))); \
            int gnc = gn < N ? gn : N - 1;                                      \
            cpasync16z(dst, B + (size_t)gnc * K + (kt) + pcc * 8,               \
                       gn < N ? 16u : 0u);                                      \
        }                                                                       \
        CP_COMMIT();                                                            \
    } while (0)

        WPREFETCH(0, 0);
        WPREFETCH(1, KC);
#pragma unroll 1
        for (int c = 0; c < 8; c++) {
            if (c + 2 < 8) WPREFETCH((c + 2) % 3, (c + 2) * KC);
            if (c + 2 < 8)      asm volatile("cp.async.wait_group 2;" ::: "memory");
            else if (c + 1 < 8) asm volatile("cp.async.wait_group 1;" ::: "memory");
            else                asm volatile("cp.async.wait_group 0;" ::: "memory");
            __syncthreads();
            const uint32_t As = sb + (c % 3) * STAGE_BYTES;
            const uint32_t Bs = As + 16384;
#pragma unroll
            for (int ks = 0; ks < 4; ks++) {
                uint32_t a[4][4], b[4][4];
#pragma unroll
                for (int mt = 0; mt < 4; mt++)
                    ldsm4(a[mt], As + (uint32_t)((rowA + mt * 16) * 128 + ((ks * 32) ^ kxA)));
#pragma unroll
                for (int j = 0; j < 4; j++)
                    ldsm4(b[j], Bs + (uint32_t)((rowB + j * 16) * 128 + ((ks * 32) ^ kxB)));
#pragma unroll
                for (int mt = 0; mt < 4; mt++)
#pragma unroll
                    for (int nt = 0; nt < 8; nt++)
                        mma16816(acc[mt][nt], a[mt],
                                 b[nt >> 1][(nt & 1) * 2], b[nt >> 1][(nt & 1) * 2 + 1]);
            }
            __syncthreads();
        }
#undef WPREFETCH

        const int mrow  = m0 + wm * 64 + (lane >> 2);
        const int ncol0 = n0 + wn * 64 + (lane & 3) * 2;
#pragma unroll
        for (int mt = 0; mt < 4; mt++) {
#pragma unroll
            for (int nt = 0; nt < 8; nt++) {
                int cc = ncol0 + nt * 8;
                if (cc < N) {
                    float b0v = bias0[cc], b1v = bias0[cc + 1];
                    int r0 = mrow + mt * 16;
                    int or0 = (r0 & 31) * 64 + (r0 >> 5);        // b*64 + t
                    int or1 = ((r0 + 8) & 31) * 64 + ((r0 + 8) >> 5);
                    float2 v0 = make_float2(acc[mt][nt][0] + b0v, acc[mt][nt][1] + b1v);
                    float2 v1 = make_float2(acc[mt][nt][2] + b0v, acc[mt][nt][3] + b1v);
                    *(float2*)(C + (size_t)or0 * N + cc) = v0;
                    *(float2*)(C + (size_t)or1 * N + cc) = v1;
                }
            }
        }
    }
}

// ---------------- persistent LSTM, tensor-core recurrence ----------------------
// 32 CTAs x 256 threads; 16 units/CTA. Ws (64KB) staged, hoisted into registers,
// then its SMEM is REUSED for hs/pg/gsm (overlay) -> dynamic SMEM 85KB, so
// output-GEMM worker CTAs (96KB) co-reside on LSTM SMs and fill the idle
// tensor pipe. pg prefetch gated on pregates m-group progress (t-major pg).
#define LWS_OFF  0                              // init-only, overlaid below
#define LHS_OFF  0                              // 32KB h stage
#define LPG_OFF  32768                          // 2 x 8KB pregates buffers
#define LGSM_OFF 49152                          // 4 x GK floats
#define GK (64 * 33)
#define LCSM_OFF (LGSM_OFF + 4 * GK * 4)        // 82944
#define LSM_BYTES (LCSM_OFF + 512 * 4)          // 84992

__device__ __forceinline__ float sigf(float x) { return 1.0f / (1.0f + expf(-x)); }

__global__ __launch_bounds__(256, 1) void lstm_persistent(
    const float* __restrict__ pregates,
    const __half* __restrict__ Whh2,
    __half* __restrict__ hA, __half* __restrict__ hB,
    __half* __restrict__ H2, int* __restrict__ bars, int* __restrict__ stepf,
    int* __restrict__ pgp)
{
    extern __shared__ char smem[];
    const uint32_t sb = smem_u32(smem);
    float* gsm = (float*)(smem + LGSM_OFF);
    float* csm = (float*)(smem + LCSM_OFF);

    const int tid  = threadIdx.x;
    const int lane = tid & 31, wid = tid >> 5;
    const int u0   = blockIdx.x * 16;

    // PDL: release cvt_wfc (and transitively workers)
    if (tid == 0) cudaTriggerProgrammaticLaunchCompletion();

    // pregates prefetch geometry (t-major: row = t*32+b)
    const int qb = tid >> 3, qg = (tid >> 1) & 3, qh = tid & 1;
    const size_t qsrc_base = (size_t)qb * G4 + qg * 512 + u0 + qh * 4;
    const uint32_t qdst_off = (uint32_t)(qb * 256 + qg * 64 + qh * 16);

    // stage 64 gate rows of W_hh (fp16) into the overlay region
    for (int i = tid; i < 4096; i += 256) {
        int rr = i >> 6, cq = i & 63;
        int g = rr >> 4, ul = rr & 15;
        uint32_t dst = sb + LWS_OFF + (uint32_t)(rr * 1024 + ((cq * 16) ^ ((rr & 7) * 16)));
        cpasync16(dst, Whh2 + (size_t)(g * 512 + u0 + ul) * HID + cq * 8);
    }
    CP_COMMIT();
    csm[tid] = 0.0f;          // csm is outside the Ws overlay (offset 82944)
    csm[tid + 256] = 0.0f;

    // warp geometry
    const int km = wid >> 1, mg = wid & 1;
    const int kbase = km * 256;
    const int kxA  = (lane >> 4) * 16;
    const int rb   = lane & 7;
    const int kxB  = ((lane >> 3) & 3) * 16;
    const int sxB  = rb * 16;
    const uint32_t wsb = sb + LWS_OFF, hsb = sb + LHS_OFF;

    asm volatile("cp.async.wait_group 0;" ::: "memory");
    __syncthreads();
    // hoist A fragments (time-invariant) into registers; Ws is dead after this
    uint32_t afr[2][4][2][4];
#pragma unroll
    for (int mt = 0; mt < 2; mt++) {
        int rowA = mg * 32 + mt * 16 + (lane & 15);
        int sxA  = (rowA & 7) * 16;
#pragma unroll
        for (int ks = 0; ks < 4; ks++) {
            int kb = kbase + ks * 64;
            ldsm4(afr[mt][ks][0], wsb + (uint32_t)(rowA * 1024 + ((kb + kxA) ^ sxA)));
            ldsm4(afr[mt][ks][1], wsb + (uint32_t)(rowA * 1024 + ((kb + 32 + kxA) ^ sxA)));
        }
    }
    // gate pregates group 0 (tid0 polls while others finish hoisting)
    if (tid == 0) { while (ld_acq(&pgp[0]) < 16) __nanosleep(64); }
    __syncthreads();          // hoist complete on ALL warps; overlay now writable
    // prefetch pregates for t = 0 into buffer 0 (overlay region)
    cpasync16(sb + LPG_OFF + qdst_off,      pregates + qsrc_base);
    cpasync16(sb + LPG_OFF + qdst_off + 32, pregates + qsrc_base + 8);
    CP_COMMIT();

    const int pb = tid >> 3, pup = (tid & 7) * 2;
    const int pu = u0 + pup;

    for (int t = 0; t < TT; t++) {
        const __half* hin = (t & 1) ? hB : hA;
        for (int i = tid; i < 2048; i += 256) {
            int b = i >> 6, cq = i & 63;
            uint32_t dst = hsb + (uint32_t)(b * 1024 + ((cq * 16) ^ ((b & 7) * 16)));
            cpasync16(dst, hin + b * HID + cq * 8);
        }
        CP_COMMIT();
        if (t + 1 < TT) {
            if (((t + 1) & 3) == 0) {          // new pregates m-group boundary
                if (tid == 0) {
                    while (ld_acq(&pgp[(t + 1) >> 2]) < 16) __nanosleep(64);
                }
                __syncthreads();
            }
            uint32_t pgd = sb + LPG_OFF + ((t + 1) & 1) * 8192 + qdst_off;
            const float* pgsrc = pregates + qsrc_base + (size_t)(t + 1) * 32 * G4;
            cpasync16(pgd,      pgsrc);
            cpasync16(pgd + 32, pgsrc + 8);
            CP_COMMIT();
            asm volatile("cp.async.wait_group 1;" ::: "memory");
        } else {
            asm volatile("cp.async.wait_group 0;" ::: "memory");
        }
        __syncthreads();

        float cacc[2][4][4];
#pragma unroll
        for (int mt = 0; mt < 2; mt++)
#pragma unroll
            for (int j = 0; j < 4; j++)
#pragma unroll
                for (int e = 0; e < 4; e++) cacc[mt][j][e] = 0.f;
#pragma unroll
        for (int ks = 0; ks < 4; ks++) {
            int kb = kbase + ks * 64;
            uint32_t bf[4][4];
#pragma unroll
            for (int j = 0; j < 4; j++)
                ldsm4(bf[j], hsb + (uint32_t)((j * 8 + rb) * 1024 + ((kb + kxB) ^ sxB)));
#pragma unroll
            for (int mt = 0; mt < 2; mt++)
#pragma unroll
                for (int j = 0; j < 4; j++) {
                    mma16816(cacc[mt][j], afr[mt][ks][0], bf[j][0], bf[j][1]);
                    mma16816(cacc[mt][j], afr[mt][ks][1], bf[j][2], bf[j][3]);
                }
        }
        {
            float* gk = gsm + km * GK;
            int cc = (lane & 3) * 2;
#pragma unroll
            for (int mt = 0; mt < 2; mt++) {
                int r0 = mg * 32 + mt * 16 + (lane >> 2);
#pragma unroll
                for (int j = 0; j < 4; j++) {
                    gk[r0 * 33 + cc + j * 8]           = cacc[mt][j][0];
                    gk[r0 * 33 + cc + j * 8 + 1]       = cacc[mt][j][1];
                    gk[(r0 + 8) * 33 + cc + j * 8]     = cacc[mt][j][2];
                    gk[(r0 + 8) * 33 + cc + j * 8 + 1] = cacc[mt][j][3];
                }
            }
        }
        __syncthreads();

        {
            const float* pgs = (const float*)(smem + LPG_OFF + (t & 1) * 8192);
            __half2 hh2;
            float hn2[2];
#pragma unroll
            for (int s = 0; s < 2; s++) {
                int ul = pup + s;
                float gi = pgs[pb * 64 + 0 * 16 + ul];
                float gf = pgs[pb * 64 + 1 * 16 + ul];
                float gg = pgs[pb * 64 + 2 * 16 + ul];
                float go = pgs[pb * 64 + 3 * 16 + ul];
#pragma unroll
                for (int k = 0; k < 4; k++) {
                    const float* gk = gsm + k * GK;
                    gi += gk[(0  + ul) * 33 + pb];
                    gf += gk[(16 + ul) * 33 + pb];
                    gg += gk[(32 + ul) * 33 + pb];
                    go += gk[(48 + ul) * 33 + pb];
                }
                float c_old = csm[pb * 16 + ul];
                float cn = sigf(gf) * c_old + sigf(gi) * tanhf(gg);
                hn2[s] = sigf(go) * tanhf(cn);
                csm[pb * 16 + ul] = cn;
            }
            hh2 = __floats2half2_rn(hn2[0], hn2[1]);
            __half* hout = (t & 1) ? hA : hB;
            *(__half2*)(hout + pb * HID + pu) = hh2;
            *(__half2*)(H2 + ((size_t)t * 32 + pb) * HID + pu) = hh2;
        }

        __syncthreads();
        if (tid == 0) {
            __threadfence();
            atomicAdd(&bars[(blockIdx.x & 3) * 64], 1);
        }
        if (t < TT - 1 || blockIdx.x == 0) {
            if (tid < 4) {
                int target = 8 * (t + 1);
                while (*(volatile int*)&bars[tid * 64] < target) { }
                __threadfence();
            }
            __syncthreads();
            if (blockIdx.x == 0 && tid == 0) st_rel(stepf, t);
        }
    }
}

// ---------------- launch ------------------------------------------------------
extern "C" void kernel_launch(void* const* d_in, const int* in_sizes, int n_in,
                              void* d_out, int out_size)
{
    const float* enc       = (const float*)d_in[0];
    const int*   captions  = (const int*)  d_in[1];
    const float* emb_table = (const float*)d_in[8];
    const float* W_ih      = (const float*)d_in[9];
    const float* W_hh      = (const float*)d_in[10];
    const float* b_ih      = (const float*)d_in[11];
    const float* b_hh      = (const float*)d_in[12];
    const float* W_fc      = (const float*)d_in[13];
    const float* b_fc      = (const float*)d_in[14];
    float* out = (float*)d_out;

    __half *pX2, *pWih2, *pWhh2, *pWfc2, *pH2, *ph2A, *ph2B;
    float *pPG;
    int *pBars, *pTicket, *pStep, *pPgp;
    cudaGetSymbolAddress((void**)&pX2, g_X2);
    cudaGetSymbolAddress((void**)&pWih2, g_Wih2);
    cudaGetSymbolAddress((void**)&pWhh2, g_Whh2);
    cudaGetSymbolAddress((void**)&pWfc2, g_Wfc2);
    cudaGetSymbolAddress((void**)&pH2, g_H2);
    cudaGetSymbolAddress((void**)&ph2A, g_h2A);
    cudaGetSymbolAddress((void**)&ph2B, g_h2B);
    cudaGetSymbolAddress((void**)&pPG, g_pg);
    cudaGetSymbolAddress((void**)&pBars, g_bars);
    cudaGetSymbolAddress((void**)&pTicket, g_ticket);
    cudaGetSymbolAddress((void**)&pStep, g_step);
    cudaGetSymbolAddress((void**)&pPgp, g_pgp);

    cudaFuncSetAttribute(hmma_gemm, cudaFuncAttributeMaxDynamicSharedMemorySize, GSMEM);
    cudaFuncSetAttribute(gemm_worker, cudaFuncAttributeMaxDynamicSharedMemorySize, GSMEM);
    cudaFuncSetAttribute(lstm_persistent, cudaFuncAttributeMaxDynamicSharedMemorySize, LSM_BYTES);

    // 1) prep: X2 (t-major), h0+flags, cvt(Wih,Whh)
    prep_kernel<<<MROWS + 32 + NBLK_WSMALL, 256>>>(enc, captions, emb_table,
                                                   W_ih, W_hh, pX2, pWih2, pWhh2,
                                                   ph2A, pBars, pTicket, pStep, pPgp);

    // 2) pregates (t-major) — triggers at CTA-top, releases the LSTM
    {
        dim3 grid(G4 / 128, MROWS / 128);
        hmma_gemm<<<grid, 128, GSMEM>>>(pX2, pWih2, pPG, b_ih, b_hh,
                                        MROWS, G4, XD, pPgp);
    }

    // 3) persistent LSTM — PDL behind pregates; gated on pgp groups
    {
        cudaLaunchConfig_t cfg = {};
        cfg.gridDim = dim3(32, 1, 1);
        cfg.blockDim = dim3(256, 1, 1);
        cfg.dynamicSmemBytes = LSM_BYTES;
        cfg.stream = 0;
        cudaLaunchAttribute at[1];
        at[0].id = cudaLaunchAttributeProgrammaticStreamSerialization;
        at[0].val.programmaticStreamSerializationAllowed = 1;
        cfg.attrs = at;
        cfg.numAttrs = 1;
        cudaError_t e = cudaLaunchKernelEx(&cfg, lstm_persistent,
                                           (const float*)pPG, (const __half*)pWhh2,
                                           ph2A, ph2B, pH2, pBars, pStep, pPgp);
        if (e != cudaSuccess)
            lstm_persistent<<<32, 256, LSM_BYTES>>>(pPG, pWhh2, ph2A, ph2B, pH2,
                                                    pBars, pStep, pPgp);
    }

    // 4) W_fc convert — PDL behind the LSTM's top trigger
    {
        cudaLaunchConfig_t cfg = {};
        cfg.gridDim = dim3((N2_WFC + 255) / 256, 1, 1);
        cfg.blockDim = dim3(256, 1, 1);
        cfg.stream = 0;
        cudaLaunchAttribute at[1];
        at[0].id = cudaLaunchAttributeProgrammaticStreamSerialization;
        at[0].val.programmaticStreamSerializationAllowed = 1;
        cfg.attrs = at;
        cfg.numAttrs = 1;
        cudaError_t e = cudaLaunchKernelEx(&cfg, cvt_wfc_kernel, W_fc, pWfc2);
        if (e != cudaSuccess)
            cvt_wfc_kernel<<<(N2_WFC + 255) / 256, 256>>>(W_fc, pWfc2);
    }

    // 5) output-GEMM workers — PDL behind cvt_wfc completion; can now also
    //    co-reside on LSTM SMs (85KB + 96KB <= 227KB).
    {
        cudaLaunchConfig_t cfg = {};
        cfg.gridDim = dim3(296, 1, 1);
        cfg.blockDim = dim3(128, 1, 1);
        cfg.dynamicSmemBytes = GSMEM;
        cfg.stream = 0;
        cudaLaunchAttribute at[1];
        at[0].id = cudaLaunchAttributeProgrammaticStreamSerialization;
        at[0].val.programmaticStreamSerializationAllowed = 1;
        cfg.attrs = at;
        cfg.numAttrs = 1;
        cudaError_t e = cudaLaunchKernelEx(&cfg, gemm_worker,
                                           (const __half*)pH2, (const __half*)pWfc2,
                                           out, b_fc, pStep, pTicket);
        if (e != cudaSuccess) {
            gemm_worker<<<296, 128, GSMEM>>>(pH2, pWfc2, out, b_fc, pStep, pTicket);
        }
    }
}